// round 1
// baseline (speedup 1.0000x reference)
#include <cuda_runtime.h>
#include <math.h>

#define B_  2
#define C_  64
#define H2_ 256
#define W2_ 256
#define HW2_ (H2_*W2_)
#define H1_ 128
#define W1_ 128
#define HW1_ (H1_*W1_)
#define KK_ 9

// ---------------- scratch (__device__ globals, no allocation) ----------------
__device__ float g_wm1[B_*C_*HW2_];   // wn conv1 out
__device__ float g_wm2[B_*C_*HW2_];   // wn conv2 out
__device__ float g_wmap[B_*HW2_];     // weight map (1 ch)
__device__ float g_fuse[B_*KK_*HW2_]; // fused kernels
__device__ float g_r1[B_*C_*HW1_];    // residual temp
__device__ float g_r2[B_*C_*HW1_];    // x1
__device__ float g_r3[B_*C_*HW1_];    // x2
__device__ float g_up[B_*C_*HW2_];    // bilinear upsampled x2

// ---------------------------------------------------------------------------
// Generic 3x3 conv, 64 output channels, tile 32x8 px, 256 threads.
// Thread = (oc_grp of 16 oc) x (4 consecutive x px).
// DUAL: input is concat(in1[64ch], in2[64ch]) along channels (CIN=128).
// ---------------------------------------------------------------------------
template<int CIN, bool RELU, bool SKIP, bool DUAL>
__global__ __launch_bounds__(256, 2)
void conv3x3_64(const float* __restrict__ in1, const float* __restrict__ in2,
                const float* __restrict__ w,   const float* __restrict__ bias,
                const float* __restrict__ skip, float* __restrict__ out,
                int Hd, int Wd) {
    __shared__ float s_in[10][35];   // 34 cols used, stride 35 -> conflict-free
    __shared__ float s_w[9][64];

    const int t   = threadIdx.x;
    const int b   = blockIdx.z;
    const int gx0 = blockIdx.x * 32;
    const int gy0 = blockIdx.y * 8;
    const int oc_grp = t >> 6;        // 0..3 (16 oc each)
    const int pg  = t & 63;
    const int xl  = (pg & 7) * 4;     // 0..28
    const int yl  = pg >> 3;          // 0..7

    float acc[16][4];
#pragma unroll
    for (int o = 0; o < 16; o++) {
        acc[o][0] = 0.f; acc[o][1] = 0.f; acc[o][2] = 0.f; acc[o][3] = 0.f;
    }

    for (int ic = 0; ic < CIN; ic++) {
        __syncthreads();
        // stage weights: s_w[k][oc]
        for (int idx = t; idx < 576; idx += 256) {
            int oc = idx / 9, k = idx % 9;
            s_w[k][oc] = __ldg(&w[(oc * CIN + ic) * 9 + k]);
        }
        // stage 34x10 halo tile for this ic
        const float* src; int icc;
        if (DUAL && ic >= 64) { src = in2; icc = ic - 64; }
        else                  { src = in1; icc = ic; }
        const int chs = DUAL ? 64 : CIN;
        const float* base = src + ((size_t)b * chs + icc) * (size_t)(Hd * Wd);
        for (int idx = t; idx < 340; idx += 256) {
            int r = idx / 34, cc = idx % 34;
            int gy = gy0 + r - 1, gx = gx0 + cc - 1;
            float v = 0.f;
            if (gy >= 0 && gy < Hd && gx >= 0 && gx < Wd) v = base[gy * Wd + gx];
            s_in[r][cc] = v;
        }
        __syncthreads();

#pragma unroll
        for (int ky = 0; ky < 3; ky++) {
            float rr[6];
#pragma unroll
            for (int p = 0; p < 6; p++) rr[p] = s_in[yl + ky][xl + p];
#pragma unroll
            for (int kx = 0; kx < 3; kx++) {
#pragma unroll
                for (int o = 0; o < 16; o++) {
                    float wv = s_w[ky * 3 + kx][oc_grp * 16 + o];
                    acc[o][0] += wv * rr[kx];
                    acc[o][1] += wv * rr[kx + 1];
                    acc[o][2] += wv * rr[kx + 2];
                    acc[o][3] += wv * rr[kx + 3];
                }
            }
        }
    }

    const int gy = gy0 + yl;
    const int gx = gx0 + xl;
#pragma unroll
    for (int o = 0; o < 16; o++) {
        int oc = oc_grp * 16 + o;
        float bv = __ldg(&bias[oc]);
        size_t off = (((size_t)b * 64 + oc) * Hd + gy) * Wd + gx;
        float v0 = acc[o][0] + bv, v1 = acc[o][1] + bv,
              v2 = acc[o][2] + bv, v3 = acc[o][3] + bv;
        if (SKIP) {
            float4 s4 = *(const float4*)(skip + off);
            v0 += s4.x; v1 += s4.y; v2 += s4.z; v3 += s4.w;
        }
        if (RELU) {
            v0 = fmaxf(v0, 0.f); v1 = fmaxf(v1, 0.f);
            v2 = fmaxf(v2, 0.f); v3 = fmaxf(v3, 0.f);
        }
        float4 r4 = make_float4(v0, v1, v2, v3);
        *(float4*)(out + off) = r4;
    }
}

// ---------------------------------------------------------------------------
// 3x3 conv 64 -> 1 channel (weight_map). tile 32x8, 1 px/thread.
// ---------------------------------------------------------------------------
__global__ __launch_bounds__(256)
void conv3x3_c1(const float* __restrict__ in, const float* __restrict__ w,
                const float* __restrict__ bias, float* __restrict__ out) {
    __shared__ float s_in[10][35];
    const int t   = threadIdx.x;
    const int b   = blockIdx.z;
    const int gx0 = blockIdx.x * 32;
    const int gy0 = blockIdx.y * 8;
    const int xl  = t & 31, yl = t >> 5;

    float acc = 0.f;
    for (int ic = 0; ic < 64; ic++) {
        __syncthreads();
        const float* base = in + ((size_t)b * 64 + ic) * (size_t)HW2_;
        for (int idx = t; idx < 340; idx += 256) {
            int r = idx / 34, cc = idx % 34;
            int gy = gy0 + r - 1, gx = gx0 + cc - 1;
            float v = 0.f;
            if (gy >= 0 && gy < H2_ && gx >= 0 && gx < W2_) v = base[gy * W2_ + gx];
            s_in[r][cc] = v;
        }
        __syncthreads();
#pragma unroll
        for (int ky = 0; ky < 3; ky++)
#pragma unroll
            for (int kx = 0; kx < 3; kx++)
                acc += __ldg(&w[ic * 9 + ky * 3 + kx]) * s_in[yl + ky][xl + kx];
    }
    out[(size_t)b * HW2_ + (gy0 + yl) * W2_ + (gx0 + xl)] = acc + __ldg(&bias[0]);
}

// ---------------------------------------------------------------------------
// dk/gk 1x1 branches + softmax + fuse/tanh/normalize. 32 pixels per block.
// ---------------------------------------------------------------------------
__global__ __launch_bounds__(256)
void fuse_kernel(const float* __restrict__ depth, const float* __restrict__ guide,
                 const float* __restrict__ wmap,
                 const float* __restrict__ dkw1, const float* __restrict__ dkb1,
                 const float* __restrict__ dkw2, const float* __restrict__ dkb2,
                 const float* __restrict__ gkw1, const float* __restrict__ gkb1,
                 const float* __restrict__ gkw2, const float* __restrict__ gkb2,
                 const float* __restrict__ aff,  float* __restrict__ fuse) {
    __shared__ float s_x[64][33];
    __shared__ float s_hd[64][33];
    __shared__ float s_hg[64][33];
    __shared__ float s_dk[9][32];
    __shared__ float s_gk[9][32];

    const int b   = blockIdx.y;
    const int px0 = blockIdx.x * 32;
    const int t   = threadIdx.x;
    const int c   = t >> 2;
    const int pb  = (t & 3) * 8;

    // depth channels -> smem
    for (int idx = t; idx < 2048; idx += 256) {
        int cc = idx >> 5, p = idx & 31;
        s_x[cc][p] = depth[((size_t)b * 64 + cc) * HW2_ + px0 + p];
    }
    __syncthreads();
    // hidden_d = relu(W1 . depth)
    {
        float a[8]; 
#pragma unroll
        for (int p = 0; p < 8; p++) a[p] = 0.f;
        for (int ci = 0; ci < 64; ci++) {
            float wv = __ldg(&dkw1[c * 64 + ci]);
#pragma unroll
            for (int p = 0; p < 8; p++) a[p] += wv * s_x[ci][pb + p];
        }
        float bv = __ldg(&dkb1[c]);
#pragma unroll
        for (int p = 0; p < 8; p++) s_hd[c][pb + p] = fmaxf(a[p] + bv, 0.f);
    }
    __syncthreads();
    // guide channels -> smem
    for (int idx = t; idx < 2048; idx += 256) {
        int cc = idx >> 5, p = idx & 31;
        s_x[cc][p] = guide[((size_t)b * 64 + cc) * HW2_ + px0 + p];
    }
    __syncthreads();
    // hidden_g
    {
        float a[8];
#pragma unroll
        for (int p = 0; p < 8; p++) a[p] = 0.f;
        for (int ci = 0; ci < 64; ci++) {
            float wv = __ldg(&gkw1[c * 64 + ci]);
#pragma unroll
            for (int p = 0; p < 8; p++) a[p] += wv * s_x[ci][pb + p];
        }
        float bv = __ldg(&gkb1[c]);
#pragma unroll
        for (int p = 0; p < 8; p++) s_hg[c][pb + p] = fmaxf(a[p] + bv, 0.f);
    }
    __syncthreads();
    // 9-logit projections
    {
        const int px = t & 31;
        for (int j = t >> 5; j < 9; j += 8) {
            float a = __ldg(&dkb2[j]);
            float g = __ldg(&gkb2[j]);
            for (int c2 = 0; c2 < 64; c2++) {
                a += __ldg(&dkw2[j * 64 + c2]) * s_hd[c2][px];
                g += __ldg(&gkw2[j * 64 + c2]) * s_hg[c2][px];
            }
            s_dk[j][px] = a;
            s_gk[j][px] = g;
        }
    }
    __syncthreads();
    // softmax + fuse + tanh + L1-normalize
    if (t < 32) {
        float wm = wmap[(size_t)b * HW2_ + px0 + t];
        float dmax = -1e30f, gmax = -1e30f;
#pragma unroll
        for (int j = 0; j < 9; j++) {
            dmax = fmaxf(dmax, s_dk[j][t]);
            gmax = fmaxf(gmax, s_gk[j][t]);
        }
        float de[9], ge[9], ds = 0.f, gs = 0.f;
#pragma unroll
        for (int j = 0; j < 9; j++) {
            de[j] = expf(s_dk[j][t] - dmax); ds += de[j];
            ge[j] = expf(s_gk[j][t] - gmax); gs += ge[j];
        }
        float affv = __ldg(&aff[0]) + 1e-8f;
        float inv_d = 1.f / ds, inv_g = 1.f / gs;
        float f[9], asum = 0.f;
#pragma unroll
        for (int j = 0; j < 9; j++) {
            float fv = wm * (de[j] * inv_d) + (1.f - wm) * (ge[j] * inv_g);
            fv = tanhf(fv) / affv;
            f[j] = fv;
            asum += fabsf(fv);
        }
        float ks = fmaxf(asum + 1e-4f, 1.0f);
        float inv_ks = 1.f / ks;
#pragma unroll
        for (int j = 0; j < 9; j++)
            fuse[((size_t)b * 9 + j) * HW2_ + px0 + t] = f[j] * inv_ks;
    }
}

// ---------------------------------------------------------------------------
// Bilinear 2x upsample (half-pixel centers, clamped: matches jax.image.resize)
// ---------------------------------------------------------------------------
__global__ void upsample2x(const float* __restrict__ in, float* __restrict__ out) {
    int idx = blockIdx.x * blockDim.x + threadIdx.x;
    if (idx >= B_ * C_ * HW2_) return;
    int x  = idx & 255;
    int y  = (idx >> 8) & 255;
    int bc = idx >> 16;
    int m = y >> 1, ya, yb; float wya, wyb;
    if ((y & 1) == 0) { ya = (m - 1 < 0) ? 0 : m - 1; yb = m;  wya = 0.25f; wyb = 0.75f; }
    else              { ya = m; yb = (m + 1 > 127) ? 127 : m + 1; wya = 0.75f; wyb = 0.25f; }
    int n = x >> 1, xa, xb; float wxa, wxb;
    if ((x & 1) == 0) { xa = (n - 1 < 0) ? 0 : n - 1; xb = n;  wxa = 0.25f; wxb = 0.75f; }
    else              { xa = n; xb = (n + 1 > 127) ? 127 : n + 1; wxa = 0.75f; wxb = 0.25f; }
    const float* p = in + (size_t)bc * HW1_;
    out[idx] = wya * (wxa * p[ya * 128 + xa] + wxb * p[ya * 128 + xb]) +
               wyb * (wxa * p[yb * 128 + xa] + wxb * p[yb * 128 + xb]);
}

// ---------------------------------------------------------------------------
// Final: out[b,c,y,x] = sum_{ky,kx} fuse[b,3ky+kx,y,x] * up[b,c,y+2(ky-1),x+2(kx-1)]
// (zero outside the 256x256 range — unfold's zero padding).
// ---------------------------------------------------------------------------
__global__ __launch_bounds__(256)
void gather_kernel(const float* __restrict__ fuse, const float* __restrict__ up,
                   float* __restrict__ out) {
    __shared__ float s_up[12][37];
    const int b   = blockIdx.z;
    const int gx0 = blockIdx.x * 32;
    const int gy0 = blockIdx.y * 8;
    const int t   = threadIdx.x;
    const int xl  = t & 31, yl = t >> 5;
    const int gx  = gx0 + xl, gy = gy0 + yl;

    float f[9];
#pragma unroll
    for (int j = 0; j < 9; j++)
        f[j] = fuse[((size_t)b * 9 + j) * HW2_ + gy * W2_ + gx];

    for (int cch = 0; cch < 64; cch++) {
        __syncthreads();
        const float* base = up + ((size_t)b * 64 + cch) * (size_t)HW2_;
        for (int idx = t; idx < 432; idx += 256) {
            int r = idx / 36, cc = idx % 36;
            int yy = gy0 + r - 2, xx = gx0 + cc - 2;
            float v = 0.f;
            if (yy >= 0 && yy < H2_ && xx >= 0 && xx < W2_) v = base[yy * W2_ + xx];
            s_up[r][cc] = v;
        }
        __syncthreads();
        float acc = 0.f;
#pragma unroll
        for (int ky = 0; ky < 3; ky++)
#pragma unroll
            for (int kx = 0; kx < 3; kx++)
                acc += f[ky * 3 + kx] * s_up[yl + 2 * ky][xl + 2 * kx];
        out[(((size_t)b * 64 + cch) * H2_ + gy) * W2_ + gx] = acc;
    }
}

// ---------------------------------------------------------------------------
extern "C" void kernel_launch(void* const* d_in, const int* in_sizes, int n_in,
                              void* d_out, int out_size) {
    const float* depth  = (const float*)d_in[0];
    const float* guide  = (const float*)d_in[1];
    const float* inputs = (const float*)d_in[2];
    const float* dk_w1  = (const float*)d_in[3];
    const float* dk_b1  = (const float*)d_in[4];
    const float* dk_w2  = (const float*)d_in[5];
    const float* dk_b2  = (const float*)d_in[6];
    const float* gk_w1  = (const float*)d_in[7];
    const float* gk_b1  = (const float*)d_in[8];
    const float* gk_w2  = (const float*)d_in[9];
    const float* gk_b2  = (const float*)d_in[10];
    const float* wn_w1  = (const float*)d_in[11];
    const float* wn_b1  = (const float*)d_in[12];
    const float* wn_w2  = (const float*)d_in[13];
    const float* wn_b2  = (const float*)d_in[14];
    const float* wn_w3  = (const float*)d_in[15];
    const float* wn_b3  = (const float*)d_in[16];
    const float* rb_w   = (const float*)d_in[17];
    const float* rb_b   = (const float*)d_in[18];
    const float* aff    = (const float*)d_in[19];
    float* out = (float*)d_out;

    float *p_wm1, *p_wm2, *p_wmap, *p_fuse, *p_r1, *p_r2, *p_r3, *p_up;
    cudaGetSymbolAddress((void**)&p_wm1,  g_wm1);
    cudaGetSymbolAddress((void**)&p_wm2,  g_wm2);
    cudaGetSymbolAddress((void**)&p_wmap, g_wmap);
    cudaGetSymbolAddress((void**)&p_fuse, g_fuse);
    cudaGetSymbolAddress((void**)&p_r1,   g_r1);
    cudaGetSymbolAddress((void**)&p_r2,   g_r2);
    cudaGetSymbolAddress((void**)&p_r3,   g_r3);
    cudaGetSymbolAddress((void**)&p_up,   g_up);

    dim3 blk(256);
    dim3 ghi(W2_ / 32, H2_ / 8, B_);   // 8, 32, 2
    dim3 glo(W1_ / 32, H1_ / 8, B_);   // 4, 16, 2

    // weight-map trunk
    conv3x3_64<128, true,  false, true ><<<ghi, blk>>>(depth, guide, wn_w1, wn_b1, nullptr, p_wm1, H2_, W2_);
    conv3x3_64<64,  true,  false, false><<<ghi, blk>>>(p_wm1, nullptr, wn_w2, wn_b2, nullptr, p_wm2, H2_, W2_);
    conv3x3_c1<<<ghi, blk>>>(p_wm2, wn_w3, wn_b3, p_wmap);

    // per-pixel kernel fusion branch
    dim3 gfuse(HW2_ / 32, B_);
    fuse_kernel<<<gfuse, blk>>>(depth, guide, p_wmap,
                                dk_w1, dk_b1, dk_w2, dk_b2,
                                gk_w1, gk_b1, gk_w2, gk_b2,
                                aff, p_fuse);

    // residual stack on low-res inputs
    const int WSZ = 64 * 64 * 9;
    conv3x3_64<64, true,  false, false><<<glo, blk>>>(inputs, nullptr, rb_w + 0 * WSZ, rb_b + 0,  nullptr, p_r1, H1_, W1_);
    conv3x3_64<64, false, true,  false><<<glo, blk>>>(p_r1,   nullptr, rb_w + 1 * WSZ, rb_b + 64, inputs,  p_r2, H1_, W1_);
    conv3x3_64<64, true,  false, false><<<glo, blk>>>(p_r2,   nullptr, rb_w + 2 * WSZ, rb_b + 128, nullptr, p_r1, H1_, W1_);
    conv3x3_64<64, false, true,  false><<<glo, blk>>>(p_r1,   nullptr, rb_w + 3 * WSZ, rb_b + 192, p_r2,    p_r3, H1_, W1_);

    // upsample + gather
    upsample2x<<<(B_ * C_ * HW2_ + 255) / 256, 256>>>(p_r3, p_up);
    gather_kernel<<<ghi, blk>>>(p_fuse, p_up, out);
}

// round 2
// speedup vs baseline: 1.1128x; 1.1128x over previous
#include <cuda_runtime.h>
#include <math.h>

#define B_  2
#define C_  64
#define H2_ 256
#define W2_ 256
#define HW2_ (H2_*W2_)
#define H1_ 128
#define W1_ 128
#define HW1_ (H1_*W1_)
#define KK_ 9

typedef unsigned long long u64t;

// packed fp32x2 FMA (SASS FFMA2) — ptxas never emits this from C++
__device__ __forceinline__ void ffma2(u64t &d, u64t a, u64t b) {
    asm("fma.rn.f32x2 %0, %1, %2, %0;" : "+l"(d) : "l"(a), "l"(b));
}
__device__ __forceinline__ u64t pk2(float lo, float hi) {
    u64t r; asm("mov.b64 %0, {%1,%2};" : "=l"(r) : "f"(lo), "f"(hi)); return r;
}
__device__ __forceinline__ float2 upk(u64t v) {
    float2 f; asm("mov.b64 {%0,%1}, %2;" : "=f"(f.x), "=f"(f.y) : "l"(v)); return f;
}

// ---------------- scratch (__device__ globals, no allocation) ----------------
__device__ float g_wm1[B_*C_*HW2_];
__device__ float g_wm2[B_*C_*HW2_];
__device__ float g_wmap[B_*HW2_];
__device__ float g_fuse[B_*KK_*HW2_];
__device__ float g_r1[B_*C_*HW1_];
__device__ float g_r2[B_*C_*HW1_];
__device__ float g_r3[B_*C_*HW1_];
__device__ float g_up[B_*C_*HW2_];

// ---------------------------------------------------------------------------
// 3x3 conv, 64 out channels. Tile TX x 8 px, NT=TX*8 threads.
// Thread = 16 oc x 4 px. f32x2 packed FMA, 4-channel staging per sync round.
// ---------------------------------------------------------------------------
template<int CIN, int TX, bool RELU, bool SKIP, bool DUAL>
__global__ __launch_bounds__(TX*8, 2)
void conv3x3(const float* __restrict__ in1, const float* __restrict__ in2,
             const float* __restrict__ w,   const float* __restrict__ bias,
             const float* __restrict__ skip, float* __restrict__ out,
             int Hd, int Wd) {
    constexpr int NT  = TX * 8;
    constexpr int PAD = (TX == 32) ? 35 : 33;   // conflict-free row stride
    constexpr int ICB = 4;
    constexpr int HALO = (TX + 2) * 10;
    constexpr int XS  = TX / 4;

    __shared__ float  s_in[ICB][10][PAD];
    __shared__ float2 s_w2[ICB][9][64];

    const int t   = threadIdx.x;
    const int b   = blockIdx.z;
    const int gx0 = blockIdx.x * TX;
    const int gy0 = blockIdx.y * 8;
    const int oc_grp = t / (NT / 4);
    const int pg  = t % (NT / 4);
    const int xl  = (pg % XS) * 4;
    const int yl  = pg / XS;
    const int oc0 = oc_grp * 16;

    u64t acc[16][2];
#pragma unroll
    for (int o = 0; o < 16; o++) { acc[o][0] = 0ull; acc[o][1] = 0ull; }

    for (int ic0 = 0; ic0 < CIN; ic0 += ICB) {
        __syncthreads();
        // stage weights, duplicated for f32x2
        for (int idx = t; idx < ICB * 576; idx += NT) {
            int icl = idx / 576, rem = idx % 576;
            int oc = rem / 9, k = rem % 9;
            float wv = w[(oc * CIN + ic0 + icl) * 9 + k];
            s_w2[icl][k][oc] = make_float2(wv, wv);
        }
        // stage halo tiles for ICB channels
        for (int idx = t; idx < ICB * HALO; idx += NT) {
            int icl = idx / HALO, rem = idx % HALO;
            int r = rem / (TX + 2), cc = rem % (TX + 2);
            int ic = ic0 + icl;
            const float* src = in1; int icc = ic;
            if (DUAL && ic >= 64) { src = in2; icc = ic - 64; }
            int gy = gy0 + r - 1, gx = gx0 + cc - 1;
            float v = 0.f;
            if (gy >= 0 && gy < Hd && gx >= 0 && gx < Wd)
                v = src[((size_t)b * (DUAL ? 64 : CIN) + icc) * (size_t)(Hd * Wd)
                        + gy * Wd + gx];
            s_in[icl][r][cc] = v;
        }
        __syncthreads();

#pragma unroll
        for (int icl = 0; icl < ICB; icl++) {
#pragma unroll
            for (int ky = 0; ky < 3; ky++) {
                const float* row = &s_in[icl][yl + ky][xl];
                float r0 = row[0], r1 = row[1], r2 = row[2],
                      r3 = row[3], r4 = row[4], r5 = row[5];
                u64t lo[3] = { pk2(r0, r1), pk2(r1, r2), pk2(r2, r3) };
                u64t hi[3] = { pk2(r2, r3), pk2(r3, r4), pk2(r4, r5) };
#pragma unroll
                for (int kx = 0; kx < 3; kx++) {
                    const u64t* wp = (const u64t*)&s_w2[icl][ky * 3 + kx][oc0];
#pragma unroll
                    for (int o = 0; o < 16; o++) {
                        u64t wv = wp[o];
                        ffma2(acc[o][0], wv, lo[kx]);
                        ffma2(acc[o][1], wv, hi[kx]);
                    }
                }
            }
        }
    }

    const int gy = gy0 + yl;
    const int gx = gx0 + xl;
#pragma unroll
    for (int o = 0; o < 16; o++) {
        int oc = oc0 + o;
        float bv = __ldg(&bias[oc]);
        float2 a = upk(acc[o][0]), c = upk(acc[o][1]);
        size_t off = (((size_t)b * 64 + oc) * Hd + gy) * Wd + gx;
        float v0 = a.x + bv, v1 = a.y + bv, v2 = c.x + bv, v3 = c.y + bv;
        if (SKIP) {
            float4 s4 = *(const float4*)(skip + off);
            v0 += s4.x; v1 += s4.y; v2 += s4.z; v3 += s4.w;
        }
        if (RELU) {
            v0 = fmaxf(v0, 0.f); v1 = fmaxf(v1, 0.f);
            v2 = fmaxf(v2, 0.f); v3 = fmaxf(v3, 0.f);
        }
        *(float4*)(out + off) = make_float4(v0, v1, v2, v3);
    }
}

// ---------------------------------------------------------------------------
// 3x3 conv 64 -> 1 channel (weight_map). 32x8 tile, weights preloaded once.
// ---------------------------------------------------------------------------
__global__ __launch_bounds__(256, 2)
void conv3x3_c1(const float* __restrict__ in, const float* __restrict__ w,
                const float* __restrict__ bias, float* __restrict__ out) {
    __shared__ float s_in[4][10][35];
    __shared__ float s_w[576];
    const int t   = threadIdx.x;
    const int b   = blockIdx.z;
    const int gx0 = blockIdx.x * 32;
    const int gy0 = blockIdx.y * 8;
    const int xl  = t & 31, yl = t >> 5;

    for (int idx = t; idx < 576; idx += 256) s_w[idx] = w[idx];

    float acc = 0.f;
    for (int ic0 = 0; ic0 < 64; ic0 += 4) {
        __syncthreads();
        for (int idx = t; idx < 4 * 340; idx += 256) {
            int icl = idx / 340, rem = idx % 340;
            int r = rem / 34, cc = rem % 34;
            int gy = gy0 + r - 1, gx = gx0 + cc - 1;
            float v = 0.f;
            if (gy >= 0 && gy < H2_ && gx >= 0 && gx < W2_)
                v = in[((size_t)b * 64 + ic0 + icl) * (size_t)HW2_ + gy * W2_ + gx];
            s_in[icl][r][cc] = v;
        }
        __syncthreads();
#pragma unroll
        for (int icl = 0; icl < 4; icl++)
#pragma unroll
            for (int ky = 0; ky < 3; ky++)
#pragma unroll
                for (int kx = 0; kx < 3; kx++)
                    acc += s_w[(ic0 + icl) * 9 + ky * 3 + kx]
                         * s_in[icl][yl + ky][xl + kx];
    }
    out[(size_t)b * HW2_ + (gy0 + yl) * W2_ + (gx0 + xl)] = acc + __ldg(&bias[0]);
}

// ---------------------------------------------------------------------------
// dk/gk 1x1 branches + softmax + fuse. 64 px/block, 256 threads.
// Hidden GEMM: 4c x 4px register tile with f32x2.
// ---------------------------------------------------------------------------
__global__ __launch_bounds__(256)
void fuse_kernel(const float* __restrict__ depth, const float* __restrict__ guide,
                 const float* __restrict__ wmap,
                 const float* __restrict__ dkw1, const float* __restrict__ dkb1,
                 const float* __restrict__ dkw2, const float* __restrict__ dkb2,
                 const float* __restrict__ gkw1, const float* __restrict__ gkb1,
                 const float* __restrict__ gkw2, const float* __restrict__ gkb2,
                 const float* __restrict__ aff,  float* __restrict__ fuse) {
    __shared__ float s_x[64][66];
    __shared__ float s_h[64][66];
    __shared__ float s_l[2][9][64];
    __shared__ float s_w2s[2][9][64];

    const int b   = blockIdx.y;
    const int px0 = blockIdx.x * 64;
    const int t   = threadIdx.x;
    const int c4  = (t >> 4) * 4;
    const int p4  = (t & 15) * 4;

    for (int idx = t; idx < 576; idx += 256) {
        s_w2s[0][0][idx] = dkw2[idx];
        s_w2s[1][0][idx] = gkw2[idx];
    }

#pragma unroll
    for (int branch = 0; branch < 2; branch++) {
        const float* X   = branch ? guide : depth;
        const float* W1  = branch ? gkw1  : dkw1;
        const float* B1v = branch ? gkb1  : dkb1;
        const float* B2v = branch ? gkb2  : dkb2;

        __syncthreads();
        for (int idx = t; idx < 4096; idx += 256) {
            int cc = idx >> 6, p = idx & 63;
            s_x[cc][p] = X[((size_t)b * 64 + cc) * HW2_ + px0 + p];
        }
        __syncthreads();

        u64t acc[4][2];
#pragma unroll
        for (int i = 0; i < 4; i++) { acc[i][0] = 0ull; acc[i][1] = 0ull; }
        for (int ci = 0; ci < 64; ci++) {
            u64t xlo = *(const u64t*)&s_x[ci][p4];
            u64t xhi = *(const u64t*)&s_x[ci][p4 + 2];
#pragma unroll
            for (int i = 0; i < 4; i++) {
                float wv = __ldg(&W1[(c4 + i) * 64 + ci]);
                u64t w2v = pk2(wv, wv);
                ffma2(acc[i][0], w2v, xlo);
                ffma2(acc[i][1], w2v, xhi);
            }
        }
#pragma unroll
        for (int i = 0; i < 4; i++) {
            float bv = __ldg(&B1v[c4 + i]);
            float2 a = upk(acc[i][0]), c = upk(acc[i][1]);
            s_h[c4 + i][p4 + 0] = fmaxf(a.x + bv, 0.f);
            s_h[c4 + i][p4 + 1] = fmaxf(a.y + bv, 0.f);
            s_h[c4 + i][p4 + 2] = fmaxf(c.x + bv, 0.f);
            s_h[c4 + i][p4 + 3] = fmaxf(c.y + bv, 0.f);
        }
        __syncthreads();

        // logits: px = t&63, 4 j-groups
        {
            const int px = t & 63;
            for (int j = (t >> 6); j < 9; j += 4) {
                float a = __ldg(&B2v[j]);
#pragma unroll 8
                for (int ci = 0; ci < 64; ci++)
                    a += s_w2s[branch][j][ci] * s_h[ci][px];
                s_l[branch][j][px] = a;
            }
        }
    }
    __syncthreads();

    if (t < 64) {
        float wm = wmap[(size_t)b * HW2_ + px0 + t];
        float dmax = -1e30f, gmax = -1e30f;
#pragma unroll
        for (int j = 0; j < 9; j++) {
            dmax = fmaxf(dmax, s_l[0][j][t]);
            gmax = fmaxf(gmax, s_l[1][j][t]);
        }
        float de[9], ge[9], ds = 0.f, gs = 0.f;
#pragma unroll
        for (int j = 0; j < 9; j++) {
            de[j] = expf(s_l[0][j][t] - dmax); ds += de[j];
            ge[j] = expf(s_l[1][j][t] - gmax); gs += ge[j];
        }
        float affv = __ldg(&aff[0]) + 1e-8f;
        float inv_d = 1.f / ds, inv_g = 1.f / gs;
        float f[9], asum = 0.f;
#pragma unroll
        for (int j = 0; j < 9; j++) {
            float fv = wm * (de[j] * inv_d) + (1.f - wm) * (ge[j] * inv_g);
            fv = tanhf(fv) / affv;
            f[j] = fv;
            asum += fabsf(fv);
        }
        float inv_ks = 1.f / fmaxf(asum + 1e-4f, 1.0f);
#pragma unroll
        for (int j = 0; j < 9; j++)
            fuse[((size_t)b * 9 + j) * HW2_ + px0 + t] = f[j] * inv_ks;
    }
}

// ---------------------------------------------------------------------------
__global__ void upsample2x(const float* __restrict__ in, float* __restrict__ out) {
    int idx = blockIdx.x * blockDim.x + threadIdx.x;
    if (idx >= B_ * C_ * HW2_) return;
    int x  = idx & 255;
    int y  = (idx >> 8) & 255;
    int bc = idx >> 16;
    int m = y >> 1, ya, yb; float wya, wyb;
    if ((y & 1) == 0) { ya = (m - 1 < 0) ? 0 : m - 1; yb = m;  wya = 0.25f; wyb = 0.75f; }
    else              { ya = m; yb = (m + 1 > 127) ? 127 : m + 1; wya = 0.75f; wyb = 0.25f; }
    int n = x >> 1, xa, xb; float wxa, wxb;
    if ((x & 1) == 0) { xa = (n - 1 < 0) ? 0 : n - 1; xb = n;  wxa = 0.25f; wxb = 0.75f; }
    else              { xa = n; xb = (n + 1 > 127) ? 127 : n + 1; wxa = 0.75f; wxb = 0.25f; }
    const float* p = in + (size_t)bc * HW1_;
    out[idx] = wya * (wxa * p[ya * 128 + xa] + wxb * p[ya * 128 + xb]) +
               wyb * (wxa * p[yb * 128 + xa] + wxb * p[yb * 128 + xb]);
}

// ---------------------------------------------------------------------------
__global__ __launch_bounds__(256)
void gather_kernel(const float* __restrict__ fuse, const float* __restrict__ up,
                   float* __restrict__ out) {
    __shared__ float s_up[4][12][37];
    const int b   = blockIdx.z;
    const int gx0 = blockIdx.x * 32;
    const int gy0 = blockIdx.y * 8;
    const int t   = threadIdx.x;
    const int xl  = t & 31, yl = t >> 5;
    const int gx  = gx0 + xl, gy = gy0 + yl;

    float f[9];
#pragma unroll
    for (int j = 0; j < 9; j++)
        f[j] = fuse[((size_t)b * 9 + j) * HW2_ + gy * W2_ + gx];

    for (int c0 = 0; c0 < 64; c0 += 4) {
        __syncthreads();
        for (int idx = t; idx < 4 * 432; idx += 256) {
            int cl = idx / 432, rem = idx % 432;
            int r = rem / 36, cc = rem % 36;
            int yy = gy0 + r - 2, xx = gx0 + cc - 2;
            float v = 0.f;
            if (yy >= 0 && yy < H2_ && xx >= 0 && xx < W2_)
                v = up[((size_t)b * 64 + c0 + cl) * (size_t)HW2_ + yy * W2_ + xx];
            s_up[cl][r][cc] = v;
        }
        __syncthreads();
#pragma unroll
        for (int cl = 0; cl < 4; cl++) {
            float acc = 0.f;
#pragma unroll
            for (int ky = 0; ky < 3; ky++)
#pragma unroll
                for (int kx = 0; kx < 3; kx++)
                    acc += f[ky * 3 + kx] * s_up[cl][yl + 2 * ky][xl + 2 * kx];
            out[(((size_t)b * 64 + c0 + cl) * H2_ + gy) * W2_ + gx] = acc;
        }
    }
}

// ---------------------------------------------------------------------------
extern "C" void kernel_launch(void* const* d_in, const int* in_sizes, int n_in,
                              void* d_out, int out_size) {
    const float* depth  = (const float*)d_in[0];
    const float* guide  = (const float*)d_in[1];
    const float* inputs = (const float*)d_in[2];
    const float* dk_w1  = (const float*)d_in[3];
    const float* dk_b1  = (const float*)d_in[4];
    const float* dk_w2  = (const float*)d_in[5];
    const float* dk_b2  = (const float*)d_in[6];
    const float* gk_w1  = (const float*)d_in[7];
    const float* gk_b1  = (const float*)d_in[8];
    const float* gk_w2  = (const float*)d_in[9];
    const float* gk_b2  = (const float*)d_in[10];
    const float* wn_w1  = (const float*)d_in[11];
    const float* wn_b1  = (const float*)d_in[12];
    const float* wn_w2  = (const float*)d_in[13];
    const float* wn_b2  = (const float*)d_in[14];
    const float* wn_w3  = (const float*)d_in[15];
    const float* wn_b3  = (const float*)d_in[16];
    const float* rb_w   = (const float*)d_in[17];
    const float* rb_b   = (const float*)d_in[18];
    const float* aff    = (const float*)d_in[19];
    float* out = (float*)d_out;

    float *p_wm1, *p_wm2, *p_wmap, *p_fuse, *p_r1, *p_r2, *p_r3, *p_up;
    cudaGetSymbolAddress((void**)&p_wm1,  g_wm1);
    cudaGetSymbolAddress((void**)&p_wm2,  g_wm2);
    cudaGetSymbolAddress((void**)&p_wmap, g_wmap);
    cudaGetSymbolAddress((void**)&p_fuse, g_fuse);
    cudaGetSymbolAddress((void**)&p_r1,   g_r1);
    cudaGetSymbolAddress((void**)&p_r2,   g_r2);
    cudaGetSymbolAddress((void**)&p_r3,   g_r3);
    cudaGetSymbolAddress((void**)&p_up,   g_up);

    dim3 ghi(W2_ / 32, H2_ / 8, B_);   // 8, 32, 2
    dim3 glo(W1_ / 16, H1_ / 8, B_);   // 8, 16, 2

    // weight-map trunk
    conv3x3<128, 32, true,  false, true ><<<ghi, 256>>>(depth, guide, wn_w1, wn_b1, nullptr, p_wm1, H2_, W2_);
    conv3x3<64,  32, true,  false, false><<<ghi, 256>>>(p_wm1, nullptr, wn_w2, wn_b2, nullptr, p_wm2, H2_, W2_);
    conv3x3_c1<<<ghi, 256>>>(p_wm2, wn_w3, wn_b3, p_wmap);

    // per-pixel kernel fusion branch
    dim3 gfuse(HW2_ / 64, B_);
    fuse_kernel<<<gfuse, 256>>>(depth, guide, p_wmap,
                                dk_w1, dk_b1, dk_w2, dk_b2,
                                gk_w1, gk_b1, gk_w2, gk_b2,
                                aff, p_fuse);

    // residual stack on low-res inputs
    const int WSZ = 64 * 64 * 9;
    conv3x3<64, 16, true,  false, false><<<glo, 128>>>(inputs, nullptr, rb_w + 0 * WSZ, rb_b + 0,   nullptr, p_r1, H1_, W1_);
    conv3x3<64, 16, false, true,  false><<<glo, 128>>>(p_r1,   nullptr, rb_w + 1 * WSZ, rb_b + 64,  inputs,  p_r2, H1_, W1_);
    conv3x3<64, 16, true,  false, false><<<glo, 128>>>(p_r2,   nullptr, rb_w + 2 * WSZ, rb_b + 128, nullptr, p_r1, H1_, W1_);
    conv3x3<64, 16, false, true,  false><<<glo, 128>>>(p_r1,   nullptr, rb_w + 3 * WSZ, rb_b + 192, p_r2,    p_r3, H1_, W1_);

    // upsample + gather
    upsample2x<<<(B_ * C_ * HW2_ + 255) / 256, 256>>>(p_r3, p_up);
    gather_kernel<<<ghi, 256>>>(p_fuse, p_up, out);
}

// round 3
// speedup vs baseline: 2.5259x; 2.2699x over previous
#include <cuda_runtime.h>
#include <math.h>

#define B_  2
#define C_  64
#define H2_ 256
#define W2_ 256
#define HW2_ (H2_*W2_)
#define H1_ 128
#define W1_ 128
#define HW1_ (H1_*W1_)
#define KK_ 9

typedef unsigned long long u64t;
typedef unsigned int u32t;

__device__ __forceinline__ void ffma2(u64t &d, u64t a, u64t b) {
    asm("fma.rn.f32x2 %0, %1, %2, %0;" : "+l"(d) : "l"(a), "l"(b));
}
__device__ __forceinline__ u64t pk2(float lo, float hi) {
    u64t r; asm("mov.b64 %0, {%1,%2};" : "=l"(r) : "f"(lo), "f"(hi)); return r;
}
__device__ __forceinline__ float2 upk(u64t v) {
    float2 f; asm("mov.b64 {%0,%1}, %2;" : "=f"(f.x), "=f"(f.y) : "l"(v)); return f;
}
__device__ __forceinline__ u32t tf32b(float f) {
    u32t r; asm("cvt.rna.tf32.f32 %0, %1;" : "=r"(r) : "f"(f)); return r;
}
__device__ __forceinline__ void mma_tf32(float* d, u32t a0, u32t a1, u32t a2, u32t a3,
                                         u32t b0, u32t b1) {
    asm("mma.sync.aligned.m16n8k8.row.col.f32.tf32.tf32.f32 "
        "{%0,%1,%2,%3},{%4,%5,%6,%7},{%8,%9},{%0,%1,%2,%3};"
        : "+f"(d[0]), "+f"(d[1]), "+f"(d[2]), "+f"(d[3])
        : "r"(a0), "r"(a1), "r"(a2), "r"(a3), "r"(b0), "r"(b1));
}

// ---------------- scratch ----------------
__device__ float g_wm1[B_*C_*HW2_];
__device__ float g_wm2[B_*C_*HW2_];
__device__ float g_wmap[B_*HW2_];
__device__ float g_fuse[B_*KK_*HW2_];
__device__ float g_r1[B_*C_*HW1_];
__device__ float g_r2[B_*C_*HW1_];
__device__ float g_r3[B_*C_*HW1_];
__device__ float g_up[B_*C_*HW2_];

// ---------------------------------------------------------------------------
// tf32 tensor-core implicit-GEMM 3x3 conv, 64 out channels.
// Block: 32x8 px tile, 256 threads (8 warps). Warp w owns pixel row y=w,
// M=32 px (2 m16 fragments), N=64 oc (8 n8 chunks).
// 3x3 conv = 9 shifted 1x1 GEMMs; k-dim = channels, chunks of 8.
// ---------------------------------------------------------------------------
template<int CIN, bool RELU, bool SKIP, bool DUAL>
__global__ __launch_bounds__(256, 2)
void conv3x3_mma(const float* __restrict__ in1, const float* __restrict__ in2,
                 const float* __restrict__ w,   const float* __restrict__ bias,
                 const float* __restrict__ skip, float* __restrict__ out,
                 int Hd, int Wd) {
    __shared__ u32t s_in[10][34][9];   // [y][x][c] tf32 bits, c-pad 9 (x-stride odd)
    __shared__ u32t s_w[9][64][9];     // [tap][oc][c] tf32 bits, c-pad 9

    const int t    = threadIdx.x;
    const int warp = t >> 5, lane = t & 31;
    const int G    = lane >> 2, tig = lane & 3;
    const int b    = blockIdx.z;
    const int gx0  = blockIdx.x * 32;
    const int gy0  = blockIdx.y * 8;
    const int y    = warp;

    float d[2][8][4];
#pragma unroll
    for (int m = 0; m < 2; m++)
#pragma unroll
        for (int n = 0; n < 8; n++)
#pragma unroll
            for (int i = 0; i < 4; i++) d[m][n][i] = 0.f;

    for (int ic0 = 0; ic0 < CIN; ic0 += 8) {
        __syncthreads();
        // ---- stage input chunk (8 channels, 10x34 halo) as tf32 ----
        const float* src = in1; int cb = ic0;
        if (DUAL && ic0 >= 64) { src = in2; cb = ic0 - 64; }
        const int CH = DUAL ? 64 : CIN;
        for (int idx = t; idx < 2720; idx += 256) {
            int c = idx / 340, rem = idx % 340;
            int yy = rem / 34, xx = rem % 34;
            int gy = gy0 + yy - 1, gx = gx0 + xx - 1;
            float v = 0.f;
            if (gy >= 0 && gy < Hd && gx >= 0 && gx < Wd)
                v = src[(((size_t)b * CH + cb + c) * Hd + gy) * Wd + gx];
            s_in[yy][xx][c] = tf32b(v);
        }
        // ---- stage weights chunk: [tap][oc][c] ----
        for (int idx = t; idx < 4608; idx += 256) {
            int tap = idx >> 9, rem = idx & 511;
            int oc = rem >> 3, c = rem & 7;
            s_w[tap][oc][c] = tf32b(w[(oc * CIN + ic0 + c) * 9 + tap]);
        }
        __syncthreads();

        // ---- 9 taps x 2 m-frags x 8 n-chunks of m16n8k8 ----
#pragma unroll
        for (int tap = 0; tap < 9; tap++) {
            const int ky = tap / 3, kx = tap % 3;
#pragma unroll
            for (int m = 0; m < 2; m++) {
                const int xx = m * 16 + G + kx;
                u32t a0 = s_in[y + ky][xx][tig];
                u32t a1 = s_in[y + ky][xx + 8][tig];
                u32t a2 = s_in[y + ky][xx][tig + 4];
                u32t a3 = s_in[y + ky][xx + 8][tig + 4];
#pragma unroll
                for (int n = 0; n < 8; n++) {
                    u32t b0 = s_w[tap][n * 8 + G][tig];
                    u32t b1 = s_w[tap][n * 8 + G][tig + 4];
                    mma_tf32(d[m][n], a0, a1, a2, a3, b0, b1);
                }
            }
        }
    }

    // ---- epilogue ----
    const int gy = gy0 + y;
#pragma unroll
    for (int m = 0; m < 2; m++) {
        const int x = gx0 + m * 16 + G;
#pragma unroll
        for (int n = 0; n < 8; n++) {
            const int oc = n * 8 + 2 * tig;
            float b0v = __ldg(&bias[oc]);
            float b1v = __ldg(&bias[oc + 1]);
            size_t base0 = (((size_t)b * 64 + oc) * Hd + gy) * Wd;
            size_t base1 = base0 + (size_t)Hd * Wd;
            float v0 = d[m][n][0] + b0v;
            float v1 = d[m][n][1] + b1v;
            float v2 = d[m][n][2] + b0v;
            float v3 = d[m][n][3] + b1v;
            if (SKIP) {
                v0 += skip[base0 + x];     v1 += skip[base1 + x];
                v2 += skip[base0 + x + 8]; v3 += skip[base1 + x + 8];
            }
            if (RELU) {
                v0 = fmaxf(v0, 0.f); v1 = fmaxf(v1, 0.f);
                v2 = fmaxf(v2, 0.f); v3 = fmaxf(v3, 0.f);
            }
            out[base0 + x]     = v0;  out[base1 + x]     = v1;
            out[base0 + x + 8] = v2;  out[base1 + x + 8] = v3;
        }
    }
}

// ---------------------------------------------------------------------------
// 3x3 conv 64 -> 1 channel (weight_map)
// ---------------------------------------------------------------------------
__global__ __launch_bounds__(256, 2)
void conv3x3_c1(const float* __restrict__ in, const float* __restrict__ w,
                const float* __restrict__ bias, float* __restrict__ out) {
    __shared__ float s_in[4][10][35];
    __shared__ float s_w[576];
    const int t   = threadIdx.x;
    const int b   = blockIdx.z;
    const int gx0 = blockIdx.x * 32;
    const int gy0 = blockIdx.y * 8;
    const int xl  = t & 31, yl = t >> 5;

    for (int idx = t; idx < 576; idx += 256) s_w[idx] = w[idx];

    float acc = 0.f;
    for (int ic0 = 0; ic0 < 64; ic0 += 4) {
        __syncthreads();
        for (int idx = t; idx < 4 * 340; idx += 256) {
            int icl = idx / 340, rem = idx % 340;
            int r = rem / 34, cc = rem % 34;
            int gy = gy0 + r - 1, gx = gx0 + cc - 1;
            float v = 0.f;
            if (gy >= 0 && gy < H2_ && gx >= 0 && gx < W2_)
                v = in[((size_t)b * 64 + ic0 + icl) * (size_t)HW2_ + gy * W2_ + gx];
            s_in[icl][r][cc] = v;
        }
        __syncthreads();
#pragma unroll
        for (int icl = 0; icl < 4; icl++)
#pragma unroll
            for (int ky = 0; ky < 3; ky++)
#pragma unroll
                for (int kx = 0; kx < 3; kx++)
                    acc += s_w[(ic0 + icl) * 9 + ky * 3 + kx]
                         * s_in[icl][yl + ky][xl + kx];
    }
    out[(size_t)b * HW2_ + (gy0 + yl) * W2_ + (gx0 + xl)] = acc + __ldg(&bias[0]);
}

// ---------------------------------------------------------------------------
// dk/gk 1x1 branches + softmax + fuse. 64 px/block, 256 threads.
// ---------------------------------------------------------------------------
__global__ __launch_bounds__(256)
void fuse_kernel(const float* __restrict__ depth, const float* __restrict__ guide,
                 const float* __restrict__ wmap,
                 const float* __restrict__ dkw1, const float* __restrict__ dkb1,
                 const float* __restrict__ dkw2, const float* __restrict__ dkb2,
                 const float* __restrict__ gkw1, const float* __restrict__ gkb1,
                 const float* __restrict__ gkw2, const float* __restrict__ gkb2,
                 const float* __restrict__ aff,  float* __restrict__ fuse) {
    __shared__ float s_x[64][66];
    __shared__ float s_h[64][66];
    __shared__ float s_l[2][9][64];
    __shared__ float s_w2s[2][9][64];

    const int b   = blockIdx.y;
    const int px0 = blockIdx.x * 64;
    const int t   = threadIdx.x;
    const int c4  = (t >> 4) * 4;
    const int p4  = (t & 15) * 4;

    for (int idx = t; idx < 576; idx += 256) {
        s_w2s[0][0][idx] = dkw2[idx];
        s_w2s[1][0][idx] = gkw2[idx];
    }

#pragma unroll
    for (int branch = 0; branch < 2; branch++) {
        const float* X   = branch ? guide : depth;
        const float* W1  = branch ? gkw1  : dkw1;
        const float* B1v = branch ? gkb1  : dkb1;
        const float* B2v = branch ? gkb2  : dkb2;

        __syncthreads();
        for (int idx = t; idx < 4096; idx += 256) {
            int cc = idx >> 6, p = idx & 63;
            s_x[cc][p] = X[((size_t)b * 64 + cc) * HW2_ + px0 + p];
        }
        __syncthreads();

        u64t acc[4][2];
#pragma unroll
        for (int i = 0; i < 4; i++) { acc[i][0] = 0ull; acc[i][1] = 0ull; }
        for (int ci = 0; ci < 64; ci++) {
            u64t xlo = *(const u64t*)&s_x[ci][p4];
            u64t xhi = *(const u64t*)&s_x[ci][p4 + 2];
#pragma unroll
            for (int i = 0; i < 4; i++) {
                float wv = __ldg(&W1[(c4 + i) * 64 + ci]);
                u64t w2v = pk2(wv, wv);
                ffma2(acc[i][0], w2v, xlo);
                ffma2(acc[i][1], w2v, xhi);
            }
        }
#pragma unroll
        for (int i = 0; i < 4; i++) {
            float bv = __ldg(&B1v[c4 + i]);
            float2 a = upk(acc[i][0]), c = upk(acc[i][1]);
            s_h[c4 + i][p4 + 0] = fmaxf(a.x + bv, 0.f);
            s_h[c4 + i][p4 + 1] = fmaxf(a.y + bv, 0.f);
            s_h[c4 + i][p4 + 2] = fmaxf(c.x + bv, 0.f);
            s_h[c4 + i][p4 + 3] = fmaxf(c.y + bv, 0.f);
        }
        __syncthreads();

        {
            const int px = t & 63;
            for (int j = (t >> 6); j < 9; j += 4) {
                float a = __ldg(&B2v[j]);
#pragma unroll 8
                for (int ci = 0; ci < 64; ci++)
                    a += s_w2s[branch][j][ci] * s_h[ci][px];
                s_l[branch][j][px] = a;
            }
        }
    }
    __syncthreads();

    if (t < 64) {
        float wm = wmap[(size_t)b * HW2_ + px0 + t];
        float dmax = -1e30f, gmax = -1e30f;
#pragma unroll
        for (int j = 0; j < 9; j++) {
            dmax = fmaxf(dmax, s_l[0][j][t]);
            gmax = fmaxf(gmax, s_l[1][j][t]);
        }
        float de[9], ge[9], ds = 0.f, gs = 0.f;
#pragma unroll
        for (int j = 0; j < 9; j++) {
            de[j] = expf(s_l[0][j][t] - dmax); ds += de[j];
            ge[j] = expf(s_l[1][j][t] - gmax); gs += ge[j];
        }
        float affv = __ldg(&aff[0]) + 1e-8f;
        float inv_d = 1.f / ds, inv_g = 1.f / gs;
        float f[9], asum = 0.f;
#pragma unroll
        for (int j = 0; j < 9; j++) {
            float fv = wm * (de[j] * inv_d) + (1.f - wm) * (ge[j] * inv_g);
            fv = tanhf(fv) / affv;
            f[j] = fv;
            asum += fabsf(fv);
        }
        float inv_ks = 1.f / fmaxf(asum + 1e-4f, 1.0f);
#pragma unroll
        for (int j = 0; j < 9; j++)
            fuse[((size_t)b * 9 + j) * HW2_ + px0 + t] = f[j] * inv_ks;
    }
}

// ---------------------------------------------------------------------------
__global__ void upsample2x(const float* __restrict__ in, float* __restrict__ out) {
    int idx = blockIdx.x * blockDim.x + threadIdx.x;
    if (idx >= B_ * C_ * HW2_) return;
    int x  = idx & 255;
    int y  = (idx >> 8) & 255;
    int bc = idx >> 16;
    int m = y >> 1, ya, yb; float wya, wyb;
    if ((y & 1) == 0) { ya = (m - 1 < 0) ? 0 : m - 1; yb = m;  wya = 0.25f; wyb = 0.75f; }
    else              { ya = m; yb = (m + 1 > 127) ? 127 : m + 1; wya = 0.75f; wyb = 0.25f; }
    int n = x >> 1, xa, xb; float wxa, wxb;
    if ((x & 1) == 0) { xa = (n - 1 < 0) ? 0 : n - 1; xb = n;  wxa = 0.25f; wxb = 0.75f; }
    else              { xa = n; xb = (n + 1 > 127) ? 127 : n + 1; wxa = 0.75f; wxb = 0.25f; }
    const float* p = in + (size_t)bc * HW1_;
    out[idx] = wya * (wxa * p[ya * 128 + xa] + wxb * p[ya * 128 + xb]) +
               wyb * (wxa * p[yb * 128 + xa] + wxb * p[yb * 128 + xb]);
}

// ---------------------------------------------------------------------------
__global__ __launch_bounds__(256)
void gather_kernel(const float* __restrict__ fuse, const float* __restrict__ up,
                   float* __restrict__ out) {
    __shared__ float s_up[4][12][37];
    const int b   = blockIdx.z;
    const int gx0 = blockIdx.x * 32;
    const int gy0 = blockIdx.y * 8;
    const int t   = threadIdx.x;
    const int xl  = t & 31, yl = t >> 5;
    const int gx  = gx0 + xl, gy = gy0 + yl;

    float f[9];
#pragma unroll
    for (int j = 0; j < 9; j++)
        f[j] = fuse[((size_t)b * 9 + j) * HW2_ + gy * W2_ + gx];

    for (int c0 = 0; c0 < 64; c0 += 4) {
        __syncthreads();
        for (int idx = t; idx < 4 * 432; idx += 256) {
            int cl = idx / 432, rem = idx % 432;
            int r = rem / 36, cc = rem % 36;
            int yy = gy0 + r - 2, xx = gx0 + cc - 2;
            float v = 0.f;
            if (yy >= 0 && yy < H2_ && xx >= 0 && xx < W2_)
                v = up[((size_t)b * 64 + c0 + cl) * (size_t)HW2_ + yy * W2_ + xx];
            s_up[cl][r][cc] = v;
        }
        __syncthreads();
#pragma unroll
        for (int cl = 0; cl < 4; cl++) {
            float acc = 0.f;
#pragma unroll
            for (int ky = 0; ky < 3; ky++)
#pragma unroll
                for (int kx = 0; kx < 3; kx++)
                    acc += f[ky * 3 + kx] * s_up[cl][yl + 2 * ky][xl + 2 * kx];
            out[(((size_t)b * 64 + c0 + cl) * H2_ + gy) * W2_ + gx] = acc;
        }
    }
}

// ---------------------------------------------------------------------------
extern "C" void kernel_launch(void* const* d_in, const int* in_sizes, int n_in,
                              void* d_out, int out_size) {
    const float* depth  = (const float*)d_in[0];
    const float* guide  = (const float*)d_in[1];
    const float* inputs = (const float*)d_in[2];
    const float* dk_w1  = (const float*)d_in[3];
    const float* dk_b1  = (const float*)d_in[4];
    const float* dk_w2  = (const float*)d_in[5];
    const float* dk_b2  = (const float*)d_in[6];
    const float* gk_w1  = (const float*)d_in[7];
    const float* gk_b1  = (const float*)d_in[8];
    const float* gk_w2  = (const float*)d_in[9];
    const float* gk_b2  = (const float*)d_in[10];
    const float* wn_w1  = (const float*)d_in[11];
    const float* wn_b1  = (const float*)d_in[12];
    const float* wn_w2  = (const float*)d_in[13];
    const float* wn_b2  = (const float*)d_in[14];
    const float* wn_w3  = (const float*)d_in[15];
    const float* wn_b3  = (const float*)d_in[16];
    const float* rb_w   = (const float*)d_in[17];
    const float* rb_b   = (const float*)d_in[18];
    const float* aff    = (const float*)d_in[19];
    float* out = (float*)d_out;

    float *p_wm1, *p_wm2, *p_wmap, *p_fuse, *p_r1, *p_r2, *p_r3, *p_up;
    cudaGetSymbolAddress((void**)&p_wm1,  g_wm1);
    cudaGetSymbolAddress((void**)&p_wm2,  g_wm2);
    cudaGetSymbolAddress((void**)&p_wmap, g_wmap);
    cudaGetSymbolAddress((void**)&p_fuse, g_fuse);
    cudaGetSymbolAddress((void**)&p_r1,   g_r1);
    cudaGetSymbolAddress((void**)&p_r2,   g_r2);
    cudaGetSymbolAddress((void**)&p_r3,   g_r3);
    cudaGetSymbolAddress((void**)&p_up,   g_up);

    dim3 ghi(W2_ / 32, H2_ / 8, B_);   // 8, 32, 2
    dim3 glo(W1_ / 32, H1_ / 8, B_);   // 4, 16, 2

    // weight-map trunk (tensor-core)
    conv3x3_mma<128, true,  false, true ><<<ghi, 256>>>(depth, guide, wn_w1, wn_b1, nullptr, p_wm1, H2_, W2_);
    conv3x3_mma<64,  true,  false, false><<<ghi, 256>>>(p_wm1, nullptr, wn_w2, wn_b2, nullptr, p_wm2, H2_, W2_);
    conv3x3_c1<<<ghi, 256>>>(p_wm2, wn_w3, wn_b3, p_wmap);

    // per-pixel kernel fusion branch
    dim3 gfuse(HW2_ / 64, B_);
    fuse_kernel<<<gfuse, 256>>>(depth, guide, p_wmap,
                                dk_w1, dk_b1, dk_w2, dk_b2,
                                gk_w1, gk_b1, gk_w2, gk_b2,
                                aff, p_fuse);

    // residual stack on low-res inputs (tensor-core)
    const int WSZ = 64 * 64 * 9;
    conv3x3_mma<64, true,  false, false><<<glo, 256>>>(inputs, nullptr, rb_w + 0 * WSZ, rb_b + 0,   nullptr, p_r1, H1_, W1_);
    conv3x3_mma<64, false, true,  false><<<glo, 256>>>(p_r1,   nullptr, rb_w + 1 * WSZ, rb_b + 64,  inputs,  p_r2, H1_, W1_);
    conv3x3_mma<64, true,  false, false><<<glo, 256>>>(p_r2,   nullptr, rb_w + 2 * WSZ, rb_b + 128, nullptr, p_r1, H1_, W1_);
    conv3x3_mma<64, false, true,  false><<<glo, 256>>>(p_r1,   nullptr, rb_w + 3 * WSZ, rb_b + 192, p_r2,    p_r3, H1_, W1_);

    // upsample + gather
    upsample2x<<<(B_ * C_ * HW2_ + 255) / 256, 256>>>(p_r3, p_up);
    gather_kernel<<<ghi, 256>>>(p_fuse, p_up, out);
}

// round 4
// speedup vs baseline: 2.5742x; 1.0191x over previous
#include <cuda_runtime.h>
#include <math.h>

#define B_  2
#define C_  64
#define H2_ 256
#define W2_ 256
#define HW2_ (H2_*W2_)
#define H1_ 128
#define W1_ 128
#define HW1_ (H1_*W1_)
#define KK_ 9

typedef unsigned long long u64t;
typedef unsigned int u32t;

__device__ __forceinline__ u32t tf32b(float f) {
    u32t r; asm("cvt.rna.tf32.f32 %0, %1;" : "=r"(r) : "f"(f)); return r;
}
__device__ __forceinline__ void mma_tf32(float* d, u32t a0, u32t a1, u32t a2, u32t a3,
                                         u32t b0, u32t b1) {
    asm("mma.sync.aligned.m16n8k8.row.col.f32.tf32.tf32.f32 "
        "{%0,%1,%2,%3},{%4,%5,%6,%7},{%8,%9},{%0,%1,%2,%3};"
        : "+f"(d[0]), "+f"(d[1]), "+f"(d[2]), "+f"(d[3])
        : "r"(a0), "r"(a1), "r"(a2), "r"(a3), "r"(b0), "r"(b1));
}
// slot interleave: (c, c+4) pairs adjacent -> LDS.64 fragment loads
__device__ __forceinline__ int cslot(int c) { return ((c & 3) << 1) | (c >> 2); }

// ---------------- scratch ----------------
__device__ float g_wm1[B_*C_*HW2_];
__device__ float g_wm2[B_*C_*HW2_];
__device__ float g_wmap[B_*HW2_];
__device__ float g_fuse[B_*KK_*HW2_];
__device__ float g_r1[B_*C_*HW1_];
__device__ float g_r2[B_*C_*HW1_];
__device__ float g_r3[B_*C_*HW1_];
__device__ float g_up[B_*C_*HW2_];

// ---------------------------------------------------------------------------
// tf32 implicit-GEMM 3x3 conv, 64 oc. Tile 32 x TY px, TY warps (1 row each).
// 9 shifted 1x1 GEMMs, k = channels in chunks of 8. Vectorized fragments.
// ---------------------------------------------------------------------------
template<int CIN, int TY, bool RELU, bool SKIP, bool DUAL>
__global__ __launch_bounds__(TY*32, (TY == 8) ? 2 : 1)
void conv3x3_mma(const float* __restrict__ in1, const float* __restrict__ in2,
                 const float* __restrict__ w,   const float* __restrict__ bias,
                 const float* __restrict__ skip, float* __restrict__ out,
                 int Hd, int Wd) {
    constexpr int NT = TY * 32;
    constexpr int HR = TY + 2;
    __shared__ u32t s_in[HR][34][10];   // [y][x][slot] tf32, pad 10
    __shared__ u32t s_w[9][64][10];     // [tap][oc][slot]

    const int t    = threadIdx.x;
    const int warp = t >> 5, lane = t & 31;
    const int G    = lane >> 2, tig = lane & 3;
    const int b    = blockIdx.z;
    const int gx0  = blockIdx.x * 32;
    const int gy0  = blockIdx.y * TY;
    const int y    = warp;

    float d[2][8][4];
#pragma unroll
    for (int m = 0; m < 2; m++)
#pragma unroll
        for (int n = 0; n < 8; n++)
#pragma unroll
            for (int i = 0; i < 4; i++) d[m][n][i] = 0.f;

    for (int ic0 = 0; ic0 < CIN; ic0 += 8) {
        __syncthreads();
        // ---- stage input chunk (8 ch, HRx34 halo) ----
        const float* src = in1; int cb = ic0;
        if (DUAL && ic0 >= 64) { src = in2; cb = ic0 - 64; }
        const int CH = DUAL ? 64 : CIN;
        for (int idx = t; idx < HR * 34 * 8; idx += NT) {
            int c = idx / (HR * 34), rem = idx % (HR * 34);
            int yy = rem / 34, xx = rem % 34;
            int gy = gy0 + yy - 1, gx = gx0 + xx - 1;
            float v = 0.f;
            if (gy >= 0 && gy < Hd && gx >= 0 && gx < Wd)
                v = src[(((size_t)b * CH + cb + c) * Hd + gy) * Wd + gx];
            s_in[yy][xx][cslot(c)] = tf32b(v);
        }
        // ---- stage weights chunk ----
        for (int idx = t; idx < 4608; idx += NT) {
            int tap = idx >> 9, oc = (idx >> 3) & 63, c = idx & 7;
            s_w[tap][oc][cslot(c)] = tf32b(w[(oc * CIN + ic0 + c) * 9 + tap]);
        }
        __syncthreads();

#pragma unroll
        for (int tap = 0; tap < 9; tap++) {
            const int ky = tap / 3, kx = tap % 3;
            uint2 a[2][2];
#pragma unroll
            for (int m = 0; m < 2; m++) {
                const int xx = m * 16 + G + kx;
                a[m][0] = *(const uint2*)&s_in[y + ky][xx][2 * tig];
                a[m][1] = *(const uint2*)&s_in[y + ky][xx + 8][2 * tig];
            }
#pragma unroll
            for (int n = 0; n < 8; n++) {
                uint2 q = *(const uint2*)&s_w[tap][n * 8 + G][2 * tig];
#pragma unroll
                for (int m = 0; m < 2; m++)
                    mma_tf32(d[m][n], a[m][0].x, a[m][1].x, a[m][0].y, a[m][1].y,
                             q.x, q.y);
            }
        }
    }

    // ---- epilogue ----
    const int gy = gy0 + y;
#pragma unroll
    for (int m = 0; m < 2; m++) {
        const int x = gx0 + m * 16 + G;
#pragma unroll
        for (int n = 0; n < 8; n++) {
            const int oc = n * 8 + 2 * tig;
            float b0v = __ldg(&bias[oc]);
            float b1v = __ldg(&bias[oc + 1]);
            size_t base0 = (((size_t)b * 64 + oc) * Hd + gy) * Wd;
            size_t base1 = base0 + (size_t)Hd * Wd;
            float v0 = d[m][n][0] + b0v;
            float v1 = d[m][n][1] + b1v;
            float v2 = d[m][n][2] + b0v;
            float v3 = d[m][n][3] + b1v;
            if (SKIP) {
                v0 += skip[base0 + x];     v1 += skip[base1 + x];
                v2 += skip[base0 + x + 8]; v3 += skip[base1 + x + 8];
            }
            if (RELU) {
                v0 = fmaxf(v0, 0.f); v1 = fmaxf(v1, 0.f);
                v2 = fmaxf(v2, 0.f); v3 = fmaxf(v3, 0.f);
            }
            out[base0 + x]     = v0;  out[base1 + x]     = v1;
            out[base0 + x + 8] = v2;  out[base1 + x + 8] = v3;
        }
    }
}

// ---------------------------------------------------------------------------
// 3x3 conv 64 -> 1 channel (weight_map)
// ---------------------------------------------------------------------------
__global__ __launch_bounds__(256, 2)
void conv3x3_c1(const float* __restrict__ in, const float* __restrict__ w,
                const float* __restrict__ bias, float* __restrict__ out) {
    __shared__ float s_in[4][10][35];
    __shared__ float s_w[576];
    const int t   = threadIdx.x;
    const int b   = blockIdx.z;
    const int gx0 = blockIdx.x * 32;
    const int gy0 = blockIdx.y * 8;
    const int xl  = t & 31, yl = t >> 5;

    for (int idx = t; idx < 576; idx += 256) s_w[idx] = w[idx];

    float acc = 0.f;
    for (int ic0 = 0; ic0 < 64; ic0 += 4) {
        __syncthreads();
        for (int idx = t; idx < 4 * 340; idx += 256) {
            int icl = idx / 340, rem = idx % 340;
            int r = rem / 34, cc = rem % 34;
            int gy = gy0 + r - 1, gx = gx0 + cc - 1;
            float v = 0.f;
            if (gy >= 0 && gy < H2_ && gx >= 0 && gx < W2_)
                v = in[((size_t)b * 64 + ic0 + icl) * (size_t)HW2_ + gy * W2_ + gx];
            s_in[icl][r][cc] = v;
        }
        __syncthreads();
#pragma unroll
        for (int icl = 0; icl < 4; icl++)
#pragma unroll
            for (int ky = 0; ky < 3; ky++)
#pragma unroll
                for (int kx = 0; kx < 3; kx++)
                    acc += s_w[(ic0 + icl) * 9 + ky * 3 + kx]
                         * s_in[icl][yl + ky][xl + kx];
    }
    out[(size_t)b * HW2_ + (gy0 + yl) * W2_ + (gx0 + xl)] = acc + __ldg(&bias[0]);
}

// ---------------------------------------------------------------------------
// fuse: hidden GEMM via tf32 MMA, W1 A-frags from registers, logits SIMT.
// Block = 64 px, 256 threads, 8 warps (4 m-tiles x 2 n-halves).
// ---------------------------------------------------------------------------
__global__ __launch_bounds__(256)
void fuse_kernel(const float* __restrict__ depth, const float* __restrict__ guide,
                 const float* __restrict__ wmap,
                 const float* __restrict__ dkw1, const float* __restrict__ dkb1,
                 const float* __restrict__ dkw2, const float* __restrict__ dkb2,
                 const float* __restrict__ gkw1, const float* __restrict__ gkb1,
                 const float* __restrict__ gkw2, const float* __restrict__ gkb2,
                 const float* __restrict__ aff,  float* __restrict__ fuse) {
    __shared__ u32t  s_xT[64][65];       // [px][ci] tf32
    __shared__ float s_h[64][65];        // [c][px]
    __shared__ float s_l[2][9][64];
    __shared__ float s_w2s[2][9][64];

    const int b    = blockIdx.y;
    const int px0  = blockIdx.x * 64;
    const int t    = threadIdx.x;
    const int warp = t >> 5, lane = t & 31;
    const int G    = lane >> 2, tig = lane & 3;
    const int mt   = warp & 3, nh = warp >> 2;
    const int c0   = mt * 16;

    for (int idx = t; idx < 576; idx += 256) {
        s_w2s[0][0][idx] = dkw2[idx];
        s_w2s[1][0][idx] = gkw2[idx];
    }

#pragma unroll
    for (int branch = 0; branch < 2; branch++) {
        const float* X   = branch ? guide : depth;
        const float* W1  = branch ? gkw1  : dkw1;
        const float* B1v = branch ? gkb1  : dkb1;
        const float* B2v = branch ? gkb2  : dkb2;

        __syncthreads();
        for (int idx = t; idx < 4096; idx += 256) {
            int ci = idx >> 6, p = idx & 63;
            s_xT[p][ci] = tf32b(X[((size_t)b * 64 + ci) * HW2_ + px0 + p]);
        }
        // W1 A-fragments -> registers (32 ldg, L2-hot)
        u32t af[8][4];
#pragma unroll
        for (int kc = 0; kc < 8; kc++) {
            int k0 = kc * 8;
            af[kc][0] = tf32b(__ldg(&W1[(c0 + G)     * 64 + k0 + tig]));
            af[kc][1] = tf32b(__ldg(&W1[(c0 + G + 8) * 64 + k0 + tig]));
            af[kc][2] = tf32b(__ldg(&W1[(c0 + G)     * 64 + k0 + tig + 4]));
            af[kc][3] = tf32b(__ldg(&W1[(c0 + G + 8) * 64 + k0 + tig + 4]));
        }
        __syncthreads();

        float d[4][4];
#pragma unroll
        for (int nc = 0; nc < 4; nc++)
#pragma unroll
            for (int i = 0; i < 4; i++) d[nc][i] = 0.f;

#pragma unroll
        for (int kc = 0; kc < 8; kc++) {
            int k0 = kc * 8;
#pragma unroll
            for (int nc = 0; nc < 4; nc++) {
                int n0 = nh * 32 + nc * 8;
                u32t b0 = s_xT[n0 + G][k0 + tig];
                u32t b1 = s_xT[n0 + G][k0 + tig + 4];
                mma_tf32(d[nc], af[kc][0], af[kc][1], af[kc][2], af[kc][3], b0, b1);
            }
        }

        float bv0 = __ldg(&B1v[c0 + G]);
        float bv8 = __ldg(&B1v[c0 + G + 8]);
#pragma unroll
        for (int nc = 0; nc < 4; nc++) {
            int px = nh * 32 + nc * 8 + 2 * tig;
            s_h[c0 + G][px]         = fmaxf(d[nc][0] + bv0, 0.f);
            s_h[c0 + G][px + 1]     = fmaxf(d[nc][1] + bv0, 0.f);
            s_h[c0 + G + 8][px]     = fmaxf(d[nc][2] + bv8, 0.f);
            s_h[c0 + G + 8][px + 1] = fmaxf(d[nc][3] + bv8, 0.f);
        }
        __syncthreads();

        {
            const int px = t & 63;
            for (int j = (t >> 6); j < 9; j += 4) {
                float a = __ldg(&B2v[j]);
#pragma unroll 8
                for (int ci = 0; ci < 64; ci++)
                    a += s_w2s[branch][j][ci] * s_h[ci][px];
                s_l[branch][j][px] = a;
            }
        }
    }
    __syncthreads();

    if (t < 64) {
        float wm = wmap[(size_t)b * HW2_ + px0 + t];
        float dmax = -1e30f, gmax = -1e30f;
#pragma unroll
        for (int j = 0; j < 9; j++) {
            dmax = fmaxf(dmax, s_l[0][j][t]);
            gmax = fmaxf(gmax, s_l[1][j][t]);
        }
        float de[9], ge[9], ds = 0.f, gs = 0.f;
#pragma unroll
        for (int j = 0; j < 9; j++) {
            de[j] = expf(s_l[0][j][t] - dmax); ds += de[j];
            ge[j] = expf(s_l[1][j][t] - gmax); gs += ge[j];
        }
        float affv = __ldg(&aff[0]) + 1e-8f;
        float inv_d = 1.f / ds, inv_g = 1.f / gs;
        float f[9], asum = 0.f;
#pragma unroll
        for (int j = 0; j < 9; j++) {
            float fv = wm * (de[j] * inv_d) + (1.f - wm) * (ge[j] * inv_g);
            fv = tanhf(fv) / affv;
            f[j] = fv;
            asum += fabsf(fv);
        }
        float inv_ks = 1.f / fmaxf(asum + 1e-4f, 1.0f);
#pragma unroll
        for (int j = 0; j < 9; j++)
            fuse[((size_t)b * 9 + j) * HW2_ + px0 + t] = f[j] * inv_ks;
    }
}

// ---------------------------------------------------------------------------
__global__ void upsample2x(const float* __restrict__ in, float* __restrict__ out) {
    int idx = blockIdx.x * blockDim.x + threadIdx.x;
    if (idx >= B_ * C_ * HW2_) return;
    int x  = idx & 255;
    int y  = (idx >> 8) & 255;
    int bc = idx >> 16;
    int m = y >> 1, ya, yb; float wya, wyb;
    if ((y & 1) == 0) { ya = (m - 1 < 0) ? 0 : m - 1; yb = m;  wya = 0.25f; wyb = 0.75f; }
    else              { ya = m; yb = (m + 1 > 127) ? 127 : m + 1; wya = 0.75f; wyb = 0.25f; }
    int n = x >> 1, xa, xb; float wxa, wxb;
    if ((x & 1) == 0) { xa = (n - 1 < 0) ? 0 : n - 1; xb = n;  wxa = 0.25f; wxb = 0.75f; }
    else              { xa = n; xb = (n + 1 > 127) ? 127 : n + 1; wxa = 0.75f; wxb = 0.25f; }
    const float* p = in + (size_t)bc * HW1_;
    out[idx] = wya * (wxa * p[ya * 128 + xa] + wxb * p[ya * 128 + xb]) +
               wyb * (wxa * p[yb * 128 + xa] + wxb * p[yb * 128 + xb]);
}

// ---------------------------------------------------------------------------
__global__ __launch_bounds__(256)
void gather_kernel(const float* __restrict__ fuse, const float* __restrict__ up,
                   float* __restrict__ out) {
    __shared__ float s_up[4][12][37];
    const int b   = blockIdx.z;
    const int gx0 = blockIdx.x * 32;
    const int gy0 = blockIdx.y * 8;
    const int t   = threadIdx.x;
    const int xl  = t & 31, yl = t >> 5;
    const int gx  = gx0 + xl, gy = gy0 + yl;

    float f[9];
#pragma unroll
    for (int j = 0; j < 9; j++)
        f[j] = fuse[((size_t)b * 9 + j) * HW2_ + gy * W2_ + gx];

    for (int c0 = 0; c0 < 64; c0 += 4) {
        __syncthreads();
        for (int idx = t; idx < 4 * 432; idx += 256) {
            int cl = idx / 432, rem = idx % 432;
            int r = rem / 36, cc = rem % 36;
            int yy = gy0 + r - 2, xx = gx0 + cc - 2;
            float v = 0.f;
            if (yy >= 0 && yy < H2_ && xx >= 0 && xx < W2_)
                v = up[((size_t)b * 64 + c0 + cl) * (size_t)HW2_ + yy * W2_ + xx];
            s_up[cl][r][cc] = v;
        }
        __syncthreads();
#pragma unroll
        for (int cl = 0; cl < 4; cl++) {
            float acc = 0.f;
#pragma unroll
            for (int ky = 0; ky < 3; ky++)
#pragma unroll
                for (int kx = 0; kx < 3; kx++)
                    acc += f[ky * 3 + kx] * s_up[cl][yl + 2 * ky][xl + 2 * kx];
            out[(((size_t)b * 64 + c0 + cl) * H2_ + gy) * W2_ + gx] = acc;
        }
    }
}

// ---------------------------------------------------------------------------
extern "C" void kernel_launch(void* const* d_in, const int* in_sizes, int n_in,
                              void* d_out, int out_size) {
    const float* depth  = (const float*)d_in[0];
    const float* guide  = (const float*)d_in[1];
    const float* inputs = (const float*)d_in[2];
    const float* dk_w1  = (const float*)d_in[3];
    const float* dk_b1  = (const float*)d_in[4];
    const float* dk_w2  = (const float*)d_in[5];
    const float* dk_b2  = (const float*)d_in[6];
    const float* gk_w1  = (const float*)d_in[7];
    const float* gk_b1  = (const float*)d_in[8];
    const float* gk_w2  = (const float*)d_in[9];
    const float* gk_b2  = (const float*)d_in[10];
    const float* wn_w1  = (const float*)d_in[11];
    const float* wn_b1  = (const float*)d_in[12];
    const float* wn_w2  = (const float*)d_in[13];
    const float* wn_b2  = (const float*)d_in[14];
    const float* wn_w3  = (const float*)d_in[15];
    const float* wn_b3  = (const float*)d_in[16];
    const float* rb_w   = (const float*)d_in[17];
    const float* rb_b   = (const float*)d_in[18];
    const float* aff    = (const float*)d_in[19];
    float* out = (float*)d_out;

    float *p_wm1, *p_wm2, *p_wmap, *p_fuse, *p_r1, *p_r2, *p_r3, *p_up;
    cudaGetSymbolAddress((void**)&p_wm1,  g_wm1);
    cudaGetSymbolAddress((void**)&p_wm2,  g_wm2);
    cudaGetSymbolAddress((void**)&p_wmap, g_wmap);
    cudaGetSymbolAddress((void**)&p_fuse, g_fuse);
    cudaGetSymbolAddress((void**)&p_r1,   g_r1);
    cudaGetSymbolAddress((void**)&p_r2,   g_r2);
    cudaGetSymbolAddress((void**)&p_r3,   g_r3);
    cudaGetSymbolAddress((void**)&p_up,   g_up);

    dim3 ghi16(W2_ / 32, H2_ / 16, B_);  // 8, 16, 2  (512-thr blocks)
    dim3 ghi8 (W2_ / 32, H2_ / 8,  B_);  // 8, 32, 2
    dim3 glo  (W1_ / 32, H1_ / 8,  B_);  // 4, 16, 2

    // weight-map trunk (tensor-core, TY=16)
    conv3x3_mma<128, 16, true,  false, true ><<<ghi16, 512>>>(depth, guide, wn_w1, wn_b1, nullptr, p_wm1, H2_, W2_);
    conv3x3_mma<64,  16, true,  false, false><<<ghi16, 512>>>(p_wm1, nullptr, wn_w2, wn_b2, nullptr, p_wm2, H2_, W2_);
    conv3x3_c1<<<ghi8, 256>>>(p_wm2, wn_w3, wn_b3, p_wmap);

    // per-pixel kernel fusion branch
    dim3 gfuse(HW2_ / 64, B_);
    fuse_kernel<<<gfuse, 256>>>(depth, guide, p_wmap,
                                dk_w1, dk_b1, dk_w2, dk_b2,
                                gk_w1, gk_b1, gk_w2, gk_b2,
                                aff, p_fuse);

    // residual stack on low-res inputs (tensor-core, TY=8)
    const int WSZ = 64 * 64 * 9;
    conv3x3_mma<64, 8, true,  false, false><<<glo, 256>>>(inputs, nullptr, rb_w + 0 * WSZ, rb_b + 0,   nullptr, p_r1, H1_, W1_);
    conv3x3_mma<64, 8, false, true,  false><<<glo, 256>>>(p_r1,   nullptr, rb_w + 1 * WSZ, rb_b + 64,  inputs,  p_r2, H1_, W1_);
    conv3x3_mma<64, 8, true,  false, false><<<glo, 256>>>(p_r2,   nullptr, rb_w + 2 * WSZ, rb_b + 128, nullptr, p_r1, H1_, W1_);
    conv3x3_mma<64, 8, false, true,  false><<<glo, 256>>>(p_r1,   nullptr, rb_w + 3 * WSZ, rb_b + 192, p_r2,    p_r3, H1_, W1_);

    // upsample + gather
    upsample2x<<<(B_ * C_ * HW2_ + 255) / 256, 256>>>(p_r3, p_up);
    gather_kernel<<<ghi8, 256>>>(p_fuse, p_up, out);
}

// round 5
// speedup vs baseline: 3.7290x; 1.4486x over previous
#include <cuda_runtime.h>
#include <math.h>

#define B_  2
#define C_  64
#define H2_ 256
#define W2_ 256
#define HW2_ (H2_*W2_)
#define H1_ 128
#define W1_ 128
#define HW1_ (H1_*W1_)
#define KK_ 9

typedef unsigned long long u64t;
typedef unsigned int u32t;

__device__ __forceinline__ u32t tf32b(float f) {
    u32t r; asm("cvt.rna.tf32.f32 %0, %1;" : "=r"(r) : "f"(f)); return r;
}
__device__ __forceinline__ void mma_tf32(float* d, u32t a0, u32t a1, u32t a2, u32t a3,
                                         u32t b0, u32t b1) {
    asm("mma.sync.aligned.m16n8k8.row.col.f32.tf32.tf32.f32 "
        "{%0,%1,%2,%3},{%4,%5,%6,%7},{%8,%9},{%0,%1,%2,%3};"
        : "+f"(d[0]), "+f"(d[1]), "+f"(d[2]), "+f"(d[3])
        : "r"(a0), "r"(a1), "r"(a2), "r"(a3), "r"(b0), "r"(b1));
}
// slot interleave: (c, c+4) pairs adjacent -> LDS.64 fragment loads
__device__ __forceinline__ int cslot(int c) { return ((c & 3) << 1) | (c >> 2); }

// ---------------- scratch ----------------
__device__ float g_wm2[B_*C_*HW2_];
__device__ float g_wmap[B_*HW2_];
__device__ float g_fuse[B_*KK_*HW2_];
__device__ float g_r2[B_*C_*HW1_];     // x1 (fp32, skip source)
__device__ float g_r3[B_*C_*HW1_];     // final x (fp32)
__device__ float g_up[B_*C_*HW2_];

// interleaved tf32 buffers
__device__ u32t gt_in0[B_*16*HW2_*8];  // depth||guide
__device__ u32t gt_wm1[B_*8*HW2_*8];
__device__ u32t gt_inlo[B_*8*HW1_*8];
__device__ u32t gt_r1[B_*8*HW1_*8];
__device__ u32t gt_r2[B_*8*HW1_*8];
__device__ u32t gt_r3[B_*8*HW1_*8];
__device__ u32t gt_wn1[16*9*64*8];
__device__ u32t gt_wn2[8*9*64*8];
__device__ u32t gt_rb [4*8*9*64*8];

// ---------------------------------------------------------------------------
// prep: NCHW fp32 -> [b][chunk][px][slot8] tf32
// ---------------------------------------------------------------------------
__global__ void prep_inputs(const float* __restrict__ depth, const float* __restrict__ guide,
                            const float* __restrict__ inputs,
                            u32t* __restrict__ in0_t, u32t* __restrict__ inlo_t) {
    int idx = blockIdx.x * 256 + threadIdx.x;
    const int N0 = B_ * 16 * HW2_;
    if (idx < N0) {
        int px = idx & (HW2_ - 1);
        int ch = (idx >> 16) & 15;
        int b  = idx >> 20;
        const float* src = (ch < 8 ? depth : guide) + ((size_t)b * 64 + (ch & 7) * 8) * HW2_ + px;
        u32t v[8];
#pragma unroll
        for (int c = 0; c < 8; c++) v[c] = tf32b(src[(size_t)c * HW2_]);
        *(uint4*)&in0_t[(size_t)idx * 8]     = make_uint4(v[0], v[4], v[1], v[5]);
        *(uint4*)&in0_t[(size_t)idx * 8 + 4] = make_uint4(v[2], v[6], v[3], v[7]);
    } else {
        int j = idx - N0;
        int px = j & (HW1_ - 1);
        int ch = (j >> 14) & 7;
        int b  = j >> 17;
        const float* src = inputs + ((size_t)b * 64 + ch * 8) * HW1_ + px;
        u32t v[8];
#pragma unroll
        for (int c = 0; c < 8; c++) v[c] = tf32b(src[(size_t)c * HW1_]);
        *(uint4*)&inlo_t[(size_t)j * 8]     = make_uint4(v[0], v[4], v[1], v[5]);
        *(uint4*)&inlo_t[(size_t)j * 8 + 4] = make_uint4(v[2], v[6], v[3], v[7]);
    }
}

__device__ __forceinline__ void wcvt(const float* __restrict__ w, u32t* __restrict__ o,
                                     int widx, int CIN) {
    int slot = widx & 7;
    int oc   = (widx >> 3) & 63;
    int rem  = widx >> 9;
    int tap  = rem % 9, ch = rem / 9;
    int c    = (slot >> 1) + ((slot & 1) << 2);   // inverse of cslot
    o[widx] = tf32b(w[(oc * CIN + ch * 8 + c) * 9 + tap]);
}

__global__ void prep_weights(const float* __restrict__ wn1, const float* __restrict__ wn2,
                             const float* __restrict__ rb,
                             u32t* __restrict__ t1, u32t* __restrict__ t2,
                             u32t* __restrict__ trb) {
    int idx = blockIdx.x * 256 + threadIdx.x;
    if (idx < 73728) {
        wcvt(wn1, t1, idx, 128);
    } else if (idx < 110592) {
        wcvt(wn2, t2, idx - 73728, 64);
    } else {
        int j = idx - 110592;
        int r = j / 36864, jj = j - r * 36864;
        wcvt(rb + r * 36864, trb + r * 36864, jj, 64);
    }
}

// ---------------------------------------------------------------------------
// tf32 implicit-GEMM 3x3 conv, cp.async double-buffered.
// Tile 32x8 px, 256 threads (8 warps, 1 pixel-row each). NC = CIN/8 chunks.
// smem (dynamic): in[2][10][34][8] + w[2][9][64][8] tf32 words = 58624 B.
// ---------------------------------------------------------------------------
#define CONV_SMEM 58624

template<int NC, bool RELU, bool SKIP, bool WF32, bool WT32>
__global__ __launch_bounds__(256, 2)
void conv3x3_cp(const u32t* __restrict__ in_t, const u32t* __restrict__ wt,
                const float* __restrict__ bias, const float* __restrict__ skip,
                float* __restrict__ outf, u32t* __restrict__ outt,
                int Hd, int Wd) {
    extern __shared__ u32t sm[];
    const int t    = threadIdx.x;
    const int warp = t >> 5, lane = t & 31;
    const int G    = lane >> 2, tig = lane & 3;
    const int b    = blockIdx.z;
    const int gx0  = blockIdx.x * 32;
    const int gy0  = blockIdx.y * 8;
    const size_t HW = (size_t)Hd * Wd;

    const u32t smbase = (u32t)__cvta_generic_to_shared(sm);

    auto stage = [&](int k, int buf) {
        // input halo tile: 10 rows x 34 px x 32B, as 16B units (zero-fill OOB)
        const u32t* gin = in_t + ((size_t)b * NC + k) * HW * 8;
        const u32t sin_b = smbase + buf * (2720 * 4);
        for (int u = t; u < 680; u += 256) {
            int r  = u / 68, h = u - r * 68;
            int xx = h >> 1, hf = h & 1;
            int gy = gy0 + r - 1, gx = gx0 + xx - 1;
            bool ok = (gy >= 0) && (gy < Hd) && (gx >= 0) && (gx < Wd);
            const u32t* src = gin + (((size_t)(ok ? gy : 0)) * Wd + (ok ? gx : 0)) * 8 + hf * 4;
            int nbytes = ok ? 16 : 0;
            u32t dst = sin_b + (u32t)(((r * 34 + xx) * 8 + hf * 4) * 4);
            asm volatile("cp.async.cg.shared.global [%0], [%1], 16, %2;"
                         :: "r"(dst), "l"(src), "r"(nbytes));
        }
        // weight chunk: 4608 words = 1152 x 16B, linear
        const u32t* gw = wt + (size_t)k * 4608;
        const u32t sw_b = smbase + (u32t)((5440 + buf * 4608) * 4);
        for (int u = t; u < 1152; u += 256) {
            asm volatile("cp.async.cg.shared.global [%0], [%1], 16, 16;"
                         :: "r"(sw_b + u * 16), "l"(gw + u * 4));
        }
    };

    float d[2][8][4];
#pragma unroll
    for (int m = 0; m < 2; m++)
#pragma unroll
        for (int n = 0; n < 8; n++)
#pragma unroll
            for (int i = 0; i < 4; i++) d[m][n][i] = 0.f;

    stage(0, 0);
    asm volatile("cp.async.commit_group;");

    for (int k = 0; k < NC; k++) {
        if (k + 1 < NC) {
            stage(k + 1, (k + 1) & 1);
            asm volatile("cp.async.commit_group;");
            asm volatile("cp.async.wait_group 1;");
        } else {
            asm volatile("cp.async.wait_group 0;");
        }
        __syncthreads();
        const u32t* bin = sm + (k & 1) * 2720;
        const u32t* bw  = sm + 5440 + (k & 1) * 4608;
#pragma unroll
        for (int tap = 0; tap < 9; tap++) {
            const int ky = tap / 3, kx = tap % 3;
            uint2 a[2][2];
#pragma unroll
            for (int m = 0; m < 2; m++) {
                const int xx = m * 16 + G + kx;
                a[m][0] = *(const uint2*)&bin[((warp + ky) * 34 + xx) * 8 + 2 * tig];
                a[m][1] = *(const uint2*)&bin[((warp + ky) * 34 + xx + 8) * 8 + 2 * tig];
            }
#pragma unroll
            for (int n = 0; n < 8; n++) {
                uint2 q = *(const uint2*)&bw[(tap * 64 + n * 8 + G) * 8 + 2 * tig];
#pragma unroll
                for (int m = 0; m < 2; m++)
                    mma_tf32(d[m][n], a[m][0].x, a[m][1].x, a[m][0].y, a[m][1].y,
                             q.x, q.y);
            }
        }
        __syncthreads();   // protect buffer reuse before next stage() overwrites
    }

    // ---- epilogue ----
    const int gy    = gy0 + warp;
    const int slotA = cslot(2 * tig), slotB = cslot(2 * tig + 1);
#pragma unroll
    for (int m = 0; m < 2; m++) {
        const int x = gx0 + m * 16 + G;
#pragma unroll
        for (int n = 0; n < 8; n++) {
            const int oc = n * 8 + 2 * tig;
            float b0v = __ldg(&bias[oc]);
            float b1v = __ldg(&bias[oc + 1]);
            float v0 = d[m][n][0] + b0v;
            float v1 = d[m][n][1] + b1v;
            float v2 = d[m][n][2] + b0v;
            float v3 = d[m][n][3] + b1v;
            size_t f0 = (((size_t)b * 64 + oc) * Hd + gy) * Wd + x;
            size_t f1 = f0 + HW;
            if (SKIP) {
                v0 += skip[f0];     v1 += skip[f1];
                v2 += skip[f0 + 8]; v3 += skip[f1 + 8];
            }
            if (RELU) {
                v0 = fmaxf(v0, 0.f); v1 = fmaxf(v1, 0.f);
                v2 = fmaxf(v2, 0.f); v3 = fmaxf(v3, 0.f);
            }
            if (WF32) {
                outf[f0] = v0; outf[f1] = v1; outf[f0 + 8] = v2; outf[f1 + 8] = v3;
            }
            if (WT32) {
                size_t tb = (((size_t)b * 8 + n) * HW + (size_t)gy * Wd + x) * 8;
                outt[tb + slotA]      = tf32b(v0);
                outt[tb + slotB]      = tf32b(v1);
                outt[tb + 64 + slotA] = tf32b(v2);
                outt[tb + 64 + slotB] = tf32b(v3);
            }
        }
    }
}

// ---------------------------------------------------------------------------
// 3x3 conv 64 -> 1 channel (weight_map)
// ---------------------------------------------------------------------------
__global__ __launch_bounds__(256, 2)
void conv3x3_c1(const float* __restrict__ in, const float* __restrict__ w,
                const float* __restrict__ bias, float* __restrict__ out) {
    __shared__ float s_in[4][10][35];
    __shared__ float s_w[576];
    const int t   = threadIdx.x;
    const int b   = blockIdx.z;
    const int gx0 = blockIdx.x * 32;
    const int gy0 = blockIdx.y * 8;
    const int xl  = t & 31, yl = t >> 5;

    for (int idx = t; idx < 576; idx += 256) s_w[idx] = w[idx];

    float acc = 0.f;
    for (int ic0 = 0; ic0 < 64; ic0 += 4) {
        __syncthreads();
        for (int idx = t; idx < 4 * 340; idx += 256) {
            int icl = idx / 340, rem = idx % 340;
            int r = rem / 34, cc = rem % 34;
            int gy = gy0 + r - 1, gx = gx0 + cc - 1;
            float v = 0.f;
            if (gy >= 0 && gy < H2_ && gx >= 0 && gx < W2_)
                v = in[((size_t)b * 64 + ic0 + icl) * (size_t)HW2_ + gy * W2_ + gx];
            s_in[icl][r][cc] = v;
        }
        __syncthreads();
#pragma unroll
        for (int icl = 0; icl < 4; icl++)
#pragma unroll
            for (int ky = 0; ky < 3; ky++)
#pragma unroll
                for (int kx = 0; kx < 3; kx++)
                    acc += s_w[(ic0 + icl) * 9 + ky * 3 + kx]
                         * s_in[icl][yl + ky][xl + kx];
    }
    out[(size_t)b * HW2_ + (gy0 + yl) * W2_ + (gx0 + xl)] = acc + __ldg(&bias[0]);
}

// ---------------------------------------------------------------------------
// fuse: hidden GEMM via tf32 MMA, logits SIMT, softmax tail.
// ---------------------------------------------------------------------------
__global__ __launch_bounds__(256)
void fuse_kernel(const float* __restrict__ depth, const float* __restrict__ guide,
                 const float* __restrict__ wmap,
                 const float* __restrict__ dkw1, const float* __restrict__ dkb1,
                 const float* __restrict__ dkw2, const float* __restrict__ dkb2,
                 const float* __restrict__ gkw1, const float* __restrict__ gkb1,
                 const float* __restrict__ gkw2, const float* __restrict__ gkb2,
                 const float* __restrict__ aff,  float* __restrict__ fuse) {
    __shared__ u32t  s_xT[64][65];
    __shared__ float s_h[64][65];
    __shared__ float s_l[2][9][64];
    __shared__ float s_w2s[2][9][64];

    const int b    = blockIdx.y;
    const int px0  = blockIdx.x * 64;
    const int t    = threadIdx.x;
    const int warp = t >> 5, lane = t & 31;
    const int G    = lane >> 2, tig = lane & 3;
    const int mt   = warp & 3, nh = warp >> 2;
    const int c0   = mt * 16;

    for (int idx = t; idx < 576; idx += 256) {
        s_w2s[0][0][idx] = dkw2[idx];
        s_w2s[1][0][idx] = gkw2[idx];
    }

#pragma unroll
    for (int branch = 0; branch < 2; branch++) {
        const float* X   = branch ? guide : depth;
        const float* W1  = branch ? gkw1  : dkw1;
        const float* B1v = branch ? gkb1  : dkb1;
        const float* B2v = branch ? gkb2  : dkb2;

        __syncthreads();
        for (int idx = t; idx < 4096; idx += 256) {
            int ci = idx >> 6, p = idx & 63;
            s_xT[p][ci] = tf32b(X[((size_t)b * 64 + ci) * HW2_ + px0 + p]);
        }
        u32t af[8][4];
#pragma unroll
        for (int kc = 0; kc < 8; kc++) {
            int k0 = kc * 8;
            af[kc][0] = tf32b(__ldg(&W1[(c0 + G)     * 64 + k0 + tig]));
            af[kc][1] = tf32b(__ldg(&W1[(c0 + G + 8) * 64 + k0 + tig]));
            af[kc][2] = tf32b(__ldg(&W1[(c0 + G)     * 64 + k0 + tig + 4]));
            af[kc][3] = tf32b(__ldg(&W1[(c0 + G + 8) * 64 + k0 + tig + 4]));
        }
        __syncthreads();

        float d[4][4];
#pragma unroll
        for (int nc = 0; nc < 4; nc++)
#pragma unroll
            for (int i = 0; i < 4; i++) d[nc][i] = 0.f;

#pragma unroll
        for (int kc = 0; kc < 8; kc++) {
            int k0 = kc * 8;
#pragma unroll
            for (int nc = 0; nc < 4; nc++) {
                int n0 = nh * 32 + nc * 8;
                u32t b0 = s_xT[n0 + G][k0 + tig];
                u32t b1 = s_xT[n0 + G][k0 + tig + 4];
                mma_tf32(d[nc], af[kc][0], af[kc][1], af[kc][2], af[kc][3], b0, b1);
            }
        }

        float bv0 = __ldg(&B1v[c0 + G]);
        float bv8 = __ldg(&B1v[c0 + G + 8]);
#pragma unroll
        for (int nc = 0; nc < 4; nc++) {
            int px = nh * 32 + nc * 8 + 2 * tig;
            s_h[c0 + G][px]         = fmaxf(d[nc][0] + bv0, 0.f);
            s_h[c0 + G][px + 1]     = fmaxf(d[nc][1] + bv0, 0.f);
            s_h[c0 + G + 8][px]     = fmaxf(d[nc][2] + bv8, 0.f);
            s_h[c0 + G + 8][px + 1] = fmaxf(d[nc][3] + bv8, 0.f);
        }
        __syncthreads();

        {
            const int px = t & 63;
            for (int j = (t >> 6); j < 9; j += 4) {
                float a = __ldg(&B2v[j]);
#pragma unroll 8
                for (int ci = 0; ci < 64; ci++)
                    a += s_w2s[branch][j][ci] * s_h[ci][px];
                s_l[branch][j][px] = a;
            }
        }
    }
    __syncthreads();

    if (t < 64) {
        float wm = wmap[(size_t)b * HW2_ + px0 + t];
        float dmax = -1e30f, gmax = -1e30f;
#pragma unroll
        for (int j = 0; j < 9; j++) {
            dmax = fmaxf(dmax, s_l[0][j][t]);
            gmax = fmaxf(gmax, s_l[1][j][t]);
        }
        float de[9], ge[9], ds = 0.f, gs = 0.f;
#pragma unroll
        for (int j = 0; j < 9; j++) {
            de[j] = expf(s_l[0][j][t] - dmax); ds += de[j];
            ge[j] = expf(s_l[1][j][t] - gmax); gs += ge[j];
        }
        float affv = __ldg(&aff[0]) + 1e-8f;
        float inv_d = 1.f / ds, inv_g = 1.f / gs;
        float f[9], asum = 0.f;
#pragma unroll
        for (int j = 0; j < 9; j++) {
            float fv = wm * (de[j] * inv_d) + (1.f - wm) * (ge[j] * inv_g);
            fv = tanhf(fv) / affv;
            f[j] = fv;
            asum += fabsf(fv);
        }
        float inv_ks = 1.f / fmaxf(asum + 1e-4f, 1.0f);
#pragma unroll
        for (int j = 0; j < 9; j++)
            fuse[((size_t)b * 9 + j) * HW2_ + px0 + t] = f[j] * inv_ks;
    }
}

// ---------------------------------------------------------------------------
__global__ void upsample2x(const float* __restrict__ in, float* __restrict__ out) {
    int idx = blockIdx.x * blockDim.x + threadIdx.x;
    if (idx >= B_ * C_ * HW2_) return;
    int x  = idx & 255;
    int y  = (idx >> 8) & 255;
    int bc = idx >> 16;
    int m = y >> 1, ya, yb; float wya, wyb;
    if ((y & 1) == 0) { ya = (m - 1 < 0) ? 0 : m - 1; yb = m;  wya = 0.25f; wyb = 0.75f; }
    else              { ya = m; yb = (m + 1 > 127) ? 127 : m + 1; wya = 0.75f; wyb = 0.25f; }
    int n = x >> 1, xa, xb; float wxa, wxb;
    if ((x & 1) == 0) { xa = (n - 1 < 0) ? 0 : n - 1; xb = n;  wxa = 0.25f; wxb = 0.75f; }
    else              { xa = n; xb = (n + 1 > 127) ? 127 : n + 1; wxa = 0.75f; wxb = 0.25f; }
    const float* p = in + (size_t)bc * HW1_;
    out[idx] = wya * (wxa * p[ya * 128 + xa] + wxb * p[ya * 128 + xb]) +
               wyb * (wxa * p[yb * 128 + xa] + wxb * p[yb * 128 + xb]);
}

// ---------------------------------------------------------------------------
__global__ __launch_bounds__(256)
void gather_kernel(const float* __restrict__ fuse, const float* __restrict__ up,
                   float* __restrict__ out) {
    __shared__ float s_up[4][12][37];
    const int b   = blockIdx.z;
    const int gx0 = blockIdx.x * 32;
    const int gy0 = blockIdx.y * 8;
    const int t   = threadIdx.x;
    const int xl  = t & 31, yl = t >> 5;
    const int gx  = gx0 + xl, gy = gy0 + yl;

    float f[9];
#pragma unroll
    for (int j = 0; j < 9; j++)
        f[j] = fuse[((size_t)b * 9 + j) * HW2_ + gy * W2_ + gx];

    for (int c0 = 0; c0 < 64; c0 += 4) {
        __syncthreads();
        for (int idx = t; idx < 4 * 432; idx += 256) {
            int cl = idx / 432, rem = idx % 432;
            int r = rem / 36, cc = rem % 36;
            int yy = gy0 + r - 2, xx = gx0 + cc - 2;
            float v = 0.f;
            if (yy >= 0 && yy < H2_ && xx >= 0 && xx < W2_)
                v = up[((size_t)b * 64 + c0 + cl) * (size_t)HW2_ + yy * W2_ + xx];
            s_up[cl][r][cc] = v;
        }
        __syncthreads();
#pragma unroll
        for (int cl = 0; cl < 4; cl++) {
            float acc = 0.f;
#pragma unroll
            for (int ky = 0; ky < 3; ky++)
#pragma unroll
                for (int kx = 0; kx < 3; kx++)
                    acc += f[ky * 3 + kx] * s_up[cl][yl + 2 * ky][xl + 2 * kx];
            out[(((size_t)b * 64 + c0 + cl) * H2_ + gy) * W2_ + gx] = acc;
        }
    }
}

// ---------------------------------------------------------------------------
extern "C" void kernel_launch(void* const* d_in, const int* in_sizes, int n_in,
                              void* d_out, int out_size) {
    const float* depth  = (const float*)d_in[0];
    const float* guide  = (const float*)d_in[1];
    const float* inputs = (const float*)d_in[2];
    const float* dk_w1  = (const float*)d_in[3];
    const float* dk_b1  = (const float*)d_in[4];
    const float* dk_w2  = (const float*)d_in[5];
    const float* dk_b2  = (const float*)d_in[6];
    const float* gk_w1  = (const float*)d_in[7];
    const float* gk_b1  = (const float*)d_in[8];
    const float* gk_w2  = (const float*)d_in[9];
    const float* gk_b2  = (const float*)d_in[10];
    const float* wn_w1  = (const float*)d_in[11];
    const float* wn_b1  = (const float*)d_in[12];
    const float* wn_w2  = (const float*)d_in[13];
    const float* wn_b2  = (const float*)d_in[14];
    const float* wn_w3  = (const float*)d_in[15];
    const float* wn_b3  = (const float*)d_in[16];
    const float* rb_w   = (const float*)d_in[17];
    const float* rb_b   = (const float*)d_in[18];
    const float* aff    = (const float*)d_in[19];
    float* out = (float*)d_out;

    float *p_wm2, *p_wmap, *p_fuse, *p_r2, *p_r3, *p_up;
    u32t *pt_in0, *pt_wm1, *pt_inlo, *pt_r1, *pt_r2, *pt_r3, *pt_wn1, *pt_wn2, *pt_rb;
    cudaGetSymbolAddress((void**)&p_wm2,  g_wm2);
    cudaGetSymbolAddress((void**)&p_wmap, g_wmap);
    cudaGetSymbolAddress((void**)&p_fuse, g_fuse);
    cudaGetSymbolAddress((void**)&p_r2,   g_r2);
    cudaGetSymbolAddress((void**)&p_r3,   g_r3);
    cudaGetSymbolAddress((void**)&p_up,   g_up);
    cudaGetSymbolAddress((void**)&pt_in0,  gt_in0);
    cudaGetSymbolAddress((void**)&pt_wm1,  gt_wm1);
    cudaGetSymbolAddress((void**)&pt_inlo, gt_inlo);
    cudaGetSymbolAddress((void**)&pt_r1,   gt_r1);
    cudaGetSymbolAddress((void**)&pt_r2,   gt_r2);
    cudaGetSymbolAddress((void**)&pt_r3,   gt_r3);
    cudaGetSymbolAddress((void**)&pt_wn1,  gt_wn1);
    cudaGetSymbolAddress((void**)&pt_wn2,  gt_wn2);
    cudaGetSymbolAddress((void**)&pt_rb,   gt_rb);

    // opt-in to >48KB dynamic smem (idempotent host calls, graph-safe)
    cudaFuncSetAttribute(conv3x3_cp<16, true,  false, false, true >, cudaFuncAttributeMaxDynamicSharedMemorySize, CONV_SMEM);
    cudaFuncSetAttribute(conv3x3_cp<8,  true,  false, true,  false>, cudaFuncAttributeMaxDynamicSharedMemorySize, CONV_SMEM);
    cudaFuncSetAttribute(conv3x3_cp<8,  true,  false, false, true >, cudaFuncAttributeMaxDynamicSharedMemorySize, CONV_SMEM);
    cudaFuncSetAttribute(conv3x3_cp<8,  false, true,  true,  true >, cudaFuncAttributeMaxDynamicSharedMemorySize, CONV_SMEM);
    cudaFuncSetAttribute(conv3x3_cp<8,  false, true,  true,  false>, cudaFuncAttributeMaxDynamicSharedMemorySize, CONV_SMEM);

    dim3 ghi8(W2_ / 32, H2_ / 8, B_);   // 8, 32, 2
    dim3 glo (W1_ / 32, H1_ / 8, B_);   // 4, 16, 2

    // pre-pass conversions
    prep_inputs<<<(B_*16*HW2_ + B_*8*HW1_) / 256, 256>>>(depth, guide, inputs, pt_in0, pt_inlo);
    prep_weights<<<(16*9*64*8 + 8*9*64*8 + 4*8*9*64*8) / 256, 256>>>(wn_w1, wn_w2, rb_w, pt_wn1, pt_wn2, pt_rb);

    // weight-map trunk
    conv3x3_cp<16, true,  false, false, true ><<<ghi8, 256, CONV_SMEM>>>(pt_in0, pt_wn1, wn_b1, nullptr, nullptr, pt_wm1, H2_, W2_);
    conv3x3_cp<8,  true,  false, true,  false><<<ghi8, 256, CONV_SMEM>>>(pt_wm1, pt_wn2, wn_b2, nullptr, p_wm2,  nullptr, H2_, W2_);
    conv3x3_c1<<<ghi8, 256>>>(p_wm2, wn_w3, wn_b3, p_wmap);

    // per-pixel kernel fusion branch
    dim3 gfuse(HW2_ / 64, B_);
    fuse_kernel<<<gfuse, 256>>>(depth, guide, p_wmap,
                                dk_w1, dk_b1, dk_w2, dk_b2,
                                gk_w1, gk_b1, gk_w2, gk_b2,
                                aff, p_fuse);

    // residual stack on low-res inputs
    conv3x3_cp<8, true,  false, false, true ><<<glo, 256, CONV_SMEM>>>(pt_inlo, pt_rb + 0*36864, rb_b + 0,   nullptr, nullptr, pt_r1, H1_, W1_);
    conv3x3_cp<8, false, true,  true,  true ><<<glo, 256, CONV_SMEM>>>(pt_r1,   pt_rb + 1*36864, rb_b + 64,  inputs,  p_r2,    pt_r2, H1_, W1_);
    conv3x3_cp<8, true,  false, false, true ><<<glo, 256, CONV_SMEM>>>(pt_r2,   pt_rb + 2*36864, rb_b + 128, nullptr, nullptr, pt_r3, H1_, W1_);
    conv3x3_cp<8, false, true,  true,  false><<<glo, 256, CONV_SMEM>>>(pt_r3,   pt_rb + 3*36864, rb_b + 192, p_r2,    p_r3,    nullptr, H1_, W1_);

    // upsample + gather
    upsample2x<<<(B_ * C_ * HW2_ + 255) / 256, 256>>>(p_r3, p_up);
    gather_kernel<<<ghi8, 256>>>(p_fuse, p_up, out);
}

// round 6
// speedup vs baseline: 3.9984x; 1.0723x over previous
#include <cuda_runtime.h>
#include <math.h>

#define B_  2
#define C_  64
#define H2_ 256
#define W2_ 256
#define HW2_ (H2_*W2_)
#define H1_ 128
#define W1_ 128
#define HW1_ (H1_*W1_)
#define KK_ 9

typedef unsigned long long u64t;
typedef unsigned int u32t;

__device__ __forceinline__ u32t tf32b(float f) {
    u32t r; asm("cvt.rna.tf32.f32 %0, %1;" : "=r"(r) : "f"(f)); return r;
}
__device__ __forceinline__ void mma_tf32(float* d, u32t a0, u32t a1, u32t a2, u32t a3,
                                         u32t b0, u32t b1) {
    asm("mma.sync.aligned.m16n8k8.row.col.f32.tf32.tf32.f32 "
        "{%0,%1,%2,%3},{%4,%5,%6,%7},{%8,%9},{%0,%1,%2,%3};"
        : "+f"(d[0]), "+f"(d[1]), "+f"(d[2]), "+f"(d[3])
        : "r"(a0), "r"(a1), "r"(a2), "r"(a3), "r"(b0), "r"(b1));
}
// slot interleave: (c, c+4) pairs adjacent -> LDS.64 fragment loads
__device__ __forceinline__ int cslot(int c) { return ((c & 3) << 1) | (c >> 2); }

// ---------------- scratch ----------------
__device__ float g_wmap[B_*HW2_];
__device__ float g_fuse[B_*KK_*HW2_];
__device__ float g_r2[B_*C_*HW1_];     // x1 (fp32, skip source)
__device__ float g_r3[B_*C_*HW1_];     // final x (fp32)
__device__ float g_up[B_*C_*HW2_];

// interleaved tf32 buffers
__device__ u32t gt_in0[B_*16*HW2_*8];  // depth||guide
__device__ u32t gt_wm1[B_*8*HW2_*8];
__device__ u32t gt_wm2[B_*8*HW2_*8];
__device__ u32t gt_inlo[B_*8*HW1_*8];
__device__ u32t gt_r1[B_*8*HW1_*8];
__device__ u32t gt_r2[B_*8*HW1_*8];
__device__ u32t gt_r3[B_*8*HW1_*8];
__device__ u32t gt_wn1[16*9*64*8];
__device__ u32t gt_wn2[8*9*64*8];
__device__ u32t gt_rb [4*8*9*64*8];
__device__ u32t gt_wn3[8*9*8*8];       // NOC=1, oc padded to 8

// ---------------------------------------------------------------------------
// prep: NCHW fp32 -> [b][chunk][px][slot8] tf32
// ---------------------------------------------------------------------------
__global__ void prep_inputs(const float* __restrict__ depth, const float* __restrict__ guide,
                            const float* __restrict__ inputs,
                            u32t* __restrict__ in0_t, u32t* __restrict__ inlo_t) {
    int idx = blockIdx.x * 256 + threadIdx.x;
    const int N0 = B_ * 16 * HW2_;
    if (idx < N0) {
        int px = idx & (HW2_ - 1);
        int ch = (idx >> 16) & 15;
        int b  = idx >> 20;
        const float* src = (ch < 8 ? depth : guide) + ((size_t)b * 64 + (ch & 7) * 8) * HW2_ + px;
        u32t v[8];
#pragma unroll
        for (int c = 0; c < 8; c++) v[c] = tf32b(src[(size_t)c * HW2_]);
        *(uint4*)&in0_t[(size_t)idx * 8]     = make_uint4(v[0], v[4], v[1], v[5]);
        *(uint4*)&in0_t[(size_t)idx * 8 + 4] = make_uint4(v[2], v[6], v[3], v[7]);
    } else {
        int j = idx - N0;
        int px = j & (HW1_ - 1);
        int ch = (j >> 14) & 7;
        int b  = j >> 17;
        const float* src = inputs + ((size_t)b * 64 + ch * 8) * HW1_ + px;
        u32t v[8];
#pragma unroll
        for (int c = 0; c < 8; c++) v[c] = tf32b(src[(size_t)c * HW1_]);
        *(uint4*)&inlo_t[(size_t)j * 8]     = make_uint4(v[0], v[4], v[1], v[5]);
        *(uint4*)&inlo_t[(size_t)j * 8 + 4] = make_uint4(v[2], v[6], v[3], v[7]);
    }
}

__device__ __forceinline__ void wcvt(const float* __restrict__ w, u32t* __restrict__ o,
                                     int widx, int CIN) {
    int slot = widx & 7;
    int oc   = (widx >> 3) & 63;
    int rem  = widx >> 9;
    int tap  = rem % 9, ch = rem / 9;
    int c    = (slot >> 1) + ((slot & 1) << 2);   // inverse of cslot
    o[widx] = tf32b(w[(oc * CIN + ch * 8 + c) * 9 + tap]);
}

__global__ void prep_weights(const float* __restrict__ wn1, const float* __restrict__ wn2,
                             const float* __restrict__ rb,  const float* __restrict__ wn3,
                             u32t* __restrict__ t1, u32t* __restrict__ t2,
                             u32t* __restrict__ trb, u32t* __restrict__ t3) {
    int idx = blockIdx.x * 256 + threadIdx.x;
    if (idx < 73728) {
        wcvt(wn1, t1, idx, 128);
    } else if (idx < 110592) {
        wcvt(wn2, t2, idx - 73728, 64);
    } else if (idx < 258048) {
        int j = idx - 110592;
        int r = j / 36864, jj = j - r * 36864;
        wcvt(rb + r * 36864, trb + r * 36864, jj, 64);
    } else {
        int j = idx - 258048;           // [chunk][tap][oc8][slot8]
        int chunk = j / 576, rem = j % 576;
        int tap = rem >> 6, oc = (rem >> 3) & 7, slot = rem & 7;
        int c = (slot >> 1) + ((slot & 1) << 2);
        t3[j] = (oc == 0) ? tf32b(wn3[(chunk * 8 + c) * 9 + tap]) : 0u;
    }
}

// ---------------------------------------------------------------------------
// tf32 implicit-GEMM 3x3 conv, cp.async double-buffered.
// Tile 32 x TY px, 32*TY threads (TY warps, 1 pixel-row each). NC chunks of 8 ic.
// NOC n-chunks of 8 oc (8 = full 64 oc, 1 = single-channel conv).
// ---------------------------------------------------------------------------
template<int NC, int NOC, int TY, bool RELU, bool SKIP, bool WF32, bool WT32>
__global__ __launch_bounds__(TY*32, (TY == 8) ? 2 : 4)
void conv3x3_cp(const u32t* __restrict__ in_t, const u32t* __restrict__ wt,
                const float* __restrict__ bias, const float* __restrict__ skip,
                float* __restrict__ outf, u32t* __restrict__ outt,
                int Hd, int Wd) {
    constexpr int NT   = TY * 32;
    constexpr int HR   = TY + 2;
    constexpr int IN_W = HR * 34 * 8;      // words per input buffer
    constexpr int W_W  = 576 * NOC;        // words per weight buffer
    extern __shared__ u32t sm[];
    const int t    = threadIdx.x;
    const int warp = t >> 5, lane = t & 31;
    const int G    = lane >> 2, tig = lane & 3;
    const int b    = blockIdx.z;
    const int gx0  = blockIdx.x * 32;
    const int gy0  = blockIdx.y * TY;
    const size_t HW = (size_t)Hd * Wd;

    const u32t smbase = (u32t)__cvta_generic_to_shared(sm);

    auto stage = [&](int k, int buf) {
        const u32t* gin = in_t + ((size_t)b * NC + k) * HW * 8;
        const u32t sin_b = smbase + buf * (IN_W * 4);
        for (int u = t; u < HR * 68; u += NT) {
            int r  = u / 68, h = u - r * 68;
            int xx = h >> 1, hf = h & 1;
            int gy = gy0 + r - 1, gx = gx0 + xx - 1;
            bool ok = (gy >= 0) && (gy < Hd) && (gx >= 0) && (gx < Wd);
            const u32t* src = gin + (((size_t)(ok ? gy : 0)) * Wd + (ok ? gx : 0)) * 8 + hf * 4;
            int nbytes = ok ? 16 : 0;
            u32t dst = sin_b + (u32t)(((r * 34 + xx) * 8 + hf * 4) * 4);
            asm volatile("cp.async.cg.shared.global [%0], [%1], 16, %2;"
                         :: "r"(dst), "l"(src), "r"(nbytes));
        }
        const u32t* gw = wt + (size_t)k * W_W;
        const u32t sw_b = smbase + (u32t)((2 * IN_W + buf * W_W) * 4);
        for (int u = t; u < W_W / 4; u += NT) {
            asm volatile("cp.async.cg.shared.global [%0], [%1], 16, 16;"
                         :: "r"(sw_b + u * 16), "l"(gw + u * 4));
        }
    };

    float d[2][NOC][4];
#pragma unroll
    for (int m = 0; m < 2; m++)
#pragma unroll
        for (int n = 0; n < NOC; n++)
#pragma unroll
            for (int i = 0; i < 4; i++) d[m][n][i] = 0.f;

    stage(0, 0);
    asm volatile("cp.async.commit_group;");

    for (int k = 0; k < NC; k++) {
        if (k + 1 < NC) {
            stage(k + 1, (k + 1) & 1);
            asm volatile("cp.async.commit_group;");
            asm volatile("cp.async.wait_group 1;");
        } else {
            asm volatile("cp.async.wait_group 0;");
        }
        __syncthreads();
        const u32t* bin = sm + (k & 1) * IN_W;
        const u32t* bw  = sm + 2 * IN_W + (k & 1) * W_W;
#pragma unroll
        for (int tap = 0; tap < 9; tap++) {
            const int ky = tap / 3, kx = tap % 3;
            uint2 a[2][2];
#pragma unroll
            for (int m = 0; m < 2; m++) {
                const int xx = m * 16 + G + kx;
                a[m][0] = *(const uint2*)&bin[((warp + ky) * 34 + xx) * 8 + 2 * tig];
                a[m][1] = *(const uint2*)&bin[((warp + ky) * 34 + xx + 8) * 8 + 2 * tig];
            }
#pragma unroll
            for (int n = 0; n < NOC; n++) {
                uint2 q = *(const uint2*)&bw[(tap * (8 * NOC) + n * 8 + G) * 8 + 2 * tig];
#pragma unroll
                for (int m = 0; m < 2; m++)
                    mma_tf32(d[m][n], a[m][0].x, a[m][1].x, a[m][0].y, a[m][1].y,
                             q.x, q.y);
            }
        }
        __syncthreads();   // protect buffer reuse before next stage() overwrites
    }

    // ---- epilogue ----
    const int gy = gy0 + warp;
    if (NOC == 1) {
        // single output channel: only tig==0 holds oc 0 (cols 0)
        if (tig == 0) {
            float bv = __ldg(&bias[0]);
#pragma unroll
            for (int m = 0; m < 2; m++) {
                const int x = gx0 + m * 16 + G;
                float v0 = d[m][0][0] + bv;
                float v2 = d[m][0][2] + bv;
                if (RELU) { v0 = fmaxf(v0, 0.f); v2 = fmaxf(v2, 0.f); }
                outf[(size_t)b * HW + (size_t)gy * Wd + x]     = v0;
                outf[(size_t)b * HW + (size_t)gy * Wd + x + 8] = v2;
            }
        }
        return;
    }
    const int slotA = cslot(2 * tig), slotB = cslot(2 * tig + 1);
#pragma unroll
    for (int m = 0; m < 2; m++) {
        const int x = gx0 + m * 16 + G;
#pragma unroll
        for (int n = 0; n < NOC; n++) {
            const int oc = n * 8 + 2 * tig;
            float b0v = __ldg(&bias[oc]);
            float b1v = __ldg(&bias[oc + 1]);
            float v0 = d[m][n][0] + b0v;
            float v1 = d[m][n][1] + b1v;
            float v2 = d[m][n][2] + b0v;
            float v3 = d[m][n][3] + b1v;
            size_t f0 = (((size_t)b * 64 + oc) * Hd + gy) * Wd + x;
            size_t f1 = f0 + HW;
            if (SKIP) {
                v0 += skip[f0];     v1 += skip[f1];
                v2 += skip[f0 + 8]; v3 += skip[f1 + 8];
            }
            if (RELU) {
                v0 = fmaxf(v0, 0.f); v1 = fmaxf(v1, 0.f);
                v2 = fmaxf(v2, 0.f); v3 = fmaxf(v3, 0.f);
            }
            if (WF32) {
                outf[f0] = v0; outf[f1] = v1; outf[f0 + 8] = v2; outf[f1 + 8] = v3;
            }
            if (WT32) {
                size_t tb = (((size_t)b * 8 + n) * HW + (size_t)gy * Wd + x) * 8;
                outt[tb + slotA]      = tf32b(v0);
                outt[tb + slotB]      = tf32b(v1);
                outt[tb + 64 + slotA] = tf32b(v2);
                outt[tb + 64 + slotB] = tf32b(v3);
            }
        }
    }
}

#define SMEM_TY8  ((2*10*34*8 + 2*576*8) * 4)   // 58624
#define SMEM_TY4  ((2*6*34*8  + 2*576*8) * 4)   // 49920
#define SMEM_C1   ((2*10*34*8 + 2*576*1) * 4)   // 26368

// ---------------------------------------------------------------------------
// fuse: hidden + logits GEMMs via tf32 MMA, softmax tail.
// Block = 64 px, 256 threads, 8 warps.
// ---------------------------------------------------------------------------
__global__ __launch_bounds__(256)
void fuse_kernel(const float* __restrict__ depth, const float* __restrict__ guide,
                 const float* __restrict__ wmap,
                 const float* __restrict__ dkw1, const float* __restrict__ dkb1,
                 const float* __restrict__ dkw2, const float* __restrict__ dkb2,
                 const float* __restrict__ gkw1, const float* __restrict__ gkb1,
                 const float* __restrict__ gkw2, const float* __restrict__ gkb2,
                 const float* __restrict__ aff,  float* __restrict__ fuse) {
    __shared__ u32t  s_xT[64][65];       // [px][ci] tf32
    __shared__ u32t  s_hT[64][65];       // [px][c]  tf32 hidden
    __shared__ float s_l[2][9][64];

    const int b    = blockIdx.y;
    const int px0  = blockIdx.x * 64;
    const int t    = threadIdx.x;
    const int warp = t >> 5, lane = t & 31;
    const int G    = lane >> 2, tig = lane & 3;
    const int mt   = warp & 3, nh = warp >> 2;
    const int c0   = mt * 16;

#pragma unroll
    for (int branch = 0; branch < 2; branch++) {
        const float* X   = branch ? guide : depth;
        const float* W1  = branch ? gkw1  : dkw1;
        const float* B1v = branch ? gkb1  : dkb1;
        const float* W2  = branch ? gkw2  : dkw2;
        const float* B2v = branch ? gkb2  : dkb2;

        __syncthreads();
        for (int idx = t; idx < 4096; idx += 256) {
            int ci = idx >> 6, p = idx & 63;
            s_xT[p][ci] = tf32b(X[((size_t)b * 64 + ci) * HW2_ + px0 + p]);
        }
        u32t af[8][4];
#pragma unroll
        for (int kc = 0; kc < 8; kc++) {
            int k0 = kc * 8;
            af[kc][0] = tf32b(__ldg(&W1[(c0 + G)     * 64 + k0 + tig]));
            af[kc][1] = tf32b(__ldg(&W1[(c0 + G + 8) * 64 + k0 + tig]));
            af[kc][2] = tf32b(__ldg(&W1[(c0 + G)     * 64 + k0 + tig + 4]));
            af[kc][3] = tf32b(__ldg(&W1[(c0 + G + 8) * 64 + k0 + tig + 4]));
        }
        __syncthreads();

        // hidden = relu(W1 @ X), written transposed as tf32
        float d[4][4];
#pragma unroll
        for (int nc = 0; nc < 4; nc++)
#pragma unroll
            for (int i = 0; i < 4; i++) d[nc][i] = 0.f;
#pragma unroll
        for (int kc = 0; kc < 8; kc++) {
            int k0 = kc * 8;
#pragma unroll
            for (int nc = 0; nc < 4; nc++) {
                int n0 = nh * 32 + nc * 8;
                u32t b0 = s_xT[n0 + G][k0 + tig];
                u32t b1 = s_xT[n0 + G][k0 + tig + 4];
                mma_tf32(d[nc], af[kc][0], af[kc][1], af[kc][2], af[kc][3], b0, b1);
            }
        }
        float bv0 = __ldg(&B1v[c0 + G]);
        float bv8 = __ldg(&B1v[c0 + G + 8]);
#pragma unroll
        for (int nc = 0; nc < 4; nc++) {
            int px = nh * 32 + nc * 8 + 2 * tig;
            s_hT[px][c0 + G]         = tf32b(fmaxf(d[nc][0] + bv0, 0.f));
            s_hT[px + 1][c0 + G]     = tf32b(fmaxf(d[nc][1] + bv0, 0.f));
            s_hT[px][c0 + G + 8]     = tf32b(fmaxf(d[nc][2] + bv8, 0.f));
            s_hT[px + 1][c0 + G + 8] = tf32b(fmaxf(d[nc][3] + bv8, 0.f));
        }
        __syncthreads();

        // logits = W2 @ hidden (M=16 pad, rows 0..8 real), warp = px n-chunk
        {
            const int n0 = warp * 8;
            float d2[4] = {0.f, 0.f, 0.f, 0.f};
#pragma unroll
            for (int kc = 0; kc < 8; kc++) {
                int k0 = kc * 8;
                u32t a0 = tf32b(__ldg(&W2[G * 64 + k0 + tig]));
                u32t a1 = (G == 0) ? tf32b(__ldg(&W2[8 * 64 + k0 + tig])) : 0u;
                u32t a2 = tf32b(__ldg(&W2[G * 64 + k0 + tig + 4]));
                u32t a3 = (G == 0) ? tf32b(__ldg(&W2[8 * 64 + k0 + tig + 4])) : 0u;
                u32t b0 = s_hT[n0 + G][k0 + tig];
                u32t b1 = s_hT[n0 + G][k0 + tig + 4];
                mma_tf32(d2, a0, a1, a2, a3, b0, b1);
            }
            float bj = __ldg(&B2v[G]);
            s_l[branch][G][n0 + 2 * tig]     = d2[0] + bj;
            s_l[branch][G][n0 + 2 * tig + 1] = d2[1] + bj;
            if (G == 0) {
                float b8 = __ldg(&B2v[8]);
                s_l[branch][8][n0 + 2 * tig]     = d2[2] + b8;
                s_l[branch][8][n0 + 2 * tig + 1] = d2[3] + b8;
            }
        }
    }
    __syncthreads();

    if (t < 64) {
        float wm = wmap[(size_t)b * HW2_ + px0 + t];
        float dmax = -1e30f, gmax = -1e30f;
#pragma unroll
        for (int j = 0; j < 9; j++) {
            dmax = fmaxf(dmax, s_l[0][j][t]);
            gmax = fmaxf(gmax, s_l[1][j][t]);
        }
        float de[9], ge[9], ds = 0.f, gs = 0.f;
#pragma unroll
        for (int j = 0; j < 9; j++) {
            de[j] = expf(s_l[0][j][t] - dmax); ds += de[j];
            ge[j] = expf(s_l[1][j][t] - gmax); gs += ge[j];
        }
        float affv = __ldg(&aff[0]) + 1e-8f;
        float inv_d = 1.f / ds, inv_g = 1.f / gs;
        float f[9], asum = 0.f;
#pragma unroll
        for (int j = 0; j < 9; j++) {
            float fv = wm * (de[j] * inv_d) + (1.f - wm) * (ge[j] * inv_g);
            fv = tanhf(fv) / affv;
            f[j] = fv;
            asum += fabsf(fv);
        }
        float inv_ks = 1.f / fmaxf(asum + 1e-4f, 1.0f);
#pragma unroll
        for (int j = 0; j < 9; j++)
            fuse[((size_t)b * 9 + j) * HW2_ + px0 + t] = f[j] * inv_ks;
    }
}

// ---------------------------------------------------------------------------
__global__ void upsample2x(const float* __restrict__ in, float* __restrict__ out) {
    int idx = blockIdx.x * blockDim.x + threadIdx.x;
    if (idx >= B_ * C_ * HW2_) return;
    int x  = idx & 255;
    int y  = (idx >> 8) & 255;
    int bc = idx >> 16;
    int m = y >> 1, ya, yb; float wya, wyb;
    if ((y & 1) == 0) { ya = (m - 1 < 0) ? 0 : m - 1; yb = m;  wya = 0.25f; wyb = 0.75f; }
    else              { ya = m; yb = (m + 1 > 127) ? 127 : m + 1; wya = 0.75f; wyb = 0.25f; }
    int n = x >> 1, xa, xb; float wxa, wxb;
    if ((x & 1) == 0) { xa = (n - 1 < 0) ? 0 : n - 1; xb = n;  wxa = 0.25f; wxb = 0.75f; }
    else              { xa = n; xb = (n + 1 > 127) ? 127 : n + 1; wxa = 0.75f; wxb = 0.25f; }
    const float* p = in + (size_t)bc * HW1_;
    out[idx] = wya * (wxa * p[ya * 128 + xa] + wxb * p[ya * 128 + xb]) +
               wyb * (wxa * p[yb * 128 + xa] + wxb * p[yb * 128 + xb]);
}

// ---------------------------------------------------------------------------
__global__ __launch_bounds__(256)
void gather_kernel(const float* __restrict__ fuse, const float* __restrict__ up,
                   float* __restrict__ out) {
    __shared__ float s_up[4][12][37];
    const int b   = blockIdx.z;
    const int gx0 = blockIdx.x * 32;
    const int gy0 = blockIdx.y * 8;
    const int t   = threadIdx.x;
    const int xl  = t & 31, yl = t >> 5;
    const int gx  = gx0 + xl, gy = gy0 + yl;

    float f[9];
#pragma unroll
    for (int j = 0; j < 9; j++)
        f[j] = fuse[((size_t)b * 9 + j) * HW2_ + gy * W2_ + gx];

    for (int c0 = 0; c0 < 64; c0 += 4) {
        __syncthreads();
        for (int idx = t; idx < 4 * 432; idx += 256) {
            int cl = idx / 432, rem = idx % 432;
            int r = rem / 36, cc = rem % 36;
            int yy = gy0 + r - 2, xx = gx0 + cc - 2;
            float v = 0.f;
            if (yy >= 0 && yy < H2_ && xx >= 0 && xx < W2_)
                v = up[((size_t)b * 64 + c0 + cl) * (size_t)HW2_ + yy * W2_ + xx];
            s_up[cl][r][cc] = v;
        }
        __syncthreads();
#pragma unroll
        for (int cl = 0; cl < 4; cl++) {
            float acc = 0.f;
#pragma unroll
            for (int ky = 0; ky < 3; ky++)
#pragma unroll
                for (int kx = 0; kx < 3; kx++)
                    acc += f[ky * 3 + kx] * s_up[cl][yl + 2 * ky][xl + 2 * kx];
            out[(((size_t)b * 64 + c0 + cl) * H2_ + gy) * W2_ + gx] = acc;
        }
    }
}

// ---------------------------------------------------------------------------
extern "C" void kernel_launch(void* const* d_in, const int* in_sizes, int n_in,
                              void* d_out, int out_size) {
    const float* depth  = (const float*)d_in[0];
    const float* guide  = (const float*)d_in[1];
    const float* inputs = (const float*)d_in[2];
    const float* dk_w1  = (const float*)d_in[3];
    const float* dk_b1  = (const float*)d_in[4];
    const float* dk_w2  = (const float*)d_in[5];
    const float* dk_b2  = (const float*)d_in[6];
    const float* gk_w1  = (const float*)d_in[7];
    const float* gk_b1  = (const float*)d_in[8];
    const float* gk_w2  = (const float*)d_in[9];
    const float* gk_b2  = (const float*)d_in[10];
    const float* wn_w1  = (const float*)d_in[11];
    const float* wn_b1  = (const float*)d_in[12];
    const float* wn_w2  = (const float*)d_in[13];
    const float* wn_b2  = (const float*)d_in[14];
    const float* wn_w3  = (const float*)d_in[15];
    const float* wn_b3  = (const float*)d_in[16];
    const float* rb_w   = (const float*)d_in[17];
    const float* rb_b   = (const float*)d_in[18];
    const float* aff    = (const float*)d_in[19];
    float* out = (float*)d_out;

    float *p_wmap, *p_fuse, *p_r2, *p_r3, *p_up;
    u32t *pt_in0, *pt_wm1, *pt_wm2, *pt_inlo, *pt_r1, *pt_r2, *pt_r3;
    u32t *pt_wn1, *pt_wn2, *pt_rb, *pt_wn3;
    cudaGetSymbolAddress((void**)&p_wmap, g_wmap);
    cudaGetSymbolAddress((void**)&p_fuse, g_fuse);
    cudaGetSymbolAddress((void**)&p_r2,   g_r2);
    cudaGetSymbolAddress((void**)&p_r3,   g_r3);
    cudaGetSymbolAddress((void**)&p_up,   g_up);
    cudaGetSymbolAddress((void**)&pt_in0,  gt_in0);
    cudaGetSymbolAddress((void**)&pt_wm1,  gt_wm1);
    cudaGetSymbolAddress((void**)&pt_wm2,  gt_wm2);
    cudaGetSymbolAddress((void**)&pt_inlo, gt_inlo);
    cudaGetSymbolAddress((void**)&pt_r1,   gt_r1);
    cudaGetSymbolAddress((void**)&pt_r2,   gt_r2);
    cudaGetSymbolAddress((void**)&pt_r3,   gt_r3);
    cudaGetSymbolAddress((void**)&pt_wn1,  gt_wn1);
    cudaGetSymbolAddress((void**)&pt_wn2,  gt_wn2);
    cudaGetSymbolAddress((void**)&pt_rb,   gt_rb);
    cudaGetSymbolAddress((void**)&pt_wn3,  gt_wn3);

    cudaFuncSetAttribute(conv3x3_cp<16, 8, 8, true,  false, false, true >, cudaFuncAttributeMaxDynamicSharedMemorySize, SMEM_TY8);
    cudaFuncSetAttribute(conv3x3_cp<8,  8, 8, true,  false, false, true >, cudaFuncAttributeMaxDynamicSharedMemorySize, SMEM_TY8);
    cudaFuncSetAttribute(conv3x3_cp<8,  1, 8, false, false, true,  false>, cudaFuncAttributeMaxDynamicSharedMemorySize, SMEM_C1);
    cudaFuncSetAttribute(conv3x3_cp<8,  8, 4, true,  false, false, true >, cudaFuncAttributeMaxDynamicSharedMemorySize, SMEM_TY4);
    cudaFuncSetAttribute(conv3x3_cp<8,  8, 4, false, true,  true,  true >, cudaFuncAttributeMaxDynamicSharedMemorySize, SMEM_TY4);
    cudaFuncSetAttribute(conv3x3_cp<8,  8, 4, false, true,  true,  false>, cudaFuncAttributeMaxDynamicSharedMemorySize, SMEM_TY4);

    dim3 ghi8(W2_ / 32, H2_ / 8, B_);   // 8, 32, 2
    dim3 glo4(W1_ / 32, H1_ / 4, B_);   // 4, 32, 2

    // pre-pass conversions
    prep_inputs<<<(B_*16*HW2_ + B_*8*HW1_) / 256, 256>>>(depth, guide, inputs, pt_in0, pt_inlo);
    prep_weights<<<(73728 + 36864 + 147456 + 4608) / 256, 256>>>(wn_w1, wn_w2, rb_w, wn_w3,
                                                                 pt_wn1, pt_wn2, pt_rb, pt_wn3);

    // weight-map trunk (all tensor-core)
    conv3x3_cp<16, 8, 8, true,  false, false, true ><<<ghi8, 256, SMEM_TY8>>>(pt_in0, pt_wn1, wn_b1, nullptr, nullptr, pt_wm1, H2_, W2_);
    conv3x3_cp<8,  8, 8, true,  false, false, true ><<<ghi8, 256, SMEM_TY8>>>(pt_wm1, pt_wn2, wn_b2, nullptr, nullptr, pt_wm2, H2_, W2_);
    conv3x3_cp<8,  1, 8, false, false, true,  false><<<ghi8, 256, SMEM_C1>>>(pt_wm2, pt_wn3, wn_b3, nullptr, p_wmap, nullptr, H2_, W2_);

    // per-pixel kernel fusion branch
    dim3 gfuse(HW2_ / 64, B_);
    fuse_kernel<<<gfuse, 256>>>(depth, guide, p_wmap,
                                dk_w1, dk_b1, dk_w2, dk_b2,
                                gk_w1, gk_b1, gk_w2, gk_b2,
                                aff, p_fuse);

    // residual stack on low-res inputs (TY=4, 256 blocks)
    conv3x3_cp<8, 8, 4, true,  false, false, true ><<<glo4, 128, SMEM_TY4>>>(pt_inlo, pt_rb + 0*36864, rb_b + 0,   nullptr, nullptr, pt_r1, H1_, W1_);
    conv3x3_cp<8, 8, 4, false, true,  true,  true ><<<glo4, 128, SMEM_TY4>>>(pt_r1,   pt_rb + 1*36864, rb_b + 64,  inputs,  p_r2,    pt_r2, H1_, W1_);
    conv3x3_cp<8, 8, 4, true,  false, false, true ><<<glo4, 128, SMEM_TY4>>>(pt_r2,   pt_rb + 2*36864, rb_b + 128, nullptr, nullptr, pt_r3, H1_, W1_);
    conv3x3_cp<8, 8, 4, false, true,  true,  false><<<glo4, 128, SMEM_TY4>>>(pt_r3,   pt_rb + 3*36864, rb_b + 192, p_r2,    p_r3,    nullptr, H1_, W1_);

    // upsample + gather
    upsample2x<<<(B_ * C_ * HW2_ + 255) / 256, 256>>>(p_r3, p_up);
    gather_kernel<<<ghi8, 256>>>(p_fuse, p_up, out);
}

// round 7
// speedup vs baseline: 5.5662x; 1.3921x over previous
#include <cuda_runtime.h>
#include <cuda_fp16.h>
#include <math.h>

#define B_  2
#define C_  64
#define H2_ 256
#define W2_ 256
#define HW2_ (H2_*W2_)
#define H1_ 128
#define W1_ 128
#define HW1_ (H1_*W1_)
#define KK_ 9

typedef unsigned long long u64t;
typedef unsigned int u32t;

__device__ __forceinline__ u32t tf32b(float f) {
    u32t r; asm("cvt.rna.tf32.f32 %0, %1;" : "=r"(r) : "f"(f)); return r;
}
__device__ __forceinline__ void mma_tf32(float* d, u32t a0, u32t a1, u32t a2, u32t a3,
                                         u32t b0, u32t b1) {
    asm("mma.sync.aligned.m16n8k8.row.col.f32.tf32.tf32.f32 "
        "{%0,%1,%2,%3},{%4,%5,%6,%7},{%8,%9},{%0,%1,%2,%3};"
        : "+f"(d[0]), "+f"(d[1]), "+f"(d[2]), "+f"(d[3])
        : "r"(a0), "r"(a1), "r"(a2), "r"(a3), "r"(b0), "r"(b1));
}
__device__ __forceinline__ void mma_f16(float* d, u32t a0, u32t a1, u32t a2, u32t a3,
                                        u32t b0, u32t b1) {
    asm("mma.sync.aligned.m16n8k16.row.col.f32.f16.f16.f32 "
        "{%0,%1,%2,%3},{%4,%5,%6,%7},{%8,%9},{%0,%1,%2,%3};"
        : "+f"(d[0]), "+f"(d[1]), "+f"(d[2]), "+f"(d[3])
        : "r"(a0), "r"(a1), "r"(a2), "r"(a3), "r"(b0), "r"(b1));
}
// pair-slot interleave: pairs (p, p+4) adjacent -> one LDS.64 per k16 fragment
__device__ __forceinline__ int cslot(int p) { return ((p & 3) << 1) | (p >> 2); }
__device__ __forceinline__ u32t packh2(float lo, float hi) {
    __half2 h = __floats2half2_rn(lo, hi);
    return *(u32t*)&h;
}

// ---------------- scratch ----------------
__device__ float g_wmap[B_*HW2_];
__device__ float g_fuse[B_*KK_*HW2_];
__device__ float g_r2[B_*C_*HW1_];     // x1 (fp32, skip source)
__device__ float g_r3[B_*C_*HW1_];     // final x (fp32)
__device__ float g_up[B_*C_*HW2_];

// fp16 pair-interleaved buffers: [b][chunk16][px][8 words]
__device__ u32t gt_in0[B_*8*HW2_*8];   // depth||guide (128 ch = 8 chunks)
__device__ u32t gt_wm1[B_*4*HW2_*8];
__device__ u32t gt_wm2[B_*4*HW2_*8];
__device__ u32t gt_inlo[B_*4*HW1_*8];
__device__ u32t gt_r1[B_*4*HW1_*8];
__device__ u32t gt_r2[B_*4*HW1_*8];
__device__ u32t gt_r3[B_*4*HW1_*8];
// fp16 weights: [chunk16][tap][oc][8 words]
__device__ u32t gt_wn1[8*9*64*8];
__device__ u32t gt_wn2[4*9*64*8];
__device__ u32t gt_rb [4*4*9*64*8];
__device__ u32t gt_wn3[4*9*8*8];       // NOC=1, oc padded to 8

// ---------------------------------------------------------------------------
// prep: NCHW fp32 -> fp16 pair-interleaved
// ---------------------------------------------------------------------------
__global__ void prep_inputs(const float* __restrict__ depth, const float* __restrict__ guide,
                            const float* __restrict__ inputs,
                            u32t* __restrict__ in0_t, u32t* __restrict__ inlo_t) {
    int idx = blockIdx.x * 256 + threadIdx.x;
    const int N0 = B_ * 8 * HW2_;
    if (idx < N0) {
        int px = idx & (HW2_ - 1);
        int ch = (idx >> 16) & 7;
        int b  = idx >> 19;
        const float* src = (ch < 4 ? depth : guide) + ((size_t)b * 64 + (ch & 3) * 16) * HW2_ + px;
        u32t w[8];
#pragma unroll
        for (int ws = 0; ws < 8; ws++) {
            int p = (ws >> 1) + ((ws & 1) << 2);
            w[ws] = packh2(src[(size_t)(2 * p) * HW2_], src[(size_t)(2 * p + 1) * HW2_]);
        }
        *(uint4*)&in0_t[(size_t)idx * 8]     = make_uint4(w[0], w[1], w[2], w[3]);
        *(uint4*)&in0_t[(size_t)idx * 8 + 4] = make_uint4(w[4], w[5], w[6], w[7]);
    } else {
        int j = idx - N0;
        int px = j & (HW1_ - 1);
        int ch = (j >> 14) & 3;
        int b  = j >> 16;
        const float* src = inputs + ((size_t)b * 64 + ch * 16) * HW1_ + px;
        u32t w[8];
#pragma unroll
        for (int ws = 0; ws < 8; ws++) {
            int p = (ws >> 1) + ((ws & 1) << 2);
            w[ws] = packh2(src[(size_t)(2 * p) * HW1_], src[(size_t)(2 * p + 1) * HW1_]);
        }
        *(uint4*)&inlo_t[(size_t)j * 8]     = make_uint4(w[0], w[1], w[2], w[3]);
        *(uint4*)&inlo_t[(size_t)j * 8 + 4] = make_uint4(w[4], w[5], w[6], w[7]);
    }
}

__device__ __forceinline__ void wcvt(const float* __restrict__ w, u32t* __restrict__ o,
                                     int widx, int CIN) {
    int ws  = widx & 7;
    int oc  = (widx >> 3) & 63;
    int rem = widx >> 9;
    int tap = rem % 9, chunk = rem / 9;
    int p   = (ws >> 1) + ((ws & 1) << 2);
    int c0  = chunk * 16 + 2 * p;
    o[widx] = packh2(w[(oc * CIN + c0) * 9 + tap], w[(oc * CIN + c0 + 1) * 9 + tap]);
}

__global__ void prep_weights(const float* __restrict__ wn1, const float* __restrict__ wn2,
                             const float* __restrict__ rb,  const float* __restrict__ wn3,
                             u32t* __restrict__ t1, u32t* __restrict__ t2,
                             u32t* __restrict__ trb, u32t* __restrict__ t3) {
    int idx = blockIdx.x * 256 + threadIdx.x;
    if (idx < 36864) {
        wcvt(wn1, t1, idx, 128);
    } else if (idx < 55296) {
        wcvt(wn2, t2, idx - 36864, 64);
    } else if (idx < 129024) {
        int j = idx - 55296;
        int r = j / 18432, jj = j - r * 18432;
        wcvt(rb + r * 36864, trb + r * 18432, jj, 64);
    } else if (idx < 131328) {
        int j = idx - 129024;           // [chunk][tap][oc8][ws8]
        int chunk = j / 576, rem = j % 576;
        int tap = rem >> 6, oc = (rem >> 3) & 7, ws = rem & 7;
        int p = (ws >> 1) + ((ws & 1) << 2);
        int c0 = chunk * 16 + 2 * p;
        t3[j] = (oc == 0) ? packh2(wn3[c0 * 9 + tap], wn3[(c0 + 1) * 9 + tap]) : 0u;
    }
}

// ---------------------------------------------------------------------------
// fp16 implicit-GEMM 3x3 conv, cp.async double-buffered, m16n8k16.
// Tile 32 x TY px, 32*TY threads. NC chunks of 16 ic. NOC n-chunks of 8 oc.
// ---------------------------------------------------------------------------
template<int NC, int NOC, int TY, bool RELU, bool SKIP, bool WF32, bool WT16>
__global__ __launch_bounds__(TY*32, (TY == 8) ? 2 : 4)
void conv3x3_cp(const u32t* __restrict__ in_t, const u32t* __restrict__ wt,
                const float* __restrict__ bias, const float* __restrict__ skip,
                float* __restrict__ outf, u32t* __restrict__ outt,
                int Hd, int Wd) {
    constexpr int NT   = TY * 32;
    constexpr int HR   = TY + 2;
    constexpr int IN_W = HR * 34 * 8;      // words per input buffer (32B/px)
    constexpr int W_W  = 576 * NOC;        // words per weight buffer
    extern __shared__ u32t sm[];
    const int t    = threadIdx.x;
    const int warp = t >> 5, lane = t & 31;
    const int G    = lane >> 2, tig = lane & 3;
    const int b    = blockIdx.z;
    const int gx0  = blockIdx.x * 32;
    const int gy0  = blockIdx.y * TY;
    const size_t HW = (size_t)Hd * Wd;

    const u32t smbase = (u32t)__cvta_generic_to_shared(sm);

    auto stage = [&](int k, int buf) {
        const u32t* gin = in_t + ((size_t)b * NC + k) * HW * 8;
        const u32t sin_b = smbase + buf * (IN_W * 4);
        for (int u = t; u < HR * 68; u += NT) {
            int r  = u / 68, h = u - r * 68;
            int xx = h >> 1, hf = h & 1;
            int gy = gy0 + r - 1, gx = gx0 + xx - 1;
            bool ok = (gy >= 0) && (gy < Hd) && (gx >= 0) && (gx < Wd);
            const u32t* src = gin + (((size_t)(ok ? gy : 0)) * Wd + (ok ? gx : 0)) * 8 + hf * 4;
            int nbytes = ok ? 16 : 0;
            u32t dst = sin_b + (u32t)(((r * 34 + xx) * 8 + hf * 4) * 4);
            asm volatile("cp.async.cg.shared.global [%0], [%1], 16, %2;"
                         :: "r"(dst), "l"(src), "r"(nbytes));
        }
        const u32t* gw = wt + (size_t)k * W_W;
        const u32t sw_b = smbase + (u32t)((2 * IN_W + buf * W_W) * 4);
        for (int u = t; u < W_W / 4; u += NT) {
            asm volatile("cp.async.cg.shared.global [%0], [%1], 16, 16;"
                         :: "r"(sw_b + u * 16), "l"(gw + u * 4));
        }
    };

    float d[2][NOC][4];
#pragma unroll
    for (int m = 0; m < 2; m++)
#pragma unroll
        for (int n = 0; n < NOC; n++)
#pragma unroll
            for (int i = 0; i < 4; i++) d[m][n][i] = 0.f;

    stage(0, 0);
    asm volatile("cp.async.commit_group;");

    for (int k = 0; k < NC; k++) {
        if (k + 1 < NC) {
            stage(k + 1, (k + 1) & 1);
            asm volatile("cp.async.commit_group;");
            asm volatile("cp.async.wait_group 1;");
        } else {
            asm volatile("cp.async.wait_group 0;");
        }
        __syncthreads();
        const u32t* bin = sm + (k & 1) * IN_W;
        const u32t* bw  = sm + 2 * IN_W + (k & 1) * W_W;
#pragma unroll
        for (int tap = 0; tap < 9; tap++) {
            const int ky = tap / 3, kx = tap % 3;
            uint2 a[2][2];
#pragma unroll
            for (int m = 0; m < 2; m++) {
                const int xx = m * 16 + G + kx;
                a[m][0] = *(const uint2*)&bin[((warp + ky) * 34 + xx) * 8 + 2 * tig];
                a[m][1] = *(const uint2*)&bin[((warp + ky) * 34 + xx + 8) * 8 + 2 * tig];
            }
#pragma unroll
            for (int n = 0; n < NOC; n++) {
                uint2 q = *(const uint2*)&bw[(tap * (8 * NOC) + n * 8 + G) * 8 + 2 * tig];
#pragma unroll
                for (int m = 0; m < 2; m++)
                    mma_f16(d[m][n], a[m][0].x, a[m][1].x, a[m][0].y, a[m][1].y,
                            q.x, q.y);
            }
        }
        __syncthreads();   // protect buffer reuse before next stage() overwrites
    }

    // ---- epilogue ----
    const int gy = gy0 + warp;
    if (NOC == 1) {
        if (tig == 0) {
            float bv = __ldg(&bias[0]);
#pragma unroll
            for (int m = 0; m < 2; m++) {
                const int x = gx0 + m * 16 + G;
                float v0 = d[m][0][0] + bv;
                float v2 = d[m][0][2] + bv;
                if (RELU) { v0 = fmaxf(v0, 0.f); v2 = fmaxf(v2, 0.f); }
                outf[(size_t)b * HW + (size_t)gy * Wd + x]     = v0;
                outf[(size_t)b * HW + (size_t)gy * Wd + x + 8] = v2;
            }
        }
        return;
    }
#pragma unroll
    for (int m = 0; m < 2; m++) {
        const int x = gx0 + m * 16 + G;
#pragma unroll
        for (int n = 0; n < NOC; n++) {
            const int oc = n * 8 + 2 * tig;
            float b0v = __ldg(&bias[oc]);
            float b1v = __ldg(&bias[oc + 1]);
            float v0 = d[m][n][0] + b0v;
            float v1 = d[m][n][1] + b1v;
            float v2 = d[m][n][2] + b0v;
            float v3 = d[m][n][3] + b1v;
            size_t f0 = (((size_t)b * 64 + oc) * Hd + gy) * Wd + x;
            size_t f1 = f0 + HW;
            if (SKIP) {
                v0 += skip[f0];     v1 += skip[f1];
                v2 += skip[f0 + 8]; v3 += skip[f1 + 8];
            }
            if (RELU) {
                v0 = fmaxf(v0, 0.f); v1 = fmaxf(v1, 0.f);
                v2 = fmaxf(v2, 0.f); v3 = fmaxf(v3, 0.f);
            }
            if (WF32) {
                outf[f0] = v0; outf[f1] = v1; outf[f0 + 8] = v2; outf[f1 + 8] = v3;
            }
            if (WT16) {
                // chunk = n>>1; pair p = (n&1)*4 + tig -> word slot 2*tig + (n&1)
                int slot = 2 * tig + (n & 1);
                size_t tb = (((size_t)b * 4 + (n >> 1)) * HW + (size_t)gy * Wd + x) * 8;
                outt[tb + slot]      = packh2(v0, v1);
                outt[tb + 64 + slot] = packh2(v2, v3);
            }
        }
    }
}

#define SMEM_TY8  ((2*10*34*8 + 2*576*8) * 4)   // 58624
#define SMEM_TY4  ((2*6*34*8  + 2*576*8) * 4)   // 49920
#define SMEM_C1   ((2*10*34*8 + 2*576*1) * 4)   // 26368

// ---------------------------------------------------------------------------
// fuse: hidden + logits GEMMs via tf32 MMA, softmax tail. (unchanged)
// ---------------------------------------------------------------------------
__global__ __launch_bounds__(256)
void fuse_kernel(const float* __restrict__ depth, const float* __restrict__ guide,
                 const float* __restrict__ wmap,
                 const float* __restrict__ dkw1, const float* __restrict__ dkb1,
                 const float* __restrict__ dkw2, const float* __restrict__ dkb2,
                 const float* __restrict__ gkw1, const float* __restrict__ gkb1,
                 const float* __restrict__ gkw2, const float* __restrict__ gkb2,
                 const float* __restrict__ aff,  float* __restrict__ fuse) {
    __shared__ u32t  s_xT[64][65];
    __shared__ u32t  s_hT[64][65];
    __shared__ float s_l[2][9][64];

    const int b    = blockIdx.y;
    const int px0  = blockIdx.x * 64;
    const int t    = threadIdx.x;
    const int warp = t >> 5, lane = t & 31;
    const int G    = lane >> 2, tig = lane & 3;
    const int mt   = warp & 3, nh = warp >> 2;
    const int c0   = mt * 16;

#pragma unroll
    for (int branch = 0; branch < 2; branch++) {
        const float* X   = branch ? guide : depth;
        const float* W1  = branch ? gkw1  : dkw1;
        const float* B1v = branch ? gkb1  : dkb1;
        const float* W2  = branch ? gkw2  : dkw2;
        const float* B2v = branch ? gkb2  : dkb2;

        __syncthreads();
        for (int idx = t; idx < 4096; idx += 256) {
            int ci = idx >> 6, p = idx & 63;
            s_xT[p][ci] = tf32b(X[((size_t)b * 64 + ci) * HW2_ + px0 + p]);
        }
        u32t af[8][4];
#pragma unroll
        for (int kc = 0; kc < 8; kc++) {
            int k0 = kc * 8;
            af[kc][0] = tf32b(__ldg(&W1[(c0 + G)     * 64 + k0 + tig]));
            af[kc][1] = tf32b(__ldg(&W1[(c0 + G + 8) * 64 + k0 + tig]));
            af[kc][2] = tf32b(__ldg(&W1[(c0 + G)     * 64 + k0 + tig + 4]));
            af[kc][3] = tf32b(__ldg(&W1[(c0 + G + 8) * 64 + k0 + tig + 4]));
        }
        __syncthreads();

        float d[4][4];
#pragma unroll
        for (int nc = 0; nc < 4; nc++)
#pragma unroll
            for (int i = 0; i < 4; i++) d[nc][i] = 0.f;
#pragma unroll
        for (int kc = 0; kc < 8; kc++) {
            int k0 = kc * 8;
#pragma unroll
            for (int nc = 0; nc < 4; nc++) {
                int n0 = nh * 32 + nc * 8;
                u32t b0 = s_xT[n0 + G][k0 + tig];
                u32t b1 = s_xT[n0 + G][k0 + tig + 4];
                mma_tf32(d[nc], af[kc][0], af[kc][1], af[kc][2], af[kc][3], b0, b1);
            }
        }
        float bv0 = __ldg(&B1v[c0 + G]);
        float bv8 = __ldg(&B1v[c0 + G + 8]);
#pragma unroll
        for (int nc = 0; nc < 4; nc++) {
            int px = nh * 32 + nc * 8 + 2 * tig;
            s_hT[px][c0 + G]         = tf32b(fmaxf(d[nc][0] + bv0, 0.f));
            s_hT[px + 1][c0 + G]     = tf32b(fmaxf(d[nc][1] + bv0, 0.f));
            s_hT[px][c0 + G + 8]     = tf32b(fmaxf(d[nc][2] + bv8, 0.f));
            s_hT[px + 1][c0 + G + 8] = tf32b(fmaxf(d[nc][3] + bv8, 0.f));
        }
        __syncthreads();

        {
            const int n0 = warp * 8;
            float d2[4] = {0.f, 0.f, 0.f, 0.f};
#pragma unroll
            for (int kc = 0; kc < 8; kc++) {
                int k0 = kc * 8;
                u32t a0 = tf32b(__ldg(&W2[G * 64 + k0 + tig]));
                u32t a1 = (G == 0) ? tf32b(__ldg(&W2[8 * 64 + k0 + tig])) : 0u;
                u32t a2 = tf32b(__ldg(&W2[G * 64 + k0 + tig + 4]));
                u32t a3 = (G == 0) ? tf32b(__ldg(&W2[8 * 64 + k0 + tig + 4])) : 0u;
                u32t b0 = s_hT[n0 + G][k0 + tig];
                u32t b1 = s_hT[n0 + G][k0 + tig + 4];
                mma_tf32(d2, a0, a1, a2, a3, b0, b1);
            }
            float bj = __ldg(&B2v[G]);
            s_l[branch][G][n0 + 2 * tig]     = d2[0] + bj;
            s_l[branch][G][n0 + 2 * tig + 1] = d2[1] + bj;
            if (G == 0) {
                float b8 = __ldg(&B2v[8]);
                s_l[branch][8][n0 + 2 * tig]     = d2[2] + b8;
                s_l[branch][8][n0 + 2 * tig + 1] = d2[3] + b8;
            }
        }
    }
    __syncthreads();

    if (t < 64) {
        float wm = wmap[(size_t)b * HW2_ + px0 + t];
        float dmax = -1e30f, gmax = -1e30f;
#pragma unroll
        for (int j = 0; j < 9; j++) {
            dmax = fmaxf(dmax, s_l[0][j][t]);
            gmax = fmaxf(gmax, s_l[1][j][t]);
        }
        float de[9], ge[9], ds = 0.f, gs = 0.f;
#pragma unroll
        for (int j = 0; j < 9; j++) {
            de[j] = expf(s_l[0][j][t] - dmax); ds += de[j];
            ge[j] = expf(s_l[1][j][t] - gmax); gs += ge[j];
        }
        float affv = __ldg(&aff[0]) + 1e-8f;
        float inv_d = 1.f / ds, inv_g = 1.f / gs;
        float f[9], asum = 0.f;
#pragma unroll
        for (int j = 0; j < 9; j++) {
            float fv = wm * (de[j] * inv_d) + (1.f - wm) * (ge[j] * inv_g);
            fv = tanhf(fv) / affv;
            f[j] = fv;
            asum += fabsf(fv);
        }
        float inv_ks = 1.f / fmaxf(asum + 1e-4f, 1.0f);
#pragma unroll
        for (int j = 0; j < 9; j++)
            fuse[((size_t)b * 9 + j) * HW2_ + px0 + t] = f[j] * inv_ks;
    }
}

// ---------------------------------------------------------------------------
__global__ void upsample2x(const float* __restrict__ in, float* __restrict__ out) {
    int idx = blockIdx.x * blockDim.x + threadIdx.x;
    if (idx >= B_ * C_ * HW2_) return;
    int x  = idx & 255;
    int y  = (idx >> 8) & 255;
    int bc = idx >> 16;
    int m = y >> 1, ya, yb; float wya, wyb;
    if ((y & 1) == 0) { ya = (m - 1 < 0) ? 0 : m - 1; yb = m;  wya = 0.25f; wyb = 0.75f; }
    else              { ya = m; yb = (m + 1 > 127) ? 127 : m + 1; wya = 0.75f; wyb = 0.25f; }
    int n = x >> 1, xa, xb; float wxa, wxb;
    if ((x & 1) == 0) { xa = (n - 1 < 0) ? 0 : n - 1; xb = n;  wxa = 0.25f; wxb = 0.75f; }
    else              { xa = n; xb = (n + 1 > 127) ? 127 : n + 1; wxa = 0.75f; wxb = 0.25f; }
    const float* p = in + (size_t)bc * HW1_;
    out[idx] = wya * (wxa * p[ya * 128 + xa] + wxb * p[ya * 128 + xb]) +
               wyb * (wxa * p[yb * 128 + xa] + wxb * p[yb * 128 + xb]);
}

// ---------------------------------------------------------------------------
__global__ __launch_bounds__(256)
void gather_kernel(const float* __restrict__ fuse, const float* __restrict__ up,
                   float* __restrict__ out) {
    __shared__ float s_up[4][12][37];
    const int b   = blockIdx.z;
    const int gx0 = blockIdx.x * 32;
    const int gy0 = blockIdx.y * 8;
    const int t   = threadIdx.x;
    const int xl  = t & 31, yl = t >> 5;
    const int gx  = gx0 + xl, gy = gy0 + yl;

    float f[9];
#pragma unroll
    for (int j = 0; j < 9; j++)
        f[j] = fuse[((size_t)b * 9 + j) * HW2_ + gy * W2_ + gx];

    for (int c0 = 0; c0 < 64; c0 += 4) {
        __syncthreads();
        for (int idx = t; idx < 4 * 432; idx += 256) {
            int cl = idx / 432, rem = idx % 432;
            int r = rem / 36, cc = rem % 36;
            int yy = gy0 + r - 2, xx = gx0 + cc - 2;
            float v = 0.f;
            if (yy >= 0 && yy < H2_ && xx >= 0 && xx < W2_)
                v = up[((size_t)b * 64 + c0 + cl) * (size_t)HW2_ + yy * W2_ + xx];
            s_up[cl][r][cc] = v;
        }
        __syncthreads();
#pragma unroll
        for (int cl = 0; cl < 4; cl++) {
            float acc = 0.f;
#pragma unroll
            for (int ky = 0; ky < 3; ky++)
#pragma unroll
                for (int kx = 0; kx < 3; kx++)
                    acc += f[ky * 3 + kx] * s_up[cl][yl + 2 * ky][xl + 2 * kx];
            out[(((size_t)b * 64 + c0 + cl) * H2_ + gy) * W2_ + gx] = acc;
        }
    }
}

// ---------------------------------------------------------------------------
extern "C" void kernel_launch(void* const* d_in, const int* in_sizes, int n_in,
                              void* d_out, int out_size) {
    const float* depth  = (const float*)d_in[0];
    const float* guide  = (const float*)d_in[1];
    const float* inputs = (const float*)d_in[2];
    const float* dk_w1  = (const float*)d_in[3];
    const float* dk_b1  = (const float*)d_in[4];
    const float* dk_w2  = (const float*)d_in[5];
    const float* dk_b2  = (const float*)d_in[6];
    const float* gk_w1  = (const float*)d_in[7];
    const float* gk_b1  = (const float*)d_in[8];
    const float* gk_w2  = (const float*)d_in[9];
    const float* gk_b2  = (const float*)d_in[10];
    const float* wn_w1  = (const float*)d_in[11];
    const float* wn_b1  = (const float*)d_in[12];
    const float* wn_w2  = (const float*)d_in[13];
    const float* wn_b2  = (const float*)d_in[14];
    const float* wn_w3  = (const float*)d_in[15];
    const float* wn_b3  = (const float*)d_in[16];
    const float* rb_w   = (const float*)d_in[17];
    const float* rb_b   = (const float*)d_in[18];
    const float* aff    = (const float*)d_in[19];
    float* out = (float*)d_out;

    float *p_wmap, *p_fuse, *p_r2, *p_r3, *p_up;
    u32t *pt_in0, *pt_wm1, *pt_wm2, *pt_inlo, *pt_r1, *pt_r2, *pt_r3;
    u32t *pt_wn1, *pt_wn2, *pt_rb, *pt_wn3;
    cudaGetSymbolAddress((void**)&p_wmap, g_wmap);
    cudaGetSymbolAddress((void**)&p_fuse, g_fuse);
    cudaGetSymbolAddress((void**)&p_r2,   g_r2);
    cudaGetSymbolAddress((void**)&p_r3,   g_r3);
    cudaGetSymbolAddress((void**)&p_up,   g_up);
    cudaGetSymbolAddress((void**)&pt_in0,  gt_in0);
    cudaGetSymbolAddress((void**)&pt_wm1,  gt_wm1);
    cudaGetSymbolAddress((void**)&pt_wm2,  gt_wm2);
    cudaGetSymbolAddress((void**)&pt_inlo, gt_inlo);
    cudaGetSymbolAddress((void**)&pt_r1,   gt_r1);
    cudaGetSymbolAddress((void**)&pt_r2,   gt_r2);
    cudaGetSymbolAddress((void**)&pt_r3,   gt_r3);
    cudaGetSymbolAddress((void**)&pt_wn1,  gt_wn1);
    cudaGetSymbolAddress((void**)&pt_wn2,  gt_wn2);
    cudaGetSymbolAddress((void**)&pt_rb,   gt_rb);
    cudaGetSymbolAddress((void**)&pt_wn3,  gt_wn3);

    cudaFuncSetAttribute(conv3x3_cp<8, 8, 8, true,  false, false, true >, cudaFuncAttributeMaxDynamicSharedMemorySize, SMEM_TY8);
    cudaFuncSetAttribute(conv3x3_cp<4, 8, 8, true,  false, false, true >, cudaFuncAttributeMaxDynamicSharedMemorySize, SMEM_TY8);
    cudaFuncSetAttribute(conv3x3_cp<4, 1, 8, false, false, true,  false>, cudaFuncAttributeMaxDynamicSharedMemorySize, SMEM_C1);
    cudaFuncSetAttribute(conv3x3_cp<4, 8, 4, true,  false, false, true >, cudaFuncAttributeMaxDynamicSharedMemorySize, SMEM_TY4);
    cudaFuncSetAttribute(conv3x3_cp<4, 8, 4, false, true,  true,  true >, cudaFuncAttributeMaxDynamicSharedMemorySize, SMEM_TY4);
    cudaFuncSetAttribute(conv3x3_cp<4, 8, 4, false, true,  true,  false>, cudaFuncAttributeMaxDynamicSharedMemorySize, SMEM_TY4);

    dim3 ghi8(W2_ / 32, H2_ / 8, B_);   // 8, 32, 2
    dim3 glo4(W1_ / 32, H1_ / 4, B_);   // 4, 32, 2

    // pre-pass conversions
    prep_inputs<<<(B_*8*HW2_ + B_*4*HW1_) / 256, 256>>>(depth, guide, inputs, pt_in0, pt_inlo);
    prep_weights<<<(131328 + 255) / 256, 256>>>(wn_w1, wn_w2, rb_w, wn_w3,
                                                pt_wn1, pt_wn2, pt_rb, pt_wn3);

    // weight-map trunk (fp16 tensor-core)
    conv3x3_cp<8, 8, 8, true,  false, false, true ><<<ghi8, 256, SMEM_TY8>>>(pt_in0, pt_wn1, wn_b1, nullptr, nullptr, pt_wm1, H2_, W2_);
    conv3x3_cp<4, 8, 8, true,  false, false, true ><<<ghi8, 256, SMEM_TY8>>>(pt_wm1, pt_wn2, wn_b2, nullptr, nullptr, pt_wm2, H2_, W2_);
    conv3x3_cp<4, 1, 8, false, false, true,  false><<<ghi8, 256, SMEM_C1>>>(pt_wm2, pt_wn3, wn_b3, nullptr, p_wmap, nullptr, H2_, W2_);

    // per-pixel kernel fusion branch
    dim3 gfuse(HW2_ / 64, B_);
    fuse_kernel<<<gfuse, 256>>>(depth, guide, p_wmap,
                                dk_w1, dk_b1, dk_w2, dk_b2,
                                gk_w1, gk_b1, gk_w2, gk_b2,
                                aff, p_fuse);

    // residual stack on low-res inputs (fp16 tensor-core)
    conv3x3_cp<4, 8, 4, true,  false, false, true ><<<glo4, 128, SMEM_TY4>>>(pt_inlo, pt_rb + 0*18432, rb_b + 0,   nullptr, nullptr, pt_r1, H1_, W1_);
    conv3x3_cp<4, 8, 4, false, true,  true,  true ><<<glo4, 128, SMEM_TY4>>>(pt_r1,   pt_rb + 1*18432, rb_b + 64,  inputs,  p_r2,    pt_r2, H1_, W1_);
    conv3x3_cp<4, 8, 4, true,  false, false, true ><<<glo4, 128, SMEM_TY4>>>(pt_r2,   pt_rb + 2*18432, rb_b + 128, nullptr, nullptr, pt_r3, H1_, W1_);
    conv3x3_cp<4, 8, 4, false, true,  true,  false><<<glo4, 128, SMEM_TY4>>>(pt_r3,   pt_rb + 3*18432, rb_b + 192, p_r2,    p_r3,    nullptr, H1_, W1_);

    // upsample + gather
    upsample2x<<<(B_ * C_ * HW2_ + 255) / 256, 256>>>(p_r3, p_up);
    gather_kernel<<<ghi8, 256>>>(p_fuse, p_up, out);
}

// round 8
// speedup vs baseline: 8.0519x; 1.4466x over previous
#include <cuda_runtime.h>
#include <cuda_fp16.h>
#include <math.h>

#define B_  2
#define C_  64
#define H2_ 256
#define W2_ 256
#define HW2_ (H2_*W2_)
#define H1_ 128
#define W1_ 128
#define HW1_ (H1_*W1_)
#define KK_ 9

typedef unsigned long long u64t;
typedef unsigned int u32t;

__device__ __forceinline__ void mma_f16(float* d, u32t a0, u32t a1, u32t a2, u32t a3,
                                        u32t b0, u32t b1) {
    asm("mma.sync.aligned.m16n8k16.row.col.f32.f16.f16.f32 "
        "{%0,%1,%2,%3},{%4,%5,%6,%7},{%8,%9},{%0,%1,%2,%3};"
        : "+f"(d[0]), "+f"(d[1]), "+f"(d[2]), "+f"(d[3])
        : "r"(a0), "r"(a1), "r"(a2), "r"(a3), "r"(b0), "r"(b1));
}
__device__ __forceinline__ u32t packh2(float lo, float hi) {
    __half2 h = __floats2half2_rn(lo, hi);
    return *(u32t*)&h;
}

// ---------------- scratch ----------------
__device__ float g_wmap[B_*HW2_];
__device__ float g_fuse[B_*KK_*HW2_];
__device__ float g_r2[B_*C_*HW1_];     // x1 (fp32, skip source)
__device__ float g_r3[B_*C_*HW1_];     // final x (fp32)

// fp16 pair-interleaved buffers: [b][chunk16][px][8 words]
__device__ u32t gt_in0[B_*8*HW2_*8];   // depth||guide (128 ch = 8 chunks)
__device__ u32t gt_wm1[B_*4*HW2_*8];
__device__ u32t gt_wm2[B_*4*HW2_*8];
__device__ u32t gt_inlo[B_*4*HW1_*8];
__device__ u32t gt_r1[B_*4*HW1_*8];
__device__ u32t gt_r2[B_*4*HW1_*8];
__device__ u32t gt_r3[B_*4*HW1_*8];
// fp16 weights: [chunk16][tap][oc][8 words]
__device__ u32t gt_wn1[8*9*64*8];
__device__ u32t gt_wn2[4*9*64*8];
__device__ u32t gt_rb [4*4*9*64*8];
__device__ u32t gt_wn3[4*9*8*8];       // NOC=1, oc padded to 8
// fp16 fuse weights: W1 [branch][kc4][m64][ws8], W2 [branch][kc4][m16][ws8]
__device__ u32t gt_fw1[2*4*64*8];
__device__ u32t gt_fw2[2*4*16*8];

// ---------------------------------------------------------------------------
// prep: NCHW fp32 -> fp16 pair-interleaved
// ---------------------------------------------------------------------------
__global__ void prep_inputs(const float* __restrict__ depth, const float* __restrict__ guide,
                            const float* __restrict__ inputs,
                            u32t* __restrict__ in0_t, u32t* __restrict__ inlo_t) {
    int idx = blockIdx.x * 256 + threadIdx.x;
    const int N0 = B_ * 8 * HW2_;
    if (idx < N0) {
        int px = idx & (HW2_ - 1);
        int ch = (idx >> 16) & 7;
        int b  = idx >> 19;
        const float* src = (ch < 4 ? depth : guide) + ((size_t)b * 64 + (ch & 3) * 16) * HW2_ + px;
        u32t w[8];
#pragma unroll
        for (int ws = 0; ws < 8; ws++) {
            int p = (ws >> 1) + ((ws & 1) << 2);
            w[ws] = packh2(src[(size_t)(2 * p) * HW2_], src[(size_t)(2 * p + 1) * HW2_]);
        }
        *(uint4*)&in0_t[(size_t)idx * 8]     = make_uint4(w[0], w[1], w[2], w[3]);
        *(uint4*)&in0_t[(size_t)idx * 8 + 4] = make_uint4(w[4], w[5], w[6], w[7]);
    } else {
        int j = idx - N0;
        int px = j & (HW1_ - 1);
        int ch = (j >> 14) & 3;
        int b  = j >> 16;
        const float* src = inputs + ((size_t)b * 64 + ch * 16) * HW1_ + px;
        u32t w[8];
#pragma unroll
        for (int ws = 0; ws < 8; ws++) {
            int p = (ws >> 1) + ((ws & 1) << 2);
            w[ws] = packh2(src[(size_t)(2 * p) * HW1_], src[(size_t)(2 * p + 1) * HW1_]);
        }
        *(uint4*)&inlo_t[(size_t)j * 8]     = make_uint4(w[0], w[1], w[2], w[3]);
        *(uint4*)&inlo_t[(size_t)j * 8 + 4] = make_uint4(w[4], w[5], w[6], w[7]);
    }
}

__device__ __forceinline__ void wcvt(const float* __restrict__ w, u32t* __restrict__ o,
                                     int widx, int CIN) {
    int ws  = widx & 7;
    int oc  = (widx >> 3) & 63;
    int rem = widx >> 9;
    int tap = rem % 9, chunk = rem / 9;
    int p   = (ws >> 1) + ((ws & 1) << 2);
    int c0  = chunk * 16 + 2 * p;
    o[widx] = packh2(w[(oc * CIN + c0) * 9 + tap], w[(oc * CIN + c0 + 1) * 9 + tap]);
}

__global__ void prep_weights(const float* __restrict__ wn1, const float* __restrict__ wn2,
                             const float* __restrict__ rb,  const float* __restrict__ wn3,
                             const float* __restrict__ dkw1, const float* __restrict__ gkw1,
                             const float* __restrict__ dkw2, const float* __restrict__ gkw2,
                             u32t* __restrict__ t1, u32t* __restrict__ t2,
                             u32t* __restrict__ trb, u32t* __restrict__ t3,
                             u32t* __restrict__ tf1, u32t* __restrict__ tf2) {
    int idx = blockIdx.x * 256 + threadIdx.x;
    if (idx < 36864) {
        wcvt(wn1, t1, idx, 128);
    } else if (idx < 55296) {
        wcvt(wn2, t2, idx - 36864, 64);
    } else if (idx < 129024) {
        int j = idx - 55296;
        int r = j / 18432, jj = j - r * 18432;
        wcvt(rb + r * 36864, trb + r * 18432, jj, 64);
    } else if (idx < 131328) {
        int j = idx - 129024;           // [chunk][tap][oc8][ws8]
        int chunk = j / 576, rem = j % 576;
        int tap = rem >> 6, oc = (rem >> 3) & 7, ws = rem & 7;
        int p = (ws >> 1) + ((ws & 1) << 2);
        int c0 = chunk * 16 + 2 * p;
        t3[j] = (oc == 0) ? packh2(wn3[c0 * 9 + tap], wn3[(c0 + 1) * 9 + tap]) : 0u;
    } else if (idx < 135424) {
        int j = idx - 131328;           // fw1: [branch][kc][m64][ws8]
        int branch = j >> 11, rem = j & 2047;
        int kc = rem >> 9, m = (rem >> 3) & 63, ws = rem & 7;
        int p = (ws >> 1) + ((ws & 1) << 2);
        int k0 = kc * 16 + 2 * p;
        const float* W = branch ? gkw1 : dkw1;
        tf1[j] = packh2(W[m * 64 + k0], W[m * 64 + k0 + 1]);
    } else if (idx < 136448) {
        int j = idx - 135424;           // fw2: [branch][kc][m16][ws8]
        int branch = j >> 9, rem = j & 511;
        int kc = rem >> 7, m = (rem >> 3) & 15, ws = rem & 7;
        int p = (ws >> 1) + ((ws & 1) << 2);
        int k0 = kc * 16 + 2 * p;
        const float* W = branch ? gkw2 : dkw2;
        tf2[j] = (m < 9) ? packh2(W[m * 64 + k0], W[m * 64 + k0 + 1]) : 0u;
    }
}

// ---------------------------------------------------------------------------
// fp16 implicit-GEMM 3x3 conv, cp.async double-buffered, m16n8k16.
// ---------------------------------------------------------------------------
template<int NC, int NOC, int TY, bool RELU, bool SKIP, bool WF32, bool WT16>
__global__ __launch_bounds__(TY*32, (TY == 8) ? 2 : 4)
void conv3x3_cp(const u32t* __restrict__ in_t, const u32t* __restrict__ wt,
                const float* __restrict__ bias, const float* __restrict__ skip,
                float* __restrict__ outf, u32t* __restrict__ outt,
                int Hd, int Wd) {
    constexpr int NT   = TY * 32;
    constexpr int HR   = TY + 2;
    constexpr int IN_W = HR * 34 * 8;
    constexpr int W_W  = 576 * NOC;
    extern __shared__ u32t sm[];
    const int t    = threadIdx.x;
    const int warp = t >> 5, lane = t & 31;
    const int G    = lane >> 2, tig = lane & 3;
    const int b    = blockIdx.z;
    const int gx0  = blockIdx.x * 32;
    const int gy0  = blockIdx.y * TY;
    const size_t HW = (size_t)Hd * Wd;

    const u32t smbase = (u32t)__cvta_generic_to_shared(sm);

    auto stage = [&](int k, int buf) {
        const u32t* gin = in_t + ((size_t)b * NC + k) * HW * 8;
        const u32t sin_b = smbase + buf * (IN_W * 4);
        for (int u = t; u < HR * 68; u += NT) {
            int r  = u / 68, h = u - r * 68;
            int xx = h >> 1, hf = h & 1;
            int gy = gy0 + r - 1, gx = gx0 + xx - 1;
            bool ok = (gy >= 0) && (gy < Hd) && (gx >= 0) && (gx < Wd);
            const u32t* src = gin + (((size_t)(ok ? gy : 0)) * Wd + (ok ? gx : 0)) * 8 + hf * 4;
            int nbytes = ok ? 16 : 0;
            u32t dst = sin_b + (u32t)(((r * 34 + xx) * 8 + hf * 4) * 4);
            asm volatile("cp.async.cg.shared.global [%0], [%1], 16, %2;"
                         :: "r"(dst), "l"(src), "r"(nbytes));
        }
        const u32t* gw = wt + (size_t)k * W_W;
        const u32t sw_b = smbase + (u32t)((2 * IN_W + buf * W_W) * 4);
        for (int u = t; u < W_W / 4; u += NT) {
            asm volatile("cp.async.cg.shared.global [%0], [%1], 16, 16;"
                         :: "r"(sw_b + u * 16), "l"(gw + u * 4));
        }
    };

    float d[2][NOC][4];
#pragma unroll
    for (int m = 0; m < 2; m++)
#pragma unroll
        for (int n = 0; n < NOC; n++)
#pragma unroll
            for (int i = 0; i < 4; i++) d[m][n][i] = 0.f;

    stage(0, 0);
    asm volatile("cp.async.commit_group;");

    for (int k = 0; k < NC; k++) {
        if (k + 1 < NC) {
            stage(k + 1, (k + 1) & 1);
            asm volatile("cp.async.commit_group;");
            asm volatile("cp.async.wait_group 1;");
        } else {
            asm volatile("cp.async.wait_group 0;");
        }
        __syncthreads();
        const u32t* bin = sm + (k & 1) * IN_W;
        const u32t* bw  = sm + 2 * IN_W + (k & 1) * W_W;
#pragma unroll
        for (int tap = 0; tap < 9; tap++) {
            const int ky = tap / 3, kx = tap % 3;
            uint2 a[2][2];
#pragma unroll
            for (int m = 0; m < 2; m++) {
                const int xx = m * 16 + G + kx;
                a[m][0] = *(const uint2*)&bin[((warp + ky) * 34 + xx) * 8 + 2 * tig];
                a[m][1] = *(const uint2*)&bin[((warp + ky) * 34 + xx + 8) * 8 + 2 * tig];
            }
#pragma unroll
            for (int n = 0; n < NOC; n++) {
                uint2 q = *(const uint2*)&bw[(tap * (8 * NOC) + n * 8 + G) * 8 + 2 * tig];
#pragma unroll
                for (int m = 0; m < 2; m++)
                    mma_f16(d[m][n], a[m][0].x, a[m][1].x, a[m][0].y, a[m][1].y,
                            q.x, q.y);
            }
        }
        __syncthreads();
    }

    // ---- epilogue ----
    const int gy = gy0 + warp;
    if (NOC == 1) {
        if (tig == 0) {
            float bv = __ldg(&bias[0]);
#pragma unroll
            for (int m = 0; m < 2; m++) {
                const int x = gx0 + m * 16 + G;
                float v0 = d[m][0][0] + bv;
                float v2 = d[m][0][2] + bv;
                if (RELU) { v0 = fmaxf(v0, 0.f); v2 = fmaxf(v2, 0.f); }
                outf[(size_t)b * HW + (size_t)gy * Wd + x]     = v0;
                outf[(size_t)b * HW + (size_t)gy * Wd + x + 8] = v2;
            }
        }
        return;
    }
#pragma unroll
    for (int m = 0; m < 2; m++) {
        const int x = gx0 + m * 16 + G;
#pragma unroll
        for (int n = 0; n < NOC; n++) {
            const int oc = n * 8 + 2 * tig;
            float b0v = __ldg(&bias[oc]);
            float b1v = __ldg(&bias[oc + 1]);
            float v0 = d[m][n][0] + b0v;
            float v1 = d[m][n][1] + b1v;
            float v2 = d[m][n][2] + b0v;
            float v3 = d[m][n][3] + b1v;
            size_t f0 = (((size_t)b * 64 + oc) * Hd + gy) * Wd + x;
            size_t f1 = f0 + HW;
            if (SKIP) {
                v0 += skip[f0];     v1 += skip[f1];
                v2 += skip[f0 + 8]; v3 += skip[f1 + 8];
            }
            if (RELU) {
                v0 = fmaxf(v0, 0.f); v1 = fmaxf(v1, 0.f);
                v2 = fmaxf(v2, 0.f); v3 = fmaxf(v3, 0.f);
            }
            if (WF32) {
                outf[f0] = v0; outf[f1] = v1; outf[f0 + 8] = v2; outf[f1 + 8] = v3;
            }
            if (WT16) {
                int slot = 2 * tig + (n & 1);
                size_t tb = (((size_t)b * 4 + (n >> 1)) * HW + (size_t)gy * Wd + x) * 8;
                outt[tb + slot]      = packh2(v0, v1);
                outt[tb + 64 + slot] = packh2(v2, v3);
            }
        }
    }
}

#define SMEM_TY8  ((2*10*34*8 + 2*576*8) * 4)   // 58624
#define SMEM_TY4  ((2*6*34*8  + 2*576*8) * 4)   // 49920
#define SMEM_C1   ((2*10*34*8 + 2*576*1) * 4)   // 26368

// ---------------------------------------------------------------------------
// fuse: fp16 hidden + logits GEMMs, X staged via cp.async from gt_in0.
// Block = 64 px, 256 threads, 8 warps.
// ---------------------------------------------------------------------------
__global__ __launch_bounds__(256)
void fuse_kernel(const u32t* __restrict__ in0_t, const float* __restrict__ wmap,
                 const u32t* __restrict__ fw1, const u32t* __restrict__ fw2,
                 const float* __restrict__ dkb1, const float* __restrict__ dkb2,
                 const float* __restrict__ gkb1, const float* __restrict__ gkb2,
                 const float* __restrict__ aff,  float* __restrict__ fuse) {
    __shared__ u32t   s_x[8][64][8];     // chunks 0-3 depth, 4-7 guide (16KB)
    __shared__ __half s_h[64][72];       // hidden transposed [px][c]
    __shared__ float  s_l[2][9][64];

    const int b    = blockIdx.y;
    const int px0  = blockIdx.x * 64;
    const int t    = threadIdx.x;
    const int warp = t >> 5, lane = t & 31;
    const int G    = lane >> 2, tig = lane & 3;
    const int mt   = warp & 3, nh = warp >> 2;
    const int c0   = mt * 16;

    // stage all 8 X chunks (both branches) via cp.async
    {
        const u32t smb = (u32t)__cvta_generic_to_shared(&s_x[0][0][0]);
        for (int u = t; u < 1024; u += 256) {
            int ch = u >> 7, rem = u & 127;
            int px = rem >> 1, hf = rem & 1;
            const u32t* src = in0_t + (((size_t)b * 8 + ch) * HW2_ + px0 + px) * 8 + hf * 4;
            asm volatile("cp.async.cg.shared.global [%0], [%1], 16, 16;"
                         :: "r"(smb + (u32t)(((ch * 64 + px) * 8 + hf * 4) * 4)), "l"(src));
        }
        asm volatile("cp.async.commit_group;");
        asm volatile("cp.async.wait_group 0;");
    }
    __syncthreads();

#pragma unroll
    for (int branch = 0; branch < 2; branch++) {
        const float* B1v = branch ? gkb1 : dkb1;
        const float* B2v = branch ? gkb2 : dkb2;
        const u32t* w1 = fw1 + branch * 2048;
        const u32t* w2 = fw2 + branch * 512;

        if (branch) __syncthreads();   // protect s_h reuse

        // hidden = relu(W1 @ X): M=64 c, N=64 px, K=64 in 4 k16 chunks
        float d[4][4];
#pragma unroll
        for (int nc = 0; nc < 4; nc++)
#pragma unroll
            for (int i = 0; i < 4; i++) d[nc][i] = 0.f;
#pragma unroll
        for (int kc = 0; kc < 4; kc++) {
            uint2 q0 = *(const uint2*)&w1[((kc * 64) + c0 + G)     * 8 + 2 * tig];
            uint2 q1 = *(const uint2*)&w1[((kc * 64) + c0 + G + 8) * 8 + 2 * tig];
#pragma unroll
            for (int nc = 0; nc < 4; nc++) {
                int px = nh * 32 + nc * 8 + G;
                uint2 bb = *(const uint2*)&s_x[branch * 4 + kc][px][2 * tig];
                mma_f16(d[nc], q0.x, q1.x, q0.y, q1.y, bb.x, bb.y);
            }
        }
        float bv0 = __ldg(&B1v[c0 + G]);
        float bv8 = __ldg(&B1v[c0 + G + 8]);
#pragma unroll
        for (int nc = 0; nc < 4; nc++) {
            int px = nh * 32 + nc * 8 + 2 * tig;
            s_h[px][c0 + G]         = __float2half_rn(fmaxf(d[nc][0] + bv0, 0.f));
            s_h[px + 1][c0 + G]     = __float2half_rn(fmaxf(d[nc][1] + bv0, 0.f));
            s_h[px][c0 + G + 8]     = __float2half_rn(fmaxf(d[nc][2] + bv8, 0.f));
            s_h[px + 1][c0 + G + 8] = __float2half_rn(fmaxf(d[nc][3] + bv8, 0.f));
        }
        __syncthreads();

        // logits = W2 @ hidden (M=16 pad, rows 0..8 real), warp = 8-px n-chunk
        {
            const int n0 = warp * 8;
            float d2[4] = {0.f, 0.f, 0.f, 0.f};
#pragma unroll
            for (int kc = 0; kc < 4; kc++) {
                uint2 q0 = *(const uint2*)&w2[((kc * 16) + G)     * 8 + 2 * tig];
                uint2 q1 = *(const uint2*)&w2[((kc * 16) + G + 8) * 8 + 2 * tig];
                u32t b0 = *(const u32t*)&s_h[n0 + G][kc * 16 + 2 * tig];
                u32t b1 = *(const u32t*)&s_h[n0 + G][kc * 16 + 2 * tig + 8];
                mma_f16(d2, q0.x, q1.x, q0.y, q1.y, b0, b1);
            }
            float bj = __ldg(&B2v[G]);
            s_l[branch][G][n0 + 2 * tig]     = d2[0] + bj;
            s_l[branch][G][n0 + 2 * tig + 1] = d2[1] + bj;
            if (G == 0) {
                float b8 = __ldg(&B2v[8]);
                s_l[branch][8][n0 + 2 * tig]     = d2[2] + b8;
                s_l[branch][8][n0 + 2 * tig + 1] = d2[3] + b8;
            }
        }
    }
    __syncthreads();

    if (t < 64) {
        float wm = wmap[(size_t)b * HW2_ + px0 + t];
        float dmax = -1e30f, gmax = -1e30f;
#pragma unroll
        for (int j = 0; j < 9; j++) {
            dmax = fmaxf(dmax, s_l[0][j][t]);
            gmax = fmaxf(gmax, s_l[1][j][t]);
        }
        float de[9], ge[9], ds = 0.f, gs = 0.f;
#pragma unroll
        for (int j = 0; j < 9; j++) {
            de[j] = expf(s_l[0][j][t] - dmax); ds += de[j];
            ge[j] = expf(s_l[1][j][t] - gmax); gs += ge[j];
        }
        float affv = __ldg(&aff[0]) + 1e-8f;
        float inv_d = 1.f / ds, inv_g = 1.f / gs;
        float f[9], asum = 0.f;
#pragma unroll
        for (int j = 0; j < 9; j++) {
            float fv = wm * (de[j] * inv_d) + (1.f - wm) * (ge[j] * inv_g);
            fv = tanhf(fv) / affv;
            f[j] = fv;
            asum += fabsf(fv);
        }
        float inv_ks = 1.f / fmaxf(asum + 1e-4f, 1.0f);
#pragma unroll
        for (int j = 0; j < 9; j++)
            fuse[((size_t)b * 9 + j) * HW2_ + px0 + t] = f[j] * inv_ks;
    }
}

// ---------------------------------------------------------------------------
// gather with fused bilinear upsample: stages r3 low-res tile, builds the
// dilated halo in smem, then applies the 9-tap per-pixel kernel.
// ---------------------------------------------------------------------------
__global__ __launch_bounds__(256)
void gather_kernel(const float* __restrict__ fuse, const float* __restrict__ r3,
                   float* __restrict__ out) {
    __shared__ float s_r3[4][8][21];
    __shared__ float s_up[4][12][37];
    const int b   = blockIdx.z;
    const int gx0 = blockIdx.x * 32;
    const int gy0 = blockIdx.y * 8;
    const int t   = threadIdx.x;
    const int xl  = t & 31, yl = t >> 5;
    const int gx  = gx0 + xl, gy = gy0 + yl;
    const int ly0 = gy0 / 2 - 2, lx0 = gx0 / 2 - 2;

    float f[9];
#pragma unroll
    for (int j = 0; j < 9; j++)
        f[j] = fuse[((size_t)b * 9 + j) * HW2_ + gy * W2_ + gx];

    for (int c0 = 0; c0 < 64; c0 += 4) {
        __syncthreads();
        // stage low-res r3 region (clamped)
        for (int idx = t; idx < 640; idx += 256) {
            int cl = idx / 160, rem = idx % 160;
            int r = rem / 20, cc = rem % 20;
            int yy = min(max(ly0 + r, 0), 127);
            int xx = min(max(lx0 + cc, 0), 127);
            s_r3[cl][r][cc] = r3[((size_t)b * 64 + c0 + cl) * HW1_ + yy * 128 + xx];
        }
        __syncthreads();
        // build dilated halo via bilinear from s_r3
        for (int idx = t; idx < 432; idx += 256) {
            int r = idx / 36, cc = idx % 36;
            int Y = gy0 + r - 2, X = gx0 + cc - 2;
            bool ok = (Y >= 0) && (Y < H2_) && (X >= 0) && (X < W2_);
            int m = Y >> 1, ya, yb; float wya, wyb;
            if (Y & 1) { ya = m; yb = min(m + 1, 127); wya = 0.75f; wyb = 0.25f; }
            else       { ya = max(m - 1, 0); yb = m;   wya = 0.25f; wyb = 0.75f; }
            int n = X >> 1, xa, xb; float wxa, wxb;
            if (X & 1) { xa = n; xb = min(n + 1, 127); wxa = 0.75f; wxb = 0.25f; }
            else       { xa = max(n - 1, 0); xb = n;   wxa = 0.25f; wxb = 0.75f; }
            int iya = min(max(ya - ly0, 0), 7), iyb = min(max(yb - ly0, 0), 7);
            int ixa = min(max(xa - lx0, 0), 20), ixb = min(max(xb - lx0, 0), 20);
#pragma unroll
            for (int cl = 0; cl < 4; cl++) {
                float v = wya * (wxa * s_r3[cl][iya][ixa] + wxb * s_r3[cl][iya][ixb])
                        + wyb * (wxa * s_r3[cl][iyb][ixa] + wxb * s_r3[cl][iyb][ixb]);
                s_up[cl][r][cc] = ok ? v : 0.f;
            }
        }
        __syncthreads();
#pragma unroll
        for (int cl = 0; cl < 4; cl++) {
            float acc = 0.f;
#pragma unroll
            for (int ky = 0; ky < 3; ky++)
#pragma unroll
                for (int kx = 0; kx < 3; kx++)
                    acc += f[ky * 3 + kx] * s_up[cl][yl + 2 * ky][xl + 2 * kx];
            out[(((size_t)b * 64 + c0 + cl) * H2_ + gy) * W2_ + gx] = acc;
        }
    }
}

// ---------------------------------------------------------------------------
extern "C" void kernel_launch(void* const* d_in, const int* in_sizes, int n_in,
                              void* d_out, int out_size) {
    const float* depth  = (const float*)d_in[0];
    const float* guide  = (const float*)d_in[1];
    const float* inputs = (const float*)d_in[2];
    const float* dk_w1  = (const float*)d_in[3];
    const float* dk_b1  = (const float*)d_in[4];
    const float* dk_w2  = (const float*)d_in[5];
    const float* dk_b2  = (const float*)d_in[6];
    const float* gk_w1  = (const float*)d_in[7];
    const float* gk_b1  = (const float*)d_in[8];
    const float* gk_w2  = (const float*)d_in[9];
    const float* gk_b2  = (const float*)d_in[10];
    const float* wn_w1  = (const float*)d_in[11];
    const float* wn_b1  = (const float*)d_in[12];
    const float* wn_w2  = (const float*)d_in[13];
    const float* wn_b2  = (const float*)d_in[14];
    const float* wn_w3  = (const float*)d_in[15];
    const float* wn_b3  = (const float*)d_in[16];
    const float* rb_w   = (const float*)d_in[17];
    const float* rb_b   = (const float*)d_in[18];
    const float* aff    = (const float*)d_in[19];
    float* out = (float*)d_out;

    float *p_wmap, *p_fuse, *p_r2, *p_r3;
    u32t *pt_in0, *pt_wm1, *pt_wm2, *pt_inlo, *pt_r1, *pt_r2, *pt_r3;
    u32t *pt_wn1, *pt_wn2, *pt_rb, *pt_wn3, *pt_fw1, *pt_fw2;
    cudaGetSymbolAddress((void**)&p_wmap, g_wmap);
    cudaGetSymbolAddress((void**)&p_fuse, g_fuse);
    cudaGetSymbolAddress((void**)&p_r2,   g_r2);
    cudaGetSymbolAddress((void**)&p_r3,   g_r3);
    cudaGetSymbolAddress((void**)&pt_in0,  gt_in0);
    cudaGetSymbolAddress((void**)&pt_wm1,  gt_wm1);
    cudaGetSymbolAddress((void**)&pt_wm2,  gt_wm2);
    cudaGetSymbolAddress((void**)&pt_inlo, gt_inlo);
    cudaGetSymbolAddress((void**)&pt_r1,   gt_r1);
    cudaGetSymbolAddress((void**)&pt_r2,   gt_r2);
    cudaGetSymbolAddress((void**)&pt_r3,   gt_r3);
    cudaGetSymbolAddress((void**)&pt_wn1,  gt_wn1);
    cudaGetSymbolAddress((void**)&pt_wn2,  gt_wn2);
    cudaGetSymbolAddress((void**)&pt_rb,   gt_rb);
    cudaGetSymbolAddress((void**)&pt_wn3,  gt_wn3);
    cudaGetSymbolAddress((void**)&pt_fw1,  gt_fw1);
    cudaGetSymbolAddress((void**)&pt_fw2,  gt_fw2);

    cudaFuncSetAttribute(conv3x3_cp<8, 8, 8, true,  false, false, true >, cudaFuncAttributeMaxDynamicSharedMemorySize, SMEM_TY8);
    cudaFuncSetAttribute(conv3x3_cp<4, 8, 8, true,  false, false, true >, cudaFuncAttributeMaxDynamicSharedMemorySize, SMEM_TY8);
    cudaFuncSetAttribute(conv3x3_cp<4, 1, 8, false, false, true,  false>, cudaFuncAttributeMaxDynamicSharedMemorySize, SMEM_C1);
    cudaFuncSetAttribute(conv3x3_cp<4, 8, 4, true,  false, false, true >, cudaFuncAttributeMaxDynamicSharedMemorySize, SMEM_TY4);
    cudaFuncSetAttribute(conv3x3_cp<4, 8, 4, false, true,  true,  true >, cudaFuncAttributeMaxDynamicSharedMemorySize, SMEM_TY4);
    cudaFuncSetAttribute(conv3x3_cp<4, 8, 4, false, true,  true,  false>, cudaFuncAttributeMaxDynamicSharedMemorySize, SMEM_TY4);

    dim3 ghi8(W2_ / 32, H2_ / 8, B_);   // 8, 32, 2
    dim3 glo4(W1_ / 32, H1_ / 4, B_);   // 4, 32, 2

    // pre-pass conversions
    prep_inputs<<<(B_*8*HW2_ + B_*4*HW1_) / 256, 256>>>(depth, guide, inputs, pt_in0, pt_inlo);
    prep_weights<<<(136448 + 255) / 256, 256>>>(wn_w1, wn_w2, rb_w, wn_w3,
                                                dk_w1, gk_w1, dk_w2, gk_w2,
                                                pt_wn1, pt_wn2, pt_rb, pt_wn3,
                                                pt_fw1, pt_fw2);

    // weight-map trunk (fp16 tensor-core)
    conv3x3_cp<8, 8, 8, true,  false, false, true ><<<ghi8, 256, SMEM_TY8>>>(pt_in0, pt_wn1, wn_b1, nullptr, nullptr, pt_wm1, H2_, W2_);
    conv3x3_cp<4, 8, 8, true,  false, false, true ><<<ghi8, 256, SMEM_TY8>>>(pt_wm1, pt_wn2, wn_b2, nullptr, nullptr, pt_wm2, H2_, W2_);
    conv3x3_cp<4, 1, 8, false, false, true,  false><<<ghi8, 256, SMEM_C1>>>(pt_wm2, pt_wn3, wn_b3, nullptr, p_wmap, nullptr, H2_, W2_);

    // per-pixel kernel fusion branch (fp16 tensor-core)
    dim3 gfuse(HW2_ / 64, B_);
    fuse_kernel<<<gfuse, 256>>>(pt_in0, p_wmap, pt_fw1, pt_fw2,
                                dk_b1, dk_b2, gk_b1, gk_b2, aff, p_fuse);

    // residual stack on low-res inputs (fp16 tensor-core)
    conv3x3_cp<4, 8, 4, true,  false, false, true ><<<glo4, 128, SMEM_TY4>>>(pt_inlo, pt_rb + 0*18432, rb_b + 0,   nullptr, nullptr, pt_r1, H1_, W1_);
    conv3x3_cp<4, 8, 4, false, true,  true,  true ><<<glo4, 128, SMEM_TY4>>>(pt_r1,   pt_rb + 1*18432, rb_b + 64,  inputs,  p_r2,    pt_r2, H1_, W1_);
    conv3x3_cp<4, 8, 4, true,  false, false, true ><<<glo4, 128, SMEM_TY4>>>(pt_r2,   pt_rb + 2*18432, rb_b + 128, nullptr, nullptr, pt_r3, H1_, W1_);
    conv3x3_cp<4, 8, 4, false, true,  true,  false><<<glo4, 128, SMEM_TY4>>>(pt_r3,   pt_rb + 3*18432, rb_b + 192, p_r2,    p_r3,    nullptr, H1_, W1_);

    // fused upsample + gather
    gather_kernel<<<ghi8, 256>>>(p_fuse, p_r3, out);
}

// round 9
// speedup vs baseline: 8.2083x; 1.0194x over previous
#include <cuda_runtime.h>
#include <cuda_fp16.h>
#include <math.h>

#define B_  2
#define C_  64
#define H2_ 256
#define W2_ 256
#define HW2_ (H2_*W2_)
#define H1_ 128
#define W1_ 128
#define HW1_ (H1_*W1_)
#define KK_ 9

typedef unsigned long long u64t;
typedef unsigned int u32t;

__device__ __forceinline__ void mma_f16(float* d, u32t a0, u32t a1, u32t a2, u32t a3,
                                        u32t b0, u32t b1) {
    asm("mma.sync.aligned.m16n8k16.row.col.f32.f16.f16.f32 "
        "{%0,%1,%2,%3},{%4,%5,%6,%7},{%8,%9},{%0,%1,%2,%3};"
        : "+f"(d[0]), "+f"(d[1]), "+f"(d[2]), "+f"(d[3])
        : "r"(a0), "r"(a1), "r"(a2), "r"(a3), "r"(b0), "r"(b1));
}
__device__ __forceinline__ u32t packh2(float lo, float hi) {
    __half2 h = __floats2half2_rn(lo, hi);
    return *(u32t*)&h;
}

// ---------------- scratch ----------------
__device__ float g_wmap[B_*HW2_];
__device__ float g_fuse[B_*KK_*HW2_];
__device__ float g_r2[B_*C_*HW1_];
__device__ float g_r3[B_*C_*HW1_];

// fp16 pair-interleaved buffers: [b][chunk16][px][8 words]
__device__ u32t gt_in0[B_*8*HW2_*8];
__device__ u32t gt_wm1[B_*4*HW2_*8];
__device__ u32t gt_wm2[B_*4*HW2_*8];
__device__ u32t gt_inlo[B_*4*HW1_*8];
__device__ u32t gt_r1[B_*4*HW1_*8];
__device__ u32t gt_r2[B_*4*HW1_*8];
__device__ u32t gt_r3[B_*4*HW1_*8];
// fp16 weights: [chunk16][tap][oc][8 words]
__device__ u32t gt_wn1[8*9*64*8];
__device__ u32t gt_wn2[4*9*64*8];
__device__ u32t gt_rb [4*4*9*64*8];
__device__ u32t gt_wn3[4*9*8*8];
// fp16 fuse weights
__device__ u32t gt_fw1[2*4*64*8];
__device__ u32t gt_fw2[2*4*16*8];

// ---------------------------------------------------------------------------
// merged prep: inputs + all weights -> fp16 pair-interleaved
// ---------------------------------------------------------------------------
#define NPI_ (B_*8*HW2_ + B_*4*HW1_)

__device__ __forceinline__ void wcvt(const float* __restrict__ w, u32t* __restrict__ o,
                                     int widx, int CIN) {
    int ws  = widx & 7;
    int oc  = (widx >> 3) & 63;
    int rem = widx >> 9;
    int tap = rem % 9, chunk = rem / 9;
    int p   = (ws >> 1) + ((ws & 1) << 2);
    int c0  = chunk * 16 + 2 * p;
    o[widx] = packh2(w[(oc * CIN + c0) * 9 + tap], w[(oc * CIN + c0 + 1) * 9 + tap]);
}

__global__ void k_prep(const float* __restrict__ depth, const float* __restrict__ guide,
                       const float* __restrict__ inputs,
                       const float* __restrict__ wn1, const float* __restrict__ wn2,
                       const float* __restrict__ rb,  const float* __restrict__ wn3,
                       const float* __restrict__ dkw1, const float* __restrict__ gkw1,
                       const float* __restrict__ dkw2, const float* __restrict__ gkw2) {
    int idx = blockIdx.x * 256 + threadIdx.x;
    const int N0 = B_ * 8 * HW2_;
    if (idx < N0) {
        int px = idx & (HW2_ - 1);
        int ch = (idx >> 16) & 7;
        int b  = idx >> 19;
        const float* src = (ch < 4 ? depth : guide) + ((size_t)b * 64 + (ch & 3) * 16) * HW2_ + px;
        u32t w[8];
#pragma unroll
        for (int ws = 0; ws < 8; ws++) {
            int p = (ws >> 1) + ((ws & 1) << 2);
            w[ws] = packh2(src[(size_t)(2 * p) * HW2_], src[(size_t)(2 * p + 1) * HW2_]);
        }
        *(uint4*)&gt_in0[(size_t)idx * 8]     = make_uint4(w[0], w[1], w[2], w[3]);
        *(uint4*)&gt_in0[(size_t)idx * 8 + 4] = make_uint4(w[4], w[5], w[6], w[7]);
    } else if (idx < NPI_) {
        int j = idx - N0;
        int px = j & (HW1_ - 1);
        int ch = (j >> 14) & 3;
        int b  = j >> 16;
        const float* src = inputs + ((size_t)b * 64 + ch * 16) * HW1_ + px;
        u32t w[8];
#pragma unroll
        for (int ws = 0; ws < 8; ws++) {
            int p = (ws >> 1) + ((ws & 1) << 2);
            w[ws] = packh2(src[(size_t)(2 * p) * HW1_], src[(size_t)(2 * p + 1) * HW1_]);
        }
        *(uint4*)&gt_inlo[(size_t)j * 8]     = make_uint4(w[0], w[1], w[2], w[3]);
        *(uint4*)&gt_inlo[(size_t)j * 8 + 4] = make_uint4(w[4], w[5], w[6], w[7]);
    } else {
        int widx = idx - NPI_;
        if (widx < 36864) {
            wcvt(wn1, gt_wn1, widx, 128);
        } else if (widx < 55296) {
            wcvt(wn2, gt_wn2, widx - 36864, 64);
        } else if (widx < 129024) {
            int j = widx - 55296;
            int r = j / 18432, jj = j - r * 18432;
            wcvt(rb + r * 36864, gt_rb + r * 18432, jj, 64);
        } else if (widx < 131328) {
            int j = widx - 129024;
            int chunk = j / 576, rem = j % 576;
            int tap = rem >> 6, oc = (rem >> 3) & 7, ws = rem & 7;
            int p = (ws >> 1) + ((ws & 1) << 2);
            int c0 = chunk * 16 + 2 * p;
            gt_wn3[j] = (oc == 0) ? packh2(wn3[c0 * 9 + tap], wn3[(c0 + 1) * 9 + tap]) : 0u;
        } else if (widx < 135424) {
            int j = widx - 131328;
            int branch = j >> 11, rem = j & 2047;
            int kc = rem >> 9, m = (rem >> 3) & 63, ws = rem & 7;
            int p = (ws >> 1) + ((ws & 1) << 2);
            int k0 = kc * 16 + 2 * p;
            const float* W = branch ? gkw1 : dkw1;
            gt_fw1[j] = packh2(W[m * 64 + k0], W[m * 64 + k0 + 1]);
        } else if (widx < 136448) {
            int j = widx - 135424;
            int branch = j >> 9, rem = j & 511;
            int kc = rem >> 7, m = (rem >> 3) & 15, ws = rem & 7;
            int p = (ws >> 1) + ((ws & 1) << 2);
            int k0 = kc * 16 + 2 * p;
            const float* W = branch ? gkw2 : dkw2;
            gt_fw2[j] = (m < 9) ? packh2(W[m * 64 + k0], W[m * 64 + k0 + 1]) : 0u;
        }
    }
}

// ---------------------------------------------------------------------------
// fp16 implicit-GEMM 3x3 conv body: 3-stage cp.async pipeline, one sync/chunk.
// Tile 32x8 px, 256 threads. NC chunks of 16 ic. NOC n-chunks of 8 oc.
// smem: in[3][2720] + w[3][576*NOC] words.
// ---------------------------------------------------------------------------
#define CONV_IN_W 2720
#define SMEM_CONV ((3*CONV_IN_W + 3*4608) * 4)   // 87936 (NOC=8 worst case)

template<int NC, int NOC, bool RELU, bool SKIP, bool WF32, bool WT16>
__device__ __forceinline__ void conv_body(
    u32t* sm, const u32t* __restrict__ in_t, const u32t* __restrict__ wt,
    const float* __restrict__ bias, const float* __restrict__ skip,
    float* __restrict__ outf, u32t* __restrict__ outt,
    int Hd, int Wd, int gx0, int gy0, int b) {
    constexpr int NT  = 256;
    constexpr int W_W = 576 * NOC;
    const int t    = threadIdx.x;
    const int warp = t >> 5, lane = t & 31;
    const int G    = lane >> 2, tig = lane & 3;
    const size_t HW = (size_t)Hd * Wd;
    const u32t smbase = (u32t)__cvta_generic_to_shared(sm);

    // precomputed staging slots (10*68 = 680 16B units)
    int in_src[3]; u32t in_dst[3]; int in_nb[3];
#pragma unroll
    for (int i = 0; i < 3; i++) {
        int u = t + i * NT;
        if (u < 680) {
            int r  = u / 68, h = u - r * 68;
            int xx = h >> 1, hf = h & 1;
            int gy = gy0 + r - 1, gx = gx0 + xx - 1;
            bool ok = (gy >= 0) && (gy < Hd) && (gx >= 0) && (gx < Wd);
            in_src[i] = ((ok ? gy : 0) * Wd + (ok ? gx : 0)) * 8 + hf * 4;
            in_nb[i]  = ok ? 16 : 0;
            in_dst[i] = (u32t)(((r * 34 + xx) * 8 + hf * 4) * 4);
        } else in_nb[i] = -1;
    }

    auto stage = [&](int k, int buf) {
        const u32t* gin = in_t + ((size_t)b * NC + k) * HW * 8;
        const u32t sb = smbase + buf * (CONV_IN_W * 4);
#pragma unroll
        for (int i = 0; i < 3; i++)
            if (in_nb[i] >= 0)
                asm volatile("cp.async.cg.shared.global [%0], [%1], 16, %2;"
                             :: "r"(sb + in_dst[i]), "l"(gin + in_src[i]), "r"(in_nb[i]));
        const u32t* gw = wt + (size_t)k * W_W;
        const u32t swb = smbase + (u32t)((3 * CONV_IN_W + buf * W_W) * 4);
        for (int u = t; u < W_W / 4; u += NT)
            asm volatile("cp.async.cg.shared.global [%0], [%1], 16, 16;"
                         :: "r"(swb + u * 16), "l"(gw + u * 4));
    };

    float d[2][NOC][4];
#pragma unroll
    for (int m = 0; m < 2; m++)
#pragma unroll
        for (int n = 0; n < NOC; n++)
#pragma unroll
            for (int i = 0; i < 4; i++) d[m][n][i] = 0.f;

    stage(0, 0);
    asm volatile("cp.async.commit_group;");
    stage(1, 1);
    asm volatile("cp.async.commit_group;");

    for (int k = 0; k < NC; k++) {
        if (k + 1 < NC) asm volatile("cp.async.wait_group 1;");
        else            asm volatile("cp.async.wait_group 0;");
        __syncthreads();
        if (k + 2 < NC) {
            stage(k + 2, (k + 2) % 3);
            asm volatile("cp.async.commit_group;");
        }
        const u32t* bin = sm + (k % 3) * CONV_IN_W;
        const u32t* bw  = sm + 3 * CONV_IN_W + (k % 3) * W_W;
#pragma unroll
        for (int tap = 0; tap < 9; tap++) {
            const int ky = tap / 3, kx = tap % 3;
            uint2 a[2][2];
#pragma unroll
            for (int m = 0; m < 2; m++) {
                const int xx = m * 16 + G + kx;
                a[m][0] = *(const uint2*)&bin[((warp + ky) * 34 + xx) * 8 + 2 * tig];
                a[m][1] = *(const uint2*)&bin[((warp + ky) * 34 + xx + 8) * 8 + 2 * tig];
            }
#pragma unroll
            for (int n = 0; n < NOC; n++) {
                uint2 q = *(const uint2*)&bw[(tap * (8 * NOC) + n * 8 + G) * 8 + 2 * tig];
#pragma unroll
                for (int m = 0; m < 2; m++)
                    mma_f16(d[m][n], a[m][0].x, a[m][1].x, a[m][0].y, a[m][1].y,
                            q.x, q.y);
            }
        }
    }

    // ---- epilogue ----
    const int gy = gy0 + warp;
    if (NOC == 1) {
        if (tig == 0) {
            float bv = __ldg(&bias[0]);
#pragma unroll
            for (int m = 0; m < 2; m++) {
                const int x = gx0 + m * 16 + G;
                float v0 = d[m][0][0] + bv;
                float v2 = d[m][0][2] + bv;
                if (RELU) { v0 = fmaxf(v0, 0.f); v2 = fmaxf(v2, 0.f); }
                outf[(size_t)b * HW + (size_t)gy * Wd + x]     = v0;
                outf[(size_t)b * HW + (size_t)gy * Wd + x + 8] = v2;
            }
        }
        return;
    }
#pragma unroll
    for (int m = 0; m < 2; m++) {
        const int x = gx0 + m * 16 + G;
#pragma unroll
        for (int n = 0; n < NOC; n++) {
            const int oc = n * 8 + 2 * tig;
            float b0v = __ldg(&bias[oc]);
            float b1v = __ldg(&bias[oc + 1]);
            float v0 = d[m][n][0] + b0v;
            float v1 = d[m][n][1] + b1v;
            float v2 = d[m][n][2] + b0v;
            float v3 = d[m][n][3] + b1v;
            size_t f0 = (((size_t)b * 64 + oc) * Hd + gy) * Wd + x;
            size_t f1 = f0 + HW;
            if (SKIP) {
                v0 += skip[f0];     v1 += skip[f1];
                v2 += skip[f0 + 8]; v3 += skip[f1 + 8];
            }
            if (RELU) {
                v0 = fmaxf(v0, 0.f); v1 = fmaxf(v1, 0.f);
                v2 = fmaxf(v2, 0.f); v3 = fmaxf(v3, 0.f);
            }
            if (WF32) {
                outf[f0] = v0; outf[f1] = v1; outf[f0 + 8] = v2; outf[f1 + 8] = v3;
            }
            if (WT16) {
                int slot = 2 * tig + (n & 1);
                size_t tb = (((size_t)b * 4 + (n >> 1)) * HW + (size_t)gy * Wd + x) * 8;
                outt[tb + slot]      = packh2(v0, v1);
                outt[tb + 64 + slot] = packh2(v2, v3);
            }
        }
    }
}

// ---------------------------------------------------------------------------
// combined stage kernels: trunk conv (512 blocks) + residual rider (128 blocks)
// ---------------------------------------------------------------------------
__global__ __launch_bounds__(256, 2)
void k_stage1(const float* __restrict__ wn_b1, const float* __restrict__ rb_b) {
    extern __shared__ u32t sm[];
    int bid = blockIdx.x;
    if (bid < 512) {
        int bx = bid & 7, by = (bid >> 3) & 31, b = bid >> 8;
        conv_body<8, 8, true, false, false, true>(sm, gt_in0, gt_wn1, wn_b1,
            nullptr, nullptr, gt_wm1, H2_, W2_, bx * 32, by * 8, b);
    } else {
        int j = bid - 512;
        int bx = j & 3, by = (j >> 2) & 15, b = j >> 6;
        conv_body<4, 8, true, false, false, true>(sm, gt_inlo, gt_rb, rb_b,
            nullptr, nullptr, gt_r1, H1_, W1_, bx * 32, by * 8, b);
    }
}

__global__ __launch_bounds__(256, 2)
void k_stage2(const float* __restrict__ wn_b2, const float* __restrict__ rb_b,
              const float* __restrict__ inputs) {
    extern __shared__ u32t sm[];
    int bid = blockIdx.x;
    if (bid < 512) {
        int bx = bid & 7, by = (bid >> 3) & 31, b = bid >> 8;
        conv_body<4, 8, true, false, false, true>(sm, gt_wm1, gt_wn2, wn_b2,
            nullptr, nullptr, gt_wm2, H2_, W2_, bx * 32, by * 8, b);
    } else {
        int j = bid - 512;
        int bx = j & 3, by = (j >> 2) & 15, b = j >> 6;
        conv_body<4, 8, false, true, true, true>(sm, gt_r1, gt_rb + 1 * 18432, rb_b + 64,
            inputs, g_r2, gt_r2, H1_, W1_, bx * 32, by * 8, b);
    }
}

__global__ __launch_bounds__(256, 2)
void k_stage3(const float* __restrict__ wn_b3, const float* __restrict__ rb_b) {
    extern __shared__ u32t sm[];
    int bid = blockIdx.x;
    if (bid < 512) {
        int bx = bid & 7, by = (bid >> 3) & 31, b = bid >> 8;
        conv_body<4, 1, false, false, true, false>(sm, gt_wm2, gt_wn3, wn_b3,
            nullptr, g_wmap, nullptr, H2_, W2_, bx * 32, by * 8, b);
    } else {
        int j = bid - 512;
        int bx = j & 3, by = (j >> 2) & 15, b = j >> 6;
        conv_body<4, 8, true, false, false, true>(sm, gt_r2, gt_rb + 2 * 18432, rb_b + 128,
            nullptr, nullptr, gt_r3, H1_, W1_, bx * 32, by * 8, b);
    }
}

__global__ __launch_bounds__(256, 2)
void k_r4(const float* __restrict__ rb_b) {
    extern __shared__ u32t sm[];
    int j = blockIdx.x;
    int bx = j & 3, by = (j >> 2) & 15, b = j >> 6;
    conv_body<4, 8, false, true, true, false>(sm, gt_r3, gt_rb + 3 * 18432, rb_b + 192,
        g_r2, g_r3, nullptr, H1_, W1_, bx * 32, by * 8, b);
}

// ---------------------------------------------------------------------------
// fuse: fp16 hidden + logits GEMMs, X staged via cp.async from gt_in0.
// ---------------------------------------------------------------------------
__global__ __launch_bounds__(256)
void fuse_kernel(const float* __restrict__ dkb1, const float* __restrict__ dkb2,
                 const float* __restrict__ gkb1, const float* __restrict__ gkb2,
                 const float* __restrict__ aff) {
    __shared__ u32t   s_x[8][64][8];
    __shared__ __half s_h[64][72];
    __shared__ float  s_l[2][9][64];

    const int b    = blockIdx.y;
    const int px0  = blockIdx.x * 64;
    const int t    = threadIdx.x;
    const int warp = t >> 5, lane = t & 31;
    const int G    = lane >> 2, tig = lane & 3;
    const int mt   = warp & 3, nh = warp >> 2;
    const int c0   = mt * 16;

    {
        const u32t smb = (u32t)__cvta_generic_to_shared(&s_x[0][0][0]);
        for (int u = t; u < 1024; u += 256) {
            int ch = u >> 7, rem = u & 127;
            int px = rem >> 1, hf = rem & 1;
            const u32t* src = gt_in0 + (((size_t)b * 8 + ch) * HW2_ + px0 + px) * 8 + hf * 4;
            asm volatile("cp.async.cg.shared.global [%0], [%1], 16, 16;"
                         :: "r"(smb + (u32t)(((ch * 64 + px) * 8 + hf * 4) * 4)), "l"(src));
        }
        asm volatile("cp.async.commit_group;");
        asm volatile("cp.async.wait_group 0;");
    }
    __syncthreads();

#pragma unroll
    for (int branch = 0; branch < 2; branch++) {
        const float* B1v = branch ? gkb1 : dkb1;
        const float* B2v = branch ? gkb2 : dkb2;
        const u32t* w1 = gt_fw1 + branch * 2048;
        const u32t* w2 = gt_fw2 + branch * 512;

        if (branch) __syncthreads();

        float d[4][4];
#pragma unroll
        for (int nc = 0; nc < 4; nc++)
#pragma unroll
            for (int i = 0; i < 4; i++) d[nc][i] = 0.f;
#pragma unroll
        for (int kc = 0; kc < 4; kc++) {
            uint2 q0 = *(const uint2*)&w1[((kc * 64) + c0 + G)     * 8 + 2 * tig];
            uint2 q1 = *(const uint2*)&w1[((kc * 64) + c0 + G + 8) * 8 + 2 * tig];
#pragma unroll
            for (int nc = 0; nc < 4; nc++) {
                int px = nh * 32 + nc * 8 + G;
                uint2 bb = *(const uint2*)&s_x[branch * 4 + kc][px][2 * tig];
                mma_f16(d[nc], q0.x, q1.x, q0.y, q1.y, bb.x, bb.y);
            }
        }
        float bv0 = __ldg(&B1v[c0 + G]);
        float bv8 = __ldg(&B1v[c0 + G + 8]);
#pragma unroll
        for (int nc = 0; nc < 4; nc++) {
            int px = nh * 32 + nc * 8 + 2 * tig;
            s_h[px][c0 + G]         = __float2half_rn(fmaxf(d[nc][0] + bv0, 0.f));
            s_h[px + 1][c0 + G]     = __float2half_rn(fmaxf(d[nc][1] + bv0, 0.f));
            s_h[px][c0 + G + 8]     = __float2half_rn(fmaxf(d[nc][2] + bv8, 0.f));
            s_h[px + 1][c0 + G + 8] = __float2half_rn(fmaxf(d[nc][3] + bv8, 0.f));
        }
        __syncthreads();

        {
            const int n0 = warp * 8;
            float d2[4] = {0.f, 0.f, 0.f, 0.f};
#pragma unroll
            for (int kc = 0; kc < 4; kc++) {
                uint2 q0 = *(const uint2*)&w2[((kc * 16) + G)     * 8 + 2 * tig];
                uint2 q1 = *(const uint2*)&w2[((kc * 16) + G + 8) * 8 + 2 * tig];
                u32t b0 = *(const u32t*)&s_h[n0 + G][kc * 16 + 2 * tig];
                u32t b1 = *(const u32t*)&s_h[n0 + G][kc * 16 + 2 * tig + 8];
                mma_f16(d2, q0.x, q1.x, q0.y, q1.y, b0, b1);
            }
            float bj = __ldg(&B2v[G]);
            s_l[branch][G][n0 + 2 * tig]     = d2[0] + bj;
            s_l[branch][G][n0 + 2 * tig + 1] = d2[1] + bj;
            if (G == 0) {
                float b8 = __ldg(&B2v[8]);
                s_l[branch][8][n0 + 2 * tig]     = d2[2] + b8;
                s_l[branch][8][n0 + 2 * tig + 1] = d2[3] + b8;
            }
        }
    }
    __syncthreads();

    if (t < 64) {
        float wm = g_wmap[(size_t)b * HW2_ + px0 + t];
        float dmax = -1e30f, gmax = -1e30f;
#pragma unroll
        for (int j = 0; j < 9; j++) {
            dmax = fmaxf(dmax, s_l[0][j][t]);
            gmax = fmaxf(gmax, s_l[1][j][t]);
        }
        float de[9], ge[9], ds = 0.f, gs = 0.f;
#pragma unroll
        for (int j = 0; j < 9; j++) {
            de[j] = expf(s_l[0][j][t] - dmax); ds += de[j];
            ge[j] = expf(s_l[1][j][t] - gmax); gs += ge[j];
        }
        float affv = __ldg(&aff[0]) + 1e-8f;
        float inv_d = 1.f / ds, inv_g = 1.f / gs;
        float f[9], asum = 0.f;
#pragma unroll
        for (int j = 0; j < 9; j++) {
            float fv = wm * (de[j] * inv_d) + (1.f - wm) * (ge[j] * inv_g);
            fv = tanhf(fv) / affv;
            f[j] = fv;
            asum += fabsf(fv);
        }
        float inv_ks = 1.f / fmaxf(asum + 1e-4f, 1.0f);
#pragma unroll
        for (int j = 0; j < 9; j++)
            g_fuse[((size_t)b * 9 + j) * HW2_ + px0 + t] = f[j] * inv_ks;
    }
}

// ---------------------------------------------------------------------------
// gather with fused bilinear upsample
// ---------------------------------------------------------------------------
__global__ __launch_bounds__(256)
void gather_kernel(float* __restrict__ out) {
    __shared__ float s_r3[4][8][21];
    __shared__ float s_up[4][12][37];
    const int b   = blockIdx.z;
    const int gx0 = blockIdx.x * 32;
    const int gy0 = blockIdx.y * 8;
    const int t   = threadIdx.x;
    const int xl  = t & 31, yl = t >> 5;
    const int gx  = gx0 + xl, gy = gy0 + yl;
    const int ly0 = gy0 / 2 - 2, lx0 = gx0 / 2 - 2;

    float f[9];
#pragma unroll
    for (int j = 0; j < 9; j++)
        f[j] = g_fuse[((size_t)b * 9 + j) * HW2_ + gy * W2_ + gx];

    for (int c0 = 0; c0 < 64; c0 += 4) {
        __syncthreads();
        for (int idx = t; idx < 640; idx += 256) {
            int cl = idx / 160, rem = idx % 160;
            int r = rem / 20, cc = rem % 20;
            int yy = min(max(ly0 + r, 0), 127);
            int xx = min(max(lx0 + cc, 0), 127);
            s_r3[cl][r][cc] = g_r3[((size_t)b * 64 + c0 + cl) * HW1_ + yy * 128 + xx];
        }
        __syncthreads();
        for (int idx = t; idx < 432; idx += 256) {
            int r = idx / 36, cc = idx % 36;
            int Y = gy0 + r - 2, X = gx0 + cc - 2;
            bool ok = (Y >= 0) && (Y < H2_) && (X >= 0) && (X < W2_);
            int m = Y >> 1, ya, yb; float wya, wyb;
            if (Y & 1) { ya = m; yb = min(m + 1, 127); wya = 0.75f; wyb = 0.25f; }
            else       { ya = max(m - 1, 0); yb = m;   wya = 0.25f; wyb = 0.75f; }
            int n = X >> 1, xa, xb; float wxa, wxb;
            if (X & 1) { xa = n; xb = min(n + 1, 127); wxa = 0.75f; wxb = 0.25f; }
            else       { xa = max(n - 1, 0); xb = n;   wxa = 0.25f; wxb = 0.75f; }
            int iya = min(max(ya - ly0, 0), 7), iyb = min(max(yb - ly0, 0), 7);
            int ixa = min(max(xa - lx0, 0), 20), ixb = min(max(xb - lx0, 0), 20);
#pragma unroll
            for (int cl = 0; cl < 4; cl++) {
                float v = wya * (wxa * s_r3[cl][iya][ixa] + wxb * s_r3[cl][iya][ixb])
                        + wyb * (wxa * s_r3[cl][iyb][ixa] + wxb * s_r3[cl][iyb][ixb]);
                s_up[cl][r][cc] = ok ? v : 0.f;
            }
        }
        __syncthreads();
#pragma unroll
        for (int cl = 0; cl < 4; cl++) {
            float acc = 0.f;
#pragma unroll
            for (int ky = 0; ky < 3; ky++)
#pragma unroll
                for (int kx = 0; kx < 3; kx++)
                    acc += f[ky * 3 + kx] * s_up[cl][yl + 2 * ky][xl + 2 * kx];
            out[(((size_t)b * 64 + c0 + cl) * H2_ + gy) * W2_ + gx] = acc;
        }
    }
}

// ---------------------------------------------------------------------------
extern "C" void kernel_launch(void* const* d_in, const int* in_sizes, int n_in,
                              void* d_out, int out_size) {
    const float* depth  = (const float*)d_in[0];
    const float* guide  = (const float*)d_in[1];
    const float* inputs = (const float*)d_in[2];
    const float* dk_w1  = (const float*)d_in[3];
    const float* dk_b1  = (const float*)d_in[4];
    const float* dk_w2  = (const float*)d_in[5];
    const float* dk_b2  = (const float*)d_in[6];
    const float* gk_w1  = (const float*)d_in[7];
    const float* gk_b1  = (const float*)d_in[8];
    const float* gk_w2  = (const float*)d_in[9];
    const float* gk_b2  = (const float*)d_in[10];
    const float* wn_w1  = (const float*)d_in[11];
    const float* wn_b1  = (const float*)d_in[12];
    const float* wn_w2  = (const float*)d_in[13];
    const float* wn_b2  = (const float*)d_in[14];
    const float* wn_w3  = (const float*)d_in[15];
    const float* wn_b3  = (const float*)d_in[16];
    const float* rb_w   = (const float*)d_in[17];
    const float* rb_b   = (const float*)d_in[18];
    const float* aff    = (const float*)d_in[19];
    float* out = (float*)d_out;

    cudaFuncSetAttribute(k_stage1, cudaFuncAttributeMaxDynamicSharedMemorySize, SMEM_CONV);
    cudaFuncSetAttribute(k_stage2, cudaFuncAttributeMaxDynamicSharedMemorySize, SMEM_CONV);
    cudaFuncSetAttribute(k_stage3, cudaFuncAttributeMaxDynamicSharedMemorySize, SMEM_CONV);
    cudaFuncSetAttribute(k_r4,     cudaFuncAttributeMaxDynamicSharedMemorySize, SMEM_CONV);

    // prep (inputs + all weights in one launch)
    k_prep<<<(NPI_ + 136448 + 255) / 256, 256>>>(depth, guide, inputs,
                                                 wn_w1, wn_w2, rb_w, wn_w3,
                                                 dk_w1, gk_w1, dk_w2, gk_w2);

    // paired trunk + residual stages
    k_stage1<<<640, 256, SMEM_CONV>>>(wn_b1, rb_b);
    k_stage2<<<640, 256, SMEM_CONV>>>(wn_b2, rb_b, inputs);
    k_stage3<<<640, 256, SMEM_CONV>>>(wn_b3, rb_b);

    // fuse (high occupancy, standalone) then final residual conv
    dim3 gfuse(HW2_ / 64, B_);
    fuse_kernel<<<gfuse, 256>>>(dk_b1, dk_b2, gk_b1, gk_b2, aff);
    k_r4<<<128, 256, SMEM_CONV>>>(rb_b);

    // fused upsample + gather
    dim3 ghi8(W2_ / 32, H2_ / 8, B_);
    gather_kernel<<<ghi8, 256>>>(out);
}